// round 2
// baseline (speedup 1.0000x reference)
#include <cuda_runtime.h>
#include <math.h>

#define Bz   4
#define Cc   256
#define Hh   48
#define Ww   48
#define HW   2304
#define Stok 2484
#define NW   78      // ceil(S/32) mask words per row
#define BOT  64

// ---------------- scratch (device globals; no allocations allowed) ----------------
__device__ float g_xT [(size_t)Bz*HW*Cc];      // x transposed  [b*HW+p][C]
__device__ float g_xp [(size_t)Bz*HW*Cc];      // conv output   [b*HW+p][C]
__device__ float g_f  [(size_t)Bz*Stok*Cc];    // concat+LN features [b*S+s][C]
__device__ float g_qkv[(size_t)Bz*Stok*Cc*3];  // [b*S+s][3C]
__device__ float g_o  [(size_t)Bz*Stok*Cc];    // attention out [b*S+s][C]
__device__ float g_op [(size_t)Bz*Stok*Cc];    // out_proj      [b*S+s][C]
__device__ float g_hid[(size_t)Bz*HW*Cc];      // ln_out(lo)    [b*HW+p][C]
__device__ float g_m1 [(size_t)Bz*HW*BOT];     // gelu(mlp1)
__device__ float g_m2 [(size_t)Bz*HW*Cc];      // mlp2
__device__ unsigned g_mb[(size_t)Stok*NW];     // bit-packed mask (bit set = blocked)
__device__ int g_mdt;                          // mask dtype: 0=u8, 1=i32, 2=f32

// ---------------- mask dtype probe ----------------
// Interpret the first mask row region as u32 words. Bool stored as int32 ->
// all words in {0,1}. float32 -> {0, 0x3F800000}. byte-packed bools -> words
// like 0x01010101 (row 0 is ~87% blocked, so unambiguous).
__global__ void k_probe(const unsigned* __restrict__ m) {
    __shared__ int bad_i32, bad_f32;
    if (threadIdx.x == 0) { bad_i32 = 0; bad_f32 = 0; }
    __syncthreads();
    for (int i = threadIdx.x; i < Stok / 4; i += blockDim.x) {
        unsigned v = m[i];
        if (v != 0u && v != 1u)           bad_i32 = 1;
        if (v != 0u && v != 0x3F800000u)  bad_f32 = 1;
    }
    __syncthreads();
    if (threadIdx.x == 0)
        g_mdt = (!bad_i32) ? 1 : ((!bad_f32) ? 2 : 0);
}

// ---------------- pack mask -> bitmask (bit set = blocked) ----------------
__global__ void k_pack_mask(const void* __restrict__ mv, unsigned* __restrict__ out) {
    int idx = blockIdx.x * blockDim.x + threadIdx.x;
    if (idx >= Stok * NW) return;
    int dt = g_mdt;
    int q = idx / NW, w = idx % NW;
    unsigned bits = 0;
    int c0 = w * 32;
    const unsigned char* mu = (const unsigned char*)mv;
    const int*           mi = (const int*)mv;
    const float*         mf = (const float*)mv;
    #pragma unroll 4
    for (int j = 0; j < 32; j++) {
        int c = c0 + j;
        bool blk;
        if (c >= Stok)      blk = true;
        else if (dt == 1)   blk = mi[(size_t)q * Stok + c] != 0;
        else if (dt == 2)   blk = mf[(size_t)q * Stok + c] != 0.0f;
        else                blk = mu[(size_t)q * Stok + c] != 0;
        if (blk) bits |= 1u << j;
    }
    out[idx] = bits;
}

// ---------------- transpose in: x[b][c][p] -> xT[b*HW+p][c] ----------------
__global__ void k_transpose_in(const float* __restrict__ x, float* __restrict__ xT) {
    __shared__ float t[32][33];
    int b  = blockIdx.z;
    int p0 = blockIdx.x * 32, c0 = blockIdx.y * 32;
    int tx = threadIdx.x, ty = threadIdx.y;
    t[ty][tx] = x[((size_t)b * Cc + c0 + ty) * HW + p0 + tx];
    __syncthreads();
    xT[((size_t)b * HW + p0 + ty) * Cc + c0 + tx] = t[tx][ty];
}

// ---------------- tiled SGEMM: C[M,N] = A[M,K] @ W[N,K]^T + bias, opt GELU ----------------
__device__ __forceinline__ float gelu_exact(float v) {
    return 0.5f * v * (1.0f + erff(v * 0.70710678118654752f));
}

template<int ACT>
__global__ void __launch_bounds__(256) k_gemm(
    const float* __restrict__ A, const float* __restrict__ W,
    const float* __restrict__ bias, float* __restrict__ C,
    int M, int N, int K)
{
    __shared__ float As[16][68];
    __shared__ float Bs[16][68];
    int tid = threadIdx.x;
    int tx = tid & 15, ty = tid >> 4;
    int m0 = blockIdx.y * 64, n0 = blockIdx.x * 64;
    int lr = tid >> 2, lk = (tid & 3) * 4;
    float acc[4][4] = {};

    for (int k0 = 0; k0 < K; k0 += 16) {
        int gm = m0 + lr;
        float4 av = (gm < M) ? *(const float4*)(A + (size_t)gm * K + k0 + lk)
                             : make_float4(0.f, 0.f, 0.f, 0.f);
        float4 bv = *(const float4*)(W + (size_t)(n0 + lr) * K + k0 + lk);
        As[lk + 0][lr] = av.x; As[lk + 1][lr] = av.y; As[lk + 2][lr] = av.z; As[lk + 3][lr] = av.w;
        Bs[lk + 0][lr] = bv.x; Bs[lk + 1][lr] = bv.y; Bs[lk + 2][lr] = bv.z; Bs[lk + 3][lr] = bv.w;
        __syncthreads();
        #pragma unroll
        for (int kk = 0; kk < 16; kk++) {
            float4 a = *(const float4*)&As[kk][ty * 4];
            float4 b = *(const float4*)&Bs[kk][tx * 4];
            float ar[4] = {a.x, a.y, a.z, a.w};
            float br[4] = {b.x, b.y, b.z, b.w};
            #pragma unroll
            for (int i = 0; i < 4; i++)
                #pragma unroll
                for (int j = 0; j < 4; j++)
                    acc[i][j] = fmaf(ar[i], br[j], acc[i][j]);
        }
        __syncthreads();
    }
    float4 bb = *(const float4*)(bias + n0 + tx * 4);
    float bbr[4] = {bb.x, bb.y, bb.z, bb.w};
    #pragma unroll
    for (int i = 0; i < 4; i++) {
        int gm = m0 + ty * 4 + i;
        if (gm >= M) continue;
        float r[4];
        #pragma unroll
        for (int j = 0; j < 4; j++) {
            float v = acc[i][j] + bbr[j];
            if (ACT == 1) v = gelu_exact(v);
            r[j] = v;
        }
        *(float4*)(C + (size_t)gm * N + n0 + tx * 4) = make_float4(r[0], r[1], r[2], r[3]);
    }
}

// ---------------- row layernorm over C=256, one block per token row ----------------
__global__ void k_ln(const float* __restrict__ in, int inTok,
                     const float* __restrict__ w, const float* __restrict__ bv,
                     float* __restrict__ out, int outTok)
{
    int r = blockIdx.x;              // 0 .. B*HW-1
    int b = r / HW, p = r % HW;
    int c = threadIdx.x;
    const float* row = in + ((size_t)b * inTok + p) * Cc;
    float v = row[c];
    __shared__ float sb[8];
    float s = v;
    #pragma unroll
    for (int o = 16; o > 0; o >>= 1) s += __shfl_xor_sync(0xffffffffu, s, o);
    if ((c & 31) == 0) sb[c >> 5] = s;
    __syncthreads();
    float tot = 0.f;
    #pragma unroll
    for (int i = 0; i < 8; i++) tot += sb[i];
    float mean = tot * (1.0f / 256.0f);
    __syncthreads();
    float d = v - mean;
    float s2 = d * d;
    #pragma unroll
    for (int o = 16; o > 0; o >>= 1) s2 += __shfl_xor_sync(0xffffffffu, s2, o);
    if ((c & 31) == 0) sb[c >> 5] = s2;
    __syncthreads();
    float tot2 = 0.f;
    #pragma unroll
    for (int i = 0; i < 8; i++) tot2 += sb[i];
    float var = tot2 * (1.0f / 256.0f);
    float rs = rsqrtf(var + 1e-5f);
    out[((size_t)b * outTok + p) * Cc + c] = d * rs * w[c] + bv[c];
}

// ---------------- pool (ps x ps mean) + layernorm ----------------
__global__ void k_pool_ln(const float* __restrict__ xp,
                          const float* __restrict__ w, const float* __restrict__ bv,
                          float* __restrict__ f, int ps, int off, int reg)
{
    int b = blockIdx.y;
    int t = blockIdx.x;
    int gw = Ww / ps;
    int bh = t / gw, bw = t % gw;
    int c = threadIdx.x;
    float s = 0.f;
    for (int i = 0; i < ps; i++) {
        int prow = (bh * ps + i) * Ww + bw * ps;
        const float* base = xp + ((size_t)b * HW + prow) * Cc + c;
        for (int j = 0; j < ps; j++) s += base[(size_t)j * Cc];
    }
    float v = s / (float)(ps * ps);
    __shared__ float sb[8];
    float ss = v;
    #pragma unroll
    for (int o = 16; o > 0; o >>= 1) ss += __shfl_xor_sync(0xffffffffu, ss, o);
    if ((c & 31) == 0) sb[c >> 5] = ss;
    __syncthreads();
    float tot = 0.f;
    #pragma unroll
    for (int i = 0; i < 8; i++) tot += sb[i];
    float mean = tot * (1.0f / 256.0f);
    __syncthreads();
    float d = v - mean;
    float s2 = d * d;
    #pragma unroll
    for (int o = 16; o > 0; o >>= 1) s2 += __shfl_xor_sync(0xffffffffu, s2, o);
    if ((c & 31) == 0) sb[c >> 5] = s2;
    __syncthreads();
    float tot2 = 0.f;
    #pragma unroll
    for (int i = 0; i < 8; i++) tot2 += sb[i];
    float rs = rsqrtf(tot2 * (1.0f / 256.0f) + 1e-5f);
    f[((size_t)b * Stok + off + t) * Cc + c] = d * rs * w[reg * Cc + c] + bv[reg * Cc + c];
}

// ---------------- fused flash attention (fp32, dense, BQ=BK=64, dh=32) ----------------
__global__ void __launch_bounds__(256) k_attn(const float* __restrict__ qkv,
                                              const unsigned* __restrict__ mb,
                                              float* __restrict__ out)
{
    int qt = blockIdx.x, h = blockIdx.y, b = blockIdx.z;
    int q0 = qt * 64;
    int tid = threadIdx.x;

    __shared__ float Qs[64][36], Ks[64][36], Vs[64][36];
    __shared__ float Ss[64][65];
    __shared__ float row_m[64], row_l[64], row_a[64];
    __shared__ float red[64][4];
    __shared__ unsigned Mb[64][2];

    const float* qb = qkv + ((size_t)b * Stok) * 768 + h * 32;
    const float* kb = qb + 256;
    const float* vb = qb + 512;

    // load Q tile
    {
        int c4 = (tid & 7) * 4;
        #pragma unroll
        for (int rr = 0; rr < 2; rr++) {
            int r = (tid >> 3) + rr * 32;
            int gq = q0 + r;
            float4 v = (gq < Stok) ? *(const float4*)(qb + (size_t)gq * 768 + c4)
                                   : make_float4(0.f, 0.f, 0.f, 0.f);
            *(float4*)&Qs[r][c4] = v;
        }
    }
    if (tid < 64) { row_m[tid] = -3.0e38f; row_l[tid] = 0.f; }

    float o0[8] = {0, 0, 0, 0, 0, 0, 0, 0};
    int r_ = tid >> 2, sg = tid & 3, d0 = sg * 8;
    int ty = tid >> 4, txx = tid & 15;

    for (int kt = 0; kt < 39; kt++) {
        int k0 = kt * 64;
        // load K, V, mask bits
        {
            int c4 = (tid & 7) * 4;
            #pragma unroll
            for (int rr = 0; rr < 2; rr++) {
                int r = (tid >> 3) + rr * 32;
                int gk = k0 + r;
                float4 kv, vv;
                if (gk < Stok) {
                    kv = *(const float4*)(kb + (size_t)gk * 768 + c4);
                    vv = *(const float4*)(vb + (size_t)gk * 768 + c4);
                } else {
                    kv = make_float4(0.f, 0.f, 0.f, 0.f);
                    vv = kv;
                }
                *(float4*)&Ks[r][c4] = kv;
                *(float4*)&Vs[r][c4] = vv;
            }
            if (tid < 128) {
                int rr = tid >> 1, wz = tid & 1;
                int gq = q0 + rr;
                Mb[rr][wz] = (gq < Stok) ? mb[(size_t)gq * NW + kt * 2 + wz] : 0xFFFFFFFFu;
            }
        }
        __syncthreads();

        // scores: 16x16 threads, 4x4 each
        float acc[4][4] = {};
        #pragma unroll
        for (int k = 0; k < 32; k++) {
            float qr[4], kr[4];
            #pragma unroll
            for (int i = 0; i < 4; i++) qr[i] = Qs[ty * 4 + i][k];
            #pragma unroll
            for (int j = 0; j < 4; j++) kr[j] = Ks[txx * 4 + j][k];
            #pragma unroll
            for (int i = 0; i < 4; i++)
                #pragma unroll
                for (int j = 0; j < 4; j++)
                    acc[i][j] = fmaf(qr[i], kr[j], acc[i][j]);
        }
        const float sc = 0.17677669529663687f;   // 1/sqrt(32)
        #pragma unroll
        for (int i = 0; i < 4; i++) {
            int rr = ty * 4 + i;
            unsigned mw = Mb[rr][txx >> 3];
            #pragma unroll
            for (int j = 0; j < 4; j++) {
                int cc = txx * 4 + j;
                float v = acc[i][j] * sc;
                if (k0 + cc >= Stok) v = -3.0e38f;
                else if ((mw >> (cc & 31)) & 1u) v = -1.0e9f;
                Ss[rr][cc] = v;
            }
        }
        __syncthreads();

        // partial row max (4 threads per row)
        {
            float mx = -3.0e38f;
            #pragma unroll
            for (int cc = sg * 16; cc < sg * 16 + 16; cc++) mx = fmaxf(mx, Ss[r_][cc]);
            red[r_][sg] = mx;
        }
        __syncthreads();
        if (tid < 64) {
            float mx = fmaxf(fmaxf(red[tid][0], red[tid][1]), fmaxf(red[tid][2], red[tid][3]));
            float mo = row_m[tid];
            float mn = fmaxf(mo, mx);
            row_a[tid] = __expf(mo - mn);
            row_m[tid] = mn;
        }
        __syncthreads();

        // exponentiate segment, partial sums, rescale O
        {
            float mn = row_m[r_];
            float al = row_a[r_];
            float ps = 0.f;
            #pragma unroll
            for (int cc = sg * 16; cc < sg * 16 + 16; cc++) {
                float p = __expf(Ss[r_][cc] - mn);
                Ss[r_][cc] = p;
                ps += p;
            }
            red[r_][sg] = ps;
            #pragma unroll
            for (int j = 0; j < 8; j++) o0[j] *= al;
        }
        __syncthreads();   // Ss/red fully written before consumers below

        if (tid < 64)
            row_l[tid] = row_l[tid] * row_a[tid]
                       + red[tid][0] + red[tid][1] + red[tid][2] + red[tid][3];

        // O accumulate: each thread 1 row x 8 dims
        #pragma unroll 4
        for (int cc = 0; cc < 64; cc++) {
            float p = Ss[r_][cc];
            float4 v1 = *(const float4*)&Vs[cc][d0];
            float4 v2 = *(const float4*)&Vs[cc][d0 + 4];
            o0[0] = fmaf(p, v1.x, o0[0]);
            o0[1] = fmaf(p, v1.y, o0[1]);
            o0[2] = fmaf(p, v1.z, o0[2]);
            o0[3] = fmaf(p, v1.w, o0[3]);
            o0[4] = fmaf(p, v2.x, o0[4]);
            o0[5] = fmaf(p, v2.y, o0[5]);
            o0[6] = fmaf(p, v2.z, o0[6]);
            o0[7] = fmaf(p, v2.w, o0[7]);
        }
        __syncthreads();
    }

    int gq = q0 + r_;
    if (gq < Stok) {
        float inv = 1.0f / row_l[r_];
        float* dst = out + ((size_t)b * Stok + gq) * 256 + h * 32 + d0;
        *(float4*)(dst + 0) = make_float4(o0[0] * inv, o0[1] * inv, o0[2] * inv, o0[3] * inv);
        *(float4*)(dst + 4) = make_float4(o0[4] * inv, o0[5] * inv, o0[6] * inv, o0[7] * inv);
    }
}

// ---------------- final: out[b][c][p] = m2[p][c] + op[p][c] + x[b][c][p] ----------------
__global__ void k_final(const float* __restrict__ m2, const float* __restrict__ op,
                        const float* __restrict__ x, float* __restrict__ out)
{
    __shared__ float t[32][33];
    int b = blockIdx.z;
    int p0 = blockIdx.x * 32, c0 = blockIdx.y * 32;
    int tx = threadIdx.x, ty = threadIdx.y;
    t[ty][tx] = m2[((size_t)b * HW + p0 + ty) * Cc + c0 + tx]
              + op[((size_t)b * Stok + p0 + ty) * Cc + c0 + tx];
    __syncthreads();
    size_t oi = ((size_t)b * Cc + c0 + ty) * HW + p0 + tx;
    out[oi] = t[tx][ty] + x[oi];
}

// ---------------- launch ----------------
extern "C" void kernel_launch(void* const* d_in, const int* in_sizes, int n_in,
                              void* d_out, int out_size)
{
    const float* x          = (const float*)d_in[0];
    const float* conv_w     = (const float*)d_in[1];
    const float* conv_b     = (const float*)d_in[2];
    const float* ln_local_w = (const float*)d_in[3];
    const float* ln_local_b = (const float*)d_in[4];
    const float* ln_reg_w   = (const float*)d_in[5];
    const float* ln_reg_b   = (const float*)d_in[6];
    const float* in_proj_w  = (const float*)d_in[7];
    const float* in_proj_b  = (const float*)d_in[8];
    const float* out_proj_w = (const float*)d_in[9];
    const float* out_proj_b = (const float*)d_in[10];
    const float* ln_out_w   = (const float*)d_in[11];
    const float* ln_out_b   = (const float*)d_in[12];
    const float* mlp_w1     = (const float*)d_in[13];
    const float* mlp_b1     = (const float*)d_in[14];
    const float* mlp_w2     = (const float*)d_in[15];
    const float* mlp_b2     = (const float*)d_in[16];
    const void*  attn_mask  = (const void*)d_in[17];
    float* out = (float*)d_out;

    float *xT, *xp, *f, *qkv, *o, *op, *hid, *m1, *m2;
    unsigned* mb;
    cudaGetSymbolAddress((void**)&xT,  g_xT);
    cudaGetSymbolAddress((void**)&xp,  g_xp);
    cudaGetSymbolAddress((void**)&f,   g_f);
    cudaGetSymbolAddress((void**)&qkv, g_qkv);
    cudaGetSymbolAddress((void**)&o,   g_o);
    cudaGetSymbolAddress((void**)&op,  g_op);
    cudaGetSymbolAddress((void**)&hid, g_hid);
    cudaGetSymbolAddress((void**)&m1,  g_m1);
    cudaGetSymbolAddress((void**)&m2,  g_m2);
    cudaGetSymbolAddress((void**)&mb,  g_mb);

    // mask dtype probe + pack (independent, runs first)
    k_probe<<<1, 256>>>((const unsigned*)attn_mask);
    k_pack_mask<<<(Stok * NW + 255) / 256, 256>>>(attn_mask, mb);

    // transpose x -> token-major
    k_transpose_in<<<dim3(HW / 32, Cc / 32, Bz), dim3(32, 32)>>>(x, xT);

    // conv (1x1) : xp = xT @ conv_w^T + conv_b
    k_gemm<0><<<dim3(Cc / 64, (Bz * HW) / 64), 256>>>(xT, conv_w, conv_b, xp, Bz * HW, Cc, Cc);

    // feats: LN local + pooled LN
    k_ln<<<Bz * HW, 256>>>(xp, HW, ln_local_w, ln_local_b, f, Stok);
    k_pool_ln<<<dim3(144, Bz), 256>>>(xp, ln_reg_w, ln_reg_b, f, 4, HW, 0);
    k_pool_ln<<<dim3(36,  Bz), 256>>>(xp, ln_reg_w, ln_reg_b, f, 8, HW + 144, 1);

    // qkv = f @ in_proj^T + b
    k_gemm<0><<<dim3(768 / 64, (Bz * Stok + 63) / 64), 256>>>(f, in_proj_w, in_proj_b, qkv,
                                                              Bz * Stok, 3 * Cc, Cc);

    // attention
    k_attn<<<dim3((Stok + 63) / 64, 8, Bz), 256>>>(qkv, mb, o);

    // out_proj over all tokens
    k_gemm<0><<<dim3(Cc / 64, (Bz * Stok + 63) / 64), 256>>>(o, out_proj_w, out_proj_b, op,
                                                             Bz * Stok, Cc, Cc);

    // ln_out on local tokens
    k_ln<<<Bz * HW, 256>>>(op, Stok, ln_out_w, ln_out_b, hid, HW);

    // mlp
    k_gemm<1><<<dim3(BOT / 64, (Bz * HW) / 64), 256>>>(hid, mlp_w1, mlp_b1, m1, Bz * HW, BOT, Cc);
    k_gemm<0><<<dim3(Cc / 64,  (Bz * HW) / 64), 256>>>(m1, mlp_w2, mlp_b2, m2, Bz * HW, Cc, BOT);

    // residual + transpose back + input residual
    k_final<<<dim3(HW / 32, Cc / 32, Bz), dim3(32, 32)>>>(m2, op, x, out);
}

// round 3
// speedup vs baseline: 3.1586x; 3.1586x over previous
#include <cuda_runtime.h>
#include <math.h>

#define Bz   4
#define Cc   256
#define Hh   48
#define Ww   48
#define HW   2304
#define Stok 2484
#define NW   78      // ceil(S/32) mask words per row
#define BOT  64

// ---------------- scratch (device globals; no allocations allowed) ----------------
__device__ float g_xT [(size_t)Bz*HW*Cc];      // x transposed  [b*HW+p][C]
__device__ float g_xp [(size_t)Bz*HW*Cc];      // conv output   [b*HW+p][C]
__device__ float g_f  [(size_t)Bz*Stok*Cc];    // concat+LN features [b*S+s][C]
__device__ float g_qkv[(size_t)Bz*Stok*Cc*3];  // [b*S+s][3C]
__device__ float g_o  [(size_t)Bz*Stok*Cc];    // attention out [b*S+s][C]
__device__ float g_op [(size_t)Bz*Stok*Cc];    // out_proj      [b*S+s][C]
__device__ float g_hid[(size_t)Bz*HW*Cc];      // ln_out(lo)    [b*HW+p][C]
__device__ float g_m1 [(size_t)Bz*HW*BOT];     // gelu(mlp1)
__device__ float g_m2 [(size_t)Bz*HW*Cc];      // mlp2
__device__ unsigned g_mb[(size_t)Stok*NW];     // bit-packed mask (bit set = blocked)
__device__ int g_mdt;                          // mask dtype: 0=u8, 1=i32, 2=f32

// ---------------- mask dtype probe ----------------
__global__ void k_probe(const unsigned* __restrict__ m) {
    __shared__ int bad_i32, bad_f32;
    if (threadIdx.x == 0) { bad_i32 = 0; bad_f32 = 0; }
    __syncthreads();
    for (int i = threadIdx.x; i < Stok / 4; i += blockDim.x) {
        unsigned v = m[i];
        if (v != 0u && v != 1u)           bad_i32 = 1;
        if (v != 0u && v != 0x3F800000u)  bad_f32 = 1;
    }
    __syncthreads();
    if (threadIdx.x == 0)
        g_mdt = (!bad_i32) ? 1 : ((!bad_f32) ? 2 : 0);
}

// ---------------- pack mask -> bitmask (bit set = blocked) ----------------
__global__ void k_pack_mask(const void* __restrict__ mv, unsigned* __restrict__ out) {
    int idx = blockIdx.x * blockDim.x + threadIdx.x;
    if (idx >= Stok * NW) return;
    int dt = g_mdt;
    int q = idx / NW, w = idx % NW;
    unsigned bits = 0;
    int c0 = w * 32;
    const unsigned char* mu = (const unsigned char*)mv;
    const int*           mi = (const int*)mv;
    const float*         mf = (const float*)mv;
    #pragma unroll 4
    for (int j = 0; j < 32; j++) {
        int c = c0 + j;
        bool blk;
        if (c >= Stok)      blk = true;
        else if (dt == 1)   blk = mi[(size_t)q * Stok + c] != 0;
        else if (dt == 2)   blk = mf[(size_t)q * Stok + c] != 0.0f;
        else                blk = mu[(size_t)q * Stok + c] != 0;
        if (blk) bits |= 1u << j;
    }
    out[idx] = bits;
}

// ---------------- transpose in: x[b][c][p] -> xT[b*HW+p][c] ----------------
__global__ void k_transpose_in(const float* __restrict__ x, float* __restrict__ xT) {
    __shared__ float t[32][33];
    int b  = blockIdx.z;
    int p0 = blockIdx.x * 32, c0 = blockIdx.y * 32;
    int tx = threadIdx.x, ty = threadIdx.y;
    t[ty][tx] = x[((size_t)b * Cc + c0 + ty) * HW + p0 + tx];
    __syncthreads();
    xT[((size_t)b * HW + p0 + ty) * Cc + c0 + tx] = t[tx][ty];
}

// ---------------- tiled SGEMM: C[M,N] = A[M,K] @ W[N,K]^T + bias, opt GELU ----------------
__device__ __forceinline__ float gelu_exact(float v) {
    return 0.5f * v * (1.0f + erff(v * 0.70710678118654752f));
}

template<int ACT>
__global__ void __launch_bounds__(256) k_gemm(
    const float* __restrict__ A, const float* __restrict__ W,
    const float* __restrict__ bias, float* __restrict__ C,
    int M, int N, int K)
{
    __shared__ float As[16][68];
    __shared__ float Bs[16][68];
    int tid = threadIdx.x;
    int tx = tid & 15, ty = tid >> 4;
    int m0 = blockIdx.y * 64, n0 = blockIdx.x * 64;
    int lr = tid >> 2, lk = (tid & 3) * 4;
    float acc[4][4] = {};

    for (int k0 = 0; k0 < K; k0 += 16) {
        int gm = m0 + lr;
        float4 av = (gm < M) ? *(const float4*)(A + (size_t)gm * K + k0 + lk)
                             : make_float4(0.f, 0.f, 0.f, 0.f);
        float4 bv = *(const float4*)(W + (size_t)(n0 + lr) * K + k0 + lk);
        As[lk + 0][lr] = av.x; As[lk + 1][lr] = av.y; As[lk + 2][lr] = av.z; As[lk + 3][lr] = av.w;
        Bs[lk + 0][lr] = bv.x; Bs[lk + 1][lr] = bv.y; Bs[lk + 2][lr] = bv.z; Bs[lk + 3][lr] = bv.w;
        __syncthreads();
        #pragma unroll
        for (int kk = 0; kk < 16; kk++) {
            float4 a = *(const float4*)&As[kk][ty * 4];
            float4 b = *(const float4*)&Bs[kk][tx * 4];
            float ar[4] = {a.x, a.y, a.z, a.w};
            float br[4] = {b.x, b.y, b.z, b.w};
            #pragma unroll
            for (int i = 0; i < 4; i++)
                #pragma unroll
                for (int j = 0; j < 4; j++)
                    acc[i][j] = fmaf(ar[i], br[j], acc[i][j]);
        }
        __syncthreads();
    }
    float4 bb = *(const float4*)(bias + n0 + tx * 4);
    float bbr[4] = {bb.x, bb.y, bb.z, bb.w};
    #pragma unroll
    for (int i = 0; i < 4; i++) {
        int gm = m0 + ty * 4 + i;
        if (gm >= M) continue;
        float r[4];
        #pragma unroll
        for (int j = 0; j < 4; j++) {
            float v = acc[i][j] + bbr[j];
            if (ACT == 1) v = gelu_exact(v);
            r[j] = v;
        }
        *(float4*)(C + (size_t)gm * N + n0 + tx * 4) = make_float4(r[0], r[1], r[2], r[3]);
    }
}

// ---------------- row layernorm over C=256, one block per token row ----------------
__global__ void k_ln(const float* __restrict__ in, int inTok,
                     const float* __restrict__ w, const float* __restrict__ bv,
                     float* __restrict__ out, int outTok)
{
    int r = blockIdx.x;              // 0 .. B*HW-1
    int b = r / HW, p = r % HW;
    int c = threadIdx.x;
    const float* row = in + ((size_t)b * inTok + p) * Cc;
    float v = row[c];
    __shared__ float sb[8];
    float s = v;
    #pragma unroll
    for (int o = 16; o > 0; o >>= 1) s += __shfl_xor_sync(0xffffffffu, s, o);
    if ((c & 31) == 0) sb[c >> 5] = s;
    __syncthreads();
    float tot = 0.f;
    #pragma unroll
    for (int i = 0; i < 8; i++) tot += sb[i];
    float mean = tot * (1.0f / 256.0f);
    __syncthreads();
    float d = v - mean;
    float s2 = d * d;
    #pragma unroll
    for (int o = 16; o > 0; o >>= 1) s2 += __shfl_xor_sync(0xffffffffu, s2, o);
    if ((c & 31) == 0) sb[c >> 5] = s2;
    __syncthreads();
    float tot2 = 0.f;
    #pragma unroll
    for (int i = 0; i < 8; i++) tot2 += sb[i];
    float var = tot2 * (1.0f / 256.0f);
    float rs = rsqrtf(var + 1e-5f);
    out[((size_t)b * outTok + p) * Cc + c] = d * rs * w[c] + bv[c];
}

// ---------------- pool (ps x ps mean) + layernorm ----------------
__global__ void k_pool_ln(const float* __restrict__ xp,
                          const float* __restrict__ w, const float* __restrict__ bv,
                          float* __restrict__ f, int ps, int off, int reg)
{
    int b = blockIdx.y;
    int t = blockIdx.x;
    int gw = Ww / ps;
    int bh = t / gw, bw = t % gw;
    int c = threadIdx.x;
    float s = 0.f;
    for (int i = 0; i < ps; i++) {
        int prow = (bh * ps + i) * Ww + bw * ps;
        const float* base = xp + ((size_t)b * HW + prow) * Cc + c;
        for (int j = 0; j < ps; j++) s += base[(size_t)j * Cc];
    }
    float v = s / (float)(ps * ps);
    __shared__ float sb[8];
    float ss = v;
    #pragma unroll
    for (int o = 16; o > 0; o >>= 1) ss += __shfl_xor_sync(0xffffffffu, ss, o);
    if ((c & 31) == 0) sb[c >> 5] = ss;
    __syncthreads();
    float tot = 0.f;
    #pragma unroll
    for (int i = 0; i < 8; i++) tot += sb[i];
    float mean = tot * (1.0f / 256.0f);
    __syncthreads();
    float d = v - mean;
    float s2 = d * d;
    #pragma unroll
    for (int o = 16; o > 0; o >>= 1) s2 += __shfl_xor_sync(0xffffffffu, s2, o);
    if ((c & 31) == 0) sb[c >> 5] = s2;
    __syncthreads();
    float tot2 = 0.f;
    #pragma unroll
    for (int i = 0; i < 8; i++) tot2 += sb[i];
    float rs = rsqrtf(tot2 * (1.0f / 256.0f) + 1e-5f);
    f[((size_t)b * Stok + off + t) * Cc + c] = d * rs * w[reg * Cc + c] + bv[reg * Cc + c];
}

// ---------------- tf32 mma.sync flash attention ----------------
// BQ=128 (8 warps x 16 rows), BK=64, dh=32. Scores/softmax in register fragments.
#define KV_TILES 39          // ceil(2484/64)
#define PW_PAD   68

__device__ __forceinline__ void mma_tf32(float c[4], const float a[4], float b0, float b1) {
    const unsigned* A = reinterpret_cast<const unsigned*>(a);
    unsigned B0 = __float_as_uint(b0), B1 = __float_as_uint(b1);
    asm volatile(
        "mma.sync.aligned.m16n8k8.row.col.f32.tf32.tf32.f32 "
        "{%0,%1,%2,%3},{%4,%5,%6,%7},{%8,%9},{%0,%1,%2,%3};"
        : "+f"(c[0]), "+f"(c[1]), "+f"(c[2]), "+f"(c[3])
        : "r"(A[0]), "r"(A[1]), "r"(A[2]), "r"(A[3]), "r"(B0), "r"(B1));
}

__global__ void __launch_bounds__(256) k_attn(const float* __restrict__ qkv,
                                              const unsigned* __restrict__ mb,
                                              float* __restrict__ out)
{
    extern __shared__ float dyn[];
    float (*Ks)[36] = (float(*)[36])dyn;                       // 64 x 36
    float (*Vs)[36] = (float(*)[36])(dyn + 64 * 36);           // 64 x 36
    unsigned* Msm   = (unsigned*)(dyn + 2 * 64 * 36);          // 128 x 2
    float* Pw       = dyn + 2 * 64 * 36 + 256;                 // 8 x 16 x PW_PAD

    int tid  = threadIdx.x;
    int warp = tid >> 5, lane = tid & 31;
    int g = lane >> 2, t4 = lane & 3;
    int q0 = blockIdx.x * 128, h = blockIdx.y, b = blockIdx.z;

    const float* qb = qkv + ((size_t)b * Stok) * 768 + h * 32;
    const float* kb = qb + 256;
    const float* vb = qb + 512;

    const float SC = 0.17677669529663687f;  // 1/sqrt(32)
    int r0 = q0 + warp * 16 + g;
    int r1 = r0 + 8;

    // Q fragments (pre-scaled), loaded once: qa[k8][0..3]
    float qa[4][4];
    #pragma unroll
    for (int k8 = 0; k8 < 4; k8++) {
        int kA = k8 * 8 + t4;
        qa[k8][0] = (r0 < Stok) ? qb[(size_t)r0 * 768 + kA]     * SC : 0.f;
        qa[k8][1] = (r1 < Stok) ? qb[(size_t)r1 * 768 + kA]     * SC : 0.f;
        qa[k8][2] = (r0 < Stok) ? qb[(size_t)r0 * 768 + kA + 4] * SC : 0.f;
        qa[k8][3] = (r1 < Stok) ? qb[(size_t)r1 * 768 + kA + 4] * SC : 0.f;
    }

    float m0 = -3.0e38f, m1 = -3.0e38f, l0 = 0.f, l1 = 0.f;
    float o[4][4] = {};                    // [d8][reg] accumulators
    float* pw = Pw + warp * 16 * PW_PAD;

    for (int kt = 0; kt < KV_TILES; kt++) {
        int k0 = kt * 64;
        // ---- load K, V tiles + mask words ----
        for (int i = tid; i < 512; i += 256) {
            int row = i >> 3, c4 = (i & 7) << 2;
            int gk = k0 + row;
            float4 kv, vv;
            if (gk < Stok) {
                kv = *(const float4*)(kb + (size_t)gk * 768 + c4);
                vv = *(const float4*)(vb + (size_t)gk * 768 + c4);
            } else {
                kv = make_float4(0.f, 0.f, 0.f, 0.f); vv = kv;
            }
            *(float4*)&Ks[row][c4] = kv;
            *(float4*)&Vs[row][c4] = vv;
        }
        {
            int row = tid >> 1, w = tid & 1;
            int gq = q0 + row;
            Msm[row * 2 + w] = (gq < Stok) ? mb[(size_t)gq * NW + kt * 2 + w] : 0xFFFFFFFFu;
        }
        __syncthreads();

        // ---- QK^T: s[n8][0..3] ----
        float s[8][4];
        #pragma unroll
        for (int n8 = 0; n8 < 8; n8++) {
            s[n8][0] = s[n8][1] = s[n8][2] = s[n8][3] = 0.f;
            #pragma unroll
            for (int k8 = 0; k8 < 4; k8++) {
                float b0 = Ks[n8 * 8 + g][k8 * 8 + t4];
                float b1 = Ks[n8 * 8 + g][k8 * 8 + t4 + 4];
                mma_tf32(s[n8], qa[k8], b0, b1);
            }
        }

        // ---- mask ----
        unsigned w00 = Msm[(warp * 16 + g) * 2 + 0];
        unsigned w01 = Msm[(warp * 16 + g) * 2 + 1];
        unsigned w10 = Msm[(warp * 16 + 8 + g) * 2 + 0];
        unsigned w11 = Msm[(warp * 16 + 8 + g) * 2 + 1];
        #pragma unroll
        for (int n8 = 0; n8 < 8; n8++) {
            int c = n8 * 8 + 2 * t4;
            unsigned mr0 = (n8 < 4) ? w00 : w01;
            unsigned mr1 = (n8 < 4) ? w10 : w11;
            int sh = c & 31;
            if ((mr0 >> sh) & 1u)        s[n8][0] = -1.0e9f;
            if ((mr0 >> (sh + 1)) & 1u)  s[n8][1] = -1.0e9f;
            if ((mr1 >> sh) & 1u)        s[n8][2] = -1.0e9f;
            if ((mr1 >> (sh + 1)) & 1u)  s[n8][3] = -1.0e9f;
        }

        // ---- online softmax (quad reductions) ----
        float tm0 = -3.0e38f, tm1 = -3.0e38f;
        #pragma unroll
        for (int n8 = 0; n8 < 8; n8++) {
            tm0 = fmaxf(tm0, fmaxf(s[n8][0], s[n8][1]));
            tm1 = fmaxf(tm1, fmaxf(s[n8][2], s[n8][3]));
        }
        tm0 = fmaxf(tm0, __shfl_xor_sync(0xffffffffu, tm0, 1));
        tm0 = fmaxf(tm0, __shfl_xor_sync(0xffffffffu, tm0, 2));
        tm1 = fmaxf(tm1, __shfl_xor_sync(0xffffffffu, tm1, 1));
        tm1 = fmaxf(tm1, __shfl_xor_sync(0xffffffffu, tm1, 2));
        float mn0 = fmaxf(m0, tm0), mn1 = fmaxf(m1, tm1);
        float a0 = __expf(m0 - mn0), a1 = __expf(m1 - mn1);
        m0 = mn0; m1 = mn1;

        float rs0 = 0.f, rs1 = 0.f;
        #pragma unroll
        for (int n8 = 0; n8 < 8; n8++) {
            s[n8][0] = __expf(s[n8][0] - mn0);
            s[n8][1] = __expf(s[n8][1] - mn0);
            s[n8][2] = __expf(s[n8][2] - mn1);
            s[n8][3] = __expf(s[n8][3] - mn1);
            rs0 += s[n8][0] + s[n8][1];
            rs1 += s[n8][2] + s[n8][3];
        }
        rs0 += __shfl_xor_sync(0xffffffffu, rs0, 1);
        rs0 += __shfl_xor_sync(0xffffffffu, rs0, 2);
        rs1 += __shfl_xor_sync(0xffffffffu, rs1, 1);
        rs1 += __shfl_xor_sync(0xffffffffu, rs1, 2);
        l0 = l0 * a0 + rs0;
        l1 = l1 * a1 + rs1;
        #pragma unroll
        for (int d8 = 0; d8 < 4; d8++) {
            o[d8][0] *= a0; o[d8][1] *= a0; o[d8][2] *= a1; o[d8][3] *= a1;
        }

        // ---- P -> smem -> A fragments ----
        __syncwarp();
        #pragma unroll
        for (int n8 = 0; n8 < 8; n8++) {
            int c = n8 * 8 + 2 * t4;
            *(float2*)&pw[g * PW_PAD + c]       = make_float2(s[n8][0], s[n8][1]);
            *(float2*)&pw[(g + 8) * PW_PAD + c] = make_float2(s[n8][2], s[n8][3]);
        }
        __syncwarp();
        float pa[8][4];
        #pragma unroll
        for (int k8 = 0; k8 < 8; k8++) {
            int c = k8 * 8 + t4;
            pa[k8][0] = pw[g * PW_PAD + c];
            pa[k8][1] = pw[(g + 8) * PW_PAD + c];
            pa[k8][2] = pw[g * PW_PAD + c + 4];
            pa[k8][3] = pw[(g + 8) * PW_PAD + c + 4];
        }

        // ---- PV ----
        #pragma unroll
        for (int d8 = 0; d8 < 4; d8++) {
            #pragma unroll
            for (int k8 = 0; k8 < 8; k8++) {
                float b0 = Vs[k8 * 8 + t4][d8 * 8 + g];
                float b1 = Vs[k8 * 8 + t4 + 4][d8 * 8 + g];
                mma_tf32(o[d8], pa[k8], b0, b1);
            }
        }
        __syncthreads();
    }

    // ---- epilogue ----
    float inv0 = 1.0f / l0, inv1 = 1.0f / l1;
    #pragma unroll
    for (int d8 = 0; d8 < 4; d8++) {
        int dc = h * 32 + d8 * 8 + 2 * t4;
        if (r0 < Stok)
            *(float2*)(out + ((size_t)b * Stok + r0) * 256 + dc) =
                make_float2(o[d8][0] * inv0, o[d8][1] * inv0);
        if (r1 < Stok)
            *(float2*)(out + ((size_t)b * Stok + r1) * 256 + dc) =
                make_float2(o[d8][2] * inv1, o[d8][3] * inv1);
    }
}

#define ATTN_SMEM ((2 * 64 * 36 + 256 + 8 * 16 * PW_PAD) * 4)

// ---------------- final: out[b][c][p] = m2[p][c] + op[p][c] + x[b][c][p] ----------------
__global__ void k_final(const float* __restrict__ m2, const float* __restrict__ op,
                        const float* __restrict__ x, float* __restrict__ out)
{
    __shared__ float t[32][33];
    int b = blockIdx.z;
    int p0 = blockIdx.x * 32, c0 = blockIdx.y * 32;
    int tx = threadIdx.x, ty = threadIdx.y;
    t[ty][tx] = m2[((size_t)b * HW + p0 + ty) * Cc + c0 + tx]
              + op[((size_t)b * Stok + p0 + ty) * Cc + c0 + tx];
    __syncthreads();
    size_t oi = ((size_t)b * Cc + c0 + ty) * HW + p0 + tx;
    out[oi] = t[tx][ty] + x[oi];
}

// ---------------- launch ----------------
extern "C" void kernel_launch(void* const* d_in, const int* in_sizes, int n_in,
                              void* d_out, int out_size)
{
    const float* x          = (const float*)d_in[0];
    const float* conv_w     = (const float*)d_in[1];
    const float* conv_b     = (const float*)d_in[2];
    const float* ln_local_w = (const float*)d_in[3];
    const float* ln_local_b = (const float*)d_in[4];
    const float* ln_reg_w   = (const float*)d_in[5];
    const float* ln_reg_b   = (const float*)d_in[6];
    const float* in_proj_w  = (const float*)d_in[7];
    const float* in_proj_b  = (const float*)d_in[8];
    const float* out_proj_w = (const float*)d_in[9];
    const float* out_proj_b = (const float*)d_in[10];
    const float* ln_out_w   = (const float*)d_in[11];
    const float* ln_out_b   = (const float*)d_in[12];
    const float* mlp_w1     = (const float*)d_in[13];
    const float* mlp_b1     = (const float*)d_in[14];
    const float* mlp_w2     = (const float*)d_in[15];
    const float* mlp_b2     = (const float*)d_in[16];
    const void*  attn_mask  = (const void*)d_in[17];
    float* out = (float*)d_out;

    float *xT, *xp, *f, *qkv, *o, *op, *hid, *m1, *m2;
    unsigned* mbp;
    cudaGetSymbolAddress((void**)&xT,  g_xT);
    cudaGetSymbolAddress((void**)&xp,  g_xp);
    cudaGetSymbolAddress((void**)&f,   g_f);
    cudaGetSymbolAddress((void**)&qkv, g_qkv);
    cudaGetSymbolAddress((void**)&o,   g_o);
    cudaGetSymbolAddress((void**)&op,  g_op);
    cudaGetSymbolAddress((void**)&hid, g_hid);
    cudaGetSymbolAddress((void**)&m1,  g_m1);
    cudaGetSymbolAddress((void**)&m2,  g_m2);
    cudaGetSymbolAddress((void**)&mbp, g_mb);

    cudaFuncSetAttribute(k_attn, cudaFuncAttributeMaxDynamicSharedMemorySize, ATTN_SMEM);

    // mask dtype probe + pack (independent, runs first)
    k_probe<<<1, 256>>>((const unsigned*)attn_mask);
    k_pack_mask<<<(Stok * NW + 255) / 256, 256>>>(attn_mask, mbp);

    // transpose x -> token-major
    k_transpose_in<<<dim3(HW / 32, Cc / 32, Bz), dim3(32, 32)>>>(x, xT);

    // conv (1x1) : xp = xT @ conv_w^T + conv_b
    k_gemm<0><<<dim3(Cc / 64, (Bz * HW) / 64), 256>>>(xT, conv_w, conv_b, xp, Bz * HW, Cc, Cc);

    // feats: LN local + pooled LN
    k_ln<<<Bz * HW, 256>>>(xp, HW, ln_local_w, ln_local_b, f, Stok);
    k_pool_ln<<<dim3(144, Bz), 256>>>(xp, ln_reg_w, ln_reg_b, f, 4, HW, 0);
    k_pool_ln<<<dim3(36,  Bz), 256>>>(xp, ln_reg_w, ln_reg_b, f, 8, HW + 144, 1);

    // qkv = f @ in_proj^T + b
    k_gemm<0><<<dim3(768 / 64, (Bz * Stok + 63) / 64), 256>>>(f, in_proj_w, in_proj_b, qkv,
                                                              Bz * Stok, 3 * Cc, Cc);

    // attention (tf32 mma)
    k_attn<<<dim3((Stok + 127) / 128, 8, Bz), 256, ATTN_SMEM>>>(qkv, mbp, o);

    // out_proj over all tokens
    k_gemm<0><<<dim3(Cc / 64, (Bz * Stok + 63) / 64), 256>>>(o, out_proj_w, out_proj_b, op,
                                                             Bz * Stok, Cc, Cc);

    // ln_out on local tokens
    k_ln<<<Bz * HW, 256>>>(op, Stok, ln_out_w, ln_out_b, hid, HW);

    // mlp
    k_gemm<1><<<dim3(BOT / 64, (Bz * HW) / 64), 256>>>(hid, mlp_w1, mlp_b1, m1, Bz * HW, BOT, Cc);
    k_gemm<0><<<dim3(Cc / 64,  (Bz * HW) / 64), 256>>>(m1, mlp_w2, mlp_b2, m2, Bz * HW, Cc, BOT);

    // residual + transpose back + input residual
    k_final<<<dim3(HW / 32, Cc / 32, Bz), dim3(32, 32)>>>(m2, op, x, out);
}

// round 4
// speedup vs baseline: 5.1324x; 1.6249x over previous
#include <cuda_runtime.h>
#include <cuda_bf16.h>
#include <math.h>

#define Bz   4
#define Cc   256
#define Hh   48
#define Ww   48
#define HW   2304
#define Stok 2484
#define NW   78      // ceil(S/32) mask words per row
#define BOT  64

// ---------------- scratch (device globals; no allocations allowed) ----------------
__device__ float g_xT [(size_t)Bz*HW*Cc];
__device__ float g_xp [(size_t)Bz*HW*Cc];
__device__ float g_f  [(size_t)Bz*Stok*Cc];
__device__ float g_qkv[(size_t)Bz*Stok*Cc*3];
__device__ float g_o  [(size_t)Bz*Stok*Cc];
__device__ float g_op [(size_t)Bz*Stok*Cc];
__device__ float g_hid[(size_t)Bz*HW*Cc];
__device__ float g_m1 [(size_t)Bz*HW*BOT];
__device__ float g_m2 [(size_t)Bz*HW*Cc];
__device__ unsigned g_mb[(size_t)Stok*NW];
__device__ int g_mdt;                          // mask dtype: 0=u8, 1=i32, 2=f32

// ---------------- mask dtype probe ----------------
__global__ void k_probe(const unsigned* __restrict__ m) {
    __shared__ int bad_i32, bad_f32;
    if (threadIdx.x == 0) { bad_i32 = 0; bad_f32 = 0; }
    __syncthreads();
    for (int i = threadIdx.x; i < Stok / 4; i += blockDim.x) {
        unsigned v = m[i];
        if (v != 0u && v != 1u)           bad_i32 = 1;
        if (v != 0u && v != 0x3F800000u)  bad_f32 = 1;
    }
    __syncthreads();
    if (threadIdx.x == 0)
        g_mdt = (!bad_i32) ? 1 : ((!bad_f32) ? 2 : 0);
}

// ---------------- pack mask -> bitmask (bit set = blocked) ----------------
__global__ void k_pack_mask(const void* __restrict__ mv, unsigned* __restrict__ out) {
    int idx = blockIdx.x * blockDim.x + threadIdx.x;
    if (idx >= Stok * NW) return;
    int dt = g_mdt;
    int q = idx / NW, w = idx % NW;
    unsigned bits = 0;
    int c0 = w * 32;
    const unsigned char* mu = (const unsigned char*)mv;
    const int*           mi = (const int*)mv;
    const float*         mf = (const float*)mv;
    #pragma unroll 4
    for (int j = 0; j < 32; j++) {
        int c = c0 + j;
        bool blk;
        if (c >= Stok)      blk = true;
        else if (dt == 1)   blk = mi[(size_t)q * Stok + c] != 0;
        else if (dt == 2)   blk = mf[(size_t)q * Stok + c] != 0.0f;
        else                blk = mu[(size_t)q * Stok + c] != 0;
        if (blk) bits |= 1u << j;
    }
    out[idx] = bits;
}

// ---------------- transpose in ----------------
__global__ void k_transpose_in(const float* __restrict__ x, float* __restrict__ xT) {
    __shared__ float t[32][33];
    int b  = blockIdx.z;
    int p0 = blockIdx.x * 32, c0 = blockIdx.y * 32;
    int tx = threadIdx.x, ty = threadIdx.y;
    t[ty][tx] = x[((size_t)b * Cc + c0 + ty) * HW + p0 + tx];
    __syncthreads();
    xT[((size_t)b * HW + p0 + ty) * Cc + c0 + tx] = t[tx][ty];
}

// ---------------- mma helpers ----------------
__device__ __forceinline__ void mma_tf32(float c[4], const float a[4], float b0, float b1) {
    const unsigned* A = reinterpret_cast<const unsigned*>(a);
    unsigned B0 = __float_as_uint(b0), B1 = __float_as_uint(b1);
    asm volatile(
        "mma.sync.aligned.m16n8k8.row.col.f32.tf32.tf32.f32 "
        "{%0,%1,%2,%3},{%4,%5,%6,%7},{%8,%9},{%0,%1,%2,%3};"
        : "+f"(c[0]), "+f"(c[1]), "+f"(c[2]), "+f"(c[3])
        : "r"(A[0]), "r"(A[1]), "r"(A[2]), "r"(A[3]), "r"(B0), "r"(B1));
}

__device__ __forceinline__ void mma_bf16(float c[4], const unsigned a[4],
                                         unsigned b0, unsigned b1) {
    asm volatile(
        "mma.sync.aligned.m16n8k16.row.col.f32.bf16.bf16.f32 "
        "{%0,%1,%2,%3},{%4,%5,%6,%7},{%8,%9},{%0,%1,%2,%3};"
        : "+f"(c[0]), "+f"(c[1]), "+f"(c[2]), "+f"(c[3])
        : "r"(a[0]), "r"(a[1]), "r"(a[2]), "r"(a[3]), "r"(b0), "r"(b1));
}

__device__ __forceinline__ unsigned pkbf(float lo, float hi) {
    __nv_bfloat162 h = __float22bfloat162_rn(make_float2(lo, hi));
    return *reinterpret_cast<unsigned*>(&h);
}

// ---------------- tf32 mma GEMM: C[M,N] = A[M,K] @ W[N,K]^T + bias, opt GELU ----------------
// CTA tile 128x64, 8 warps (warp w -> rows w*16..w*16+15), k-step 16.
__device__ __forceinline__ float gelu_exact(float v) {
    return 0.5f * v * (1.0f + erff(v * 0.70710678118654752f));
}

template<int ACT>
__global__ void __launch_bounds__(256) k_mgemm(
    const float* __restrict__ A, const float* __restrict__ W,
    const float* __restrict__ bias, float* __restrict__ C,
    int M, int N, int K)
{
    __shared__ float As[128][20];
    __shared__ float Bs[64][20];
    int tid = threadIdx.x;
    int warp = tid >> 5, lane = tid & 31;
    int g = lane >> 2, t4 = lane & 3;
    int m0 = blockIdx.y * 128, n0 = blockIdx.x * 64;

    float acc[8][4] = {};

    for (int k0 = 0; k0 < K; k0 += 16) {
        // load A tile: 128 rows x 16 k
        #pragma unroll
        for (int i = tid; i < 512; i += 256) {
            int row = i >> 2, kk = (i & 3) * 4;
            int gm = m0 + row;
            float4 v = (gm < M) ? *(const float4*)(A + (size_t)gm * K + k0 + kk)
                                : make_float4(0.f, 0.f, 0.f, 0.f);
            *(float4*)&As[row][kk] = v;
        }
        // load W tile: 64 rows x 16 k
        {
            int row = tid >> 2, kk = (tid & 3) * 4;
            *(float4*)&Bs[row][kk] = *(const float4*)(W + (size_t)(n0 + row) * K + k0 + kk);
        }
        __syncthreads();

        float a[2][4];
        #pragma unroll
        for (int ks = 0; ks < 2; ks++) {
            a[ks][0] = As[warp * 16 + g][ks * 8 + t4];
            a[ks][1] = As[warp * 16 + 8 + g][ks * 8 + t4];
            a[ks][2] = As[warp * 16 + g][ks * 8 + t4 + 4];
            a[ks][3] = As[warp * 16 + 8 + g][ks * 8 + t4 + 4];
        }
        #pragma unroll
        for (int n8 = 0; n8 < 8; n8++) {
            #pragma unroll
            for (int ks = 0; ks < 2; ks++) {
                float b0 = Bs[n8 * 8 + g][ks * 8 + t4];
                float b1 = Bs[n8 * 8 + g][ks * 8 + t4 + 4];
                mma_tf32(acc[n8], a[ks], b0, b1);
            }
        }
        __syncthreads();
    }

    // epilogue
    int gm0 = m0 + warp * 16 + g;
    int gm1 = gm0 + 8;
    #pragma unroll
    for (int n8 = 0; n8 < 8; n8++) {
        int col = n0 + n8 * 8 + 2 * t4;
        float2 bb = *(const float2*)(bias + col);
        float v0 = acc[n8][0] + bb.x, v1 = acc[n8][1] + bb.y;
        float v2 = acc[n8][2] + bb.x, v3 = acc[n8][3] + bb.y;
        if (ACT == 1) {
            v0 = gelu_exact(v0); v1 = gelu_exact(v1);
            v2 = gelu_exact(v2); v3 = gelu_exact(v3);
        }
        if (gm0 < M) *(float2*)(C + (size_t)gm0 * N + col) = make_float2(v0, v1);
        if (gm1 < M) *(float2*)(C + (size_t)gm1 * N + col) = make_float2(v2, v3);
    }
}

// ---------------- row layernorm over C=256 ----------------
__global__ void k_ln(const float* __restrict__ in, int inTok,
                     const float* __restrict__ w, const float* __restrict__ bv,
                     float* __restrict__ out, int outTok)
{
    int r = blockIdx.x;
    int b = r / HW, p = r % HW;
    int c = threadIdx.x;
    const float* row = in + ((size_t)b * inTok + p) * Cc;
    float v = row[c];
    __shared__ float sb[8];
    float s = v;
    #pragma unroll
    for (int o = 16; o > 0; o >>= 1) s += __shfl_xor_sync(0xffffffffu, s, o);
    if ((c & 31) == 0) sb[c >> 5] = s;
    __syncthreads();
    float tot = 0.f;
    #pragma unroll
    for (int i = 0; i < 8; i++) tot += sb[i];
    float mean = tot * (1.0f / 256.0f);
    __syncthreads();
    float d = v - mean;
    float s2 = d * d;
    #pragma unroll
    for (int o = 16; o > 0; o >>= 1) s2 += __shfl_xor_sync(0xffffffffu, s2, o);
    if ((c & 31) == 0) sb[c >> 5] = s2;
    __syncthreads();
    float tot2 = 0.f;
    #pragma unroll
    for (int i = 0; i < 8; i++) tot2 += sb[i];
    float var = tot2 * (1.0f / 256.0f);
    float rs = rsqrtf(var + 1e-5f);
    out[((size_t)b * outTok + p) * Cc + c] = d * rs * w[c] + bv[c];
}

// ---------------- pool (ps x ps mean) + layernorm ----------------
__global__ void k_pool_ln(const float* __restrict__ xp,
                          const float* __restrict__ w, const float* __restrict__ bv,
                          float* __restrict__ f, int ps, int off, int reg)
{
    int b = blockIdx.y;
    int t = blockIdx.x;
    int gw = Ww / ps;
    int bh = t / gw, bw = t % gw;
    int c = threadIdx.x;
    float s = 0.f;
    for (int i = 0; i < ps; i++) {
        int prow = (bh * ps + i) * Ww + bw * ps;
        const float* base = xp + ((size_t)b * HW + prow) * Cc + c;
        for (int j = 0; j < ps; j++) s += base[(size_t)j * Cc];
    }
    float v = s / (float)(ps * ps);
    __shared__ float sb[8];
    float ss = v;
    #pragma unroll
    for (int o = 16; o > 0; o >>= 1) ss += __shfl_xor_sync(0xffffffffu, ss, o);
    if ((c & 31) == 0) sb[c >> 5] = ss;
    __syncthreads();
    float tot = 0.f;
    #pragma unroll
    for (int i = 0; i < 8; i++) tot += sb[i];
    float mean = tot * (1.0f / 256.0f);
    __syncthreads();
    float d = v - mean;
    float s2 = d * d;
    #pragma unroll
    for (int o = 16; o > 0; o >>= 1) s2 += __shfl_xor_sync(0xffffffffu, s2, o);
    if ((c & 31) == 0) sb[c >> 5] = s2;
    __syncthreads();
    float tot2 = 0.f;
    #pragma unroll
    for (int i = 0; i < 8; i++) tot2 += sb[i];
    float rs = rsqrtf(tot2 * (1.0f / 256.0f) + 1e-5f);
    f[((size_t)b * Stok + off + t) * Cc + c] = d * rs * w[reg * Cc + c] + bv[reg * Cc + c];
}

// ---------------- bf16 mma flash attention ----------------
// BQ=128 (8 warps x 16 rows), BK=64, dh=32. P stays in registers (C-frag -> A-frag).
#define KV_TILES 39

__global__ void __launch_bounds__(256) k_attn(const float* __restrict__ qkv,
                                              const unsigned* __restrict__ mb,
                                              float* __restrict__ out)
{
    __shared__ unsigned Ksh[64][20];   // [key][dh/2] bf16x2 pairs (dh-packed), pad 20
    __shared__ unsigned VsT[32][36];   // [dh][key/2] bf16x2 pairs (key-packed), pad 36
    __shared__ unsigned Msm[256];      // 128 q rows x 2 words
    __nv_bfloat16* VsT16 = (__nv_bfloat16*)VsT;   // stride 72 per d row

    int tid  = threadIdx.x;
    int warp = tid >> 5, lane = tid & 31;
    int g = lane >> 2, t4 = lane & 3;
    int q0 = blockIdx.x * 128, h = blockIdx.y, b = blockIdx.z;

    const float* qb = qkv + ((size_t)b * Stok) * 768 + h * 32;
    const float* kb = qb + 256;
    const float* vb = qb + 512;

    const float SC = 0.17677669529663687f;  // 1/sqrt(32)
    int r0 = q0 + warp * 16 + g;
    int r1 = r0 + 8;

    // Q fragments (pre-scaled, bf16-packed): qa[kstep][0..3]
    unsigned qa[2][4];
    #pragma unroll
    for (int ks = 0; ks < 2; ks++) {
        #pragma unroll
        for (int half = 0; half < 2; half++) {   // a0/a1 then a2/a3
            int kc = ks * 16 + half * 8 + 2 * t4;
            float2 u0 = (r0 < Stok) ? *(const float2*)(qb + (size_t)r0 * 768 + kc)
                                    : make_float2(0.f, 0.f);
            float2 u1 = (r1 < Stok) ? *(const float2*)(qb + (size_t)r1 * 768 + kc)
                                    : make_float2(0.f, 0.f);
            qa[ks][half * 2 + 0] = pkbf(u0.x * SC, u0.y * SC);
            qa[ks][half * 2 + 1] = pkbf(u1.x * SC, u1.y * SC);
        }
    }

    float m0 = -3.0e38f, m1 = -3.0e38f, l0 = 0.f, l1 = 0.f;
    float o[4][4] = {};

    for (int kt = 0; kt < KV_TILES; kt++) {
        int k0 = kt * 64;
        // ---- load K (dh-packed bf16) and V (transposed, key-packed bf16) ----
        #pragma unroll
        for (int i = tid; i < 512; i += 256) {
            int row = i >> 3, c4 = (i & 7) << 2;
            int gk = k0 + row;
            float4 kv, vv;
            if (gk < Stok) {
                kv = *(const float4*)(kb + (size_t)gk * 768 + c4);
                vv = *(const float4*)(vb + (size_t)gk * 768 + c4);
            } else {
                kv = make_float4(0.f, 0.f, 0.f, 0.f); vv = kv;
            }
            Ksh[row][(c4 >> 1) + 0] = pkbf(kv.x, kv.y);
            Ksh[row][(c4 >> 1) + 1] = pkbf(kv.z, kv.w);
            VsT16[(c4 + 0) * 72 + row] = __float2bfloat16_rn(vv.x);
            VsT16[(c4 + 1) * 72 + row] = __float2bfloat16_rn(vv.y);
            VsT16[(c4 + 2) * 72 + row] = __float2bfloat16_rn(vv.z);
            VsT16[(c4 + 3) * 72 + row] = __float2bfloat16_rn(vv.w);
        }
        {
            int row = tid >> 1, w = tid & 1;
            int gq = q0 + row;
            Msm[row * 2 + w] = (gq < Stok) ? mb[(size_t)gq * NW + kt * 2 + w] : 0xFFFFFFFFu;
        }
        __syncthreads();

        // ---- QK^T ----
        float s[8][4];
        #pragma unroll
        for (int n8 = 0; n8 < 8; n8++) {
            s[n8][0] = s[n8][1] = s[n8][2] = s[n8][3] = 0.f;
            #pragma unroll
            for (int ks = 0; ks < 2; ks++) {
                unsigned b0 = Ksh[n8 * 8 + g][ks * 8 + t4];
                unsigned b1 = Ksh[n8 * 8 + g][ks * 8 + t4 + 4];
                mma_bf16(s[n8], qa[ks], b0, b1);
            }
        }

        // ---- mask ----
        unsigned w00 = Msm[(warp * 16 + g) * 2 + 0];
        unsigned w01 = Msm[(warp * 16 + g) * 2 + 1];
        unsigned w10 = Msm[(warp * 16 + 8 + g) * 2 + 0];
        unsigned w11 = Msm[(warp * 16 + 8 + g) * 2 + 1];
        #pragma unroll
        for (int n8 = 0; n8 < 8; n8++) {
            int sh = (n8 * 8 + 2 * t4) & 31;
            unsigned mr0 = (n8 < 4) ? w00 : w01;
            unsigned mr1 = (n8 < 4) ? w10 : w11;
            if ((mr0 >> sh) & 1u)        s[n8][0] = -1.0e9f;
            if ((mr0 >> (sh + 1)) & 1u)  s[n8][1] = -1.0e9f;
            if ((mr1 >> sh) & 1u)        s[n8][2] = -1.0e9f;
            if ((mr1 >> (sh + 1)) & 1u)  s[n8][3] = -1.0e9f;
        }

        // ---- online softmax (quad reductions) ----
        float tm0 = -3.0e38f, tm1 = -3.0e38f;
        #pragma unroll
        for (int n8 = 0; n8 < 8; n8++) {
            tm0 = fmaxf(tm0, fmaxf(s[n8][0], s[n8][1]));
            tm1 = fmaxf(tm1, fmaxf(s[n8][2], s[n8][3]));
        }
        tm0 = fmaxf(tm0, __shfl_xor_sync(0xffffffffu, tm0, 1));
        tm0 = fmaxf(tm0, __shfl_xor_sync(0xffffffffu, tm0, 2));
        tm1 = fmaxf(tm1, __shfl_xor_sync(0xffffffffu, tm1, 1));
        tm1 = fmaxf(tm1, __shfl_xor_sync(0xffffffffu, tm1, 2));
        float mn0 = fmaxf(m0, tm0), mn1 = fmaxf(m1, tm1);
        float a0 = __expf(m0 - mn0), a1 = __expf(m1 - mn1);
        m0 = mn0; m1 = mn1;

        float rs0 = 0.f, rs1 = 0.f;
        #pragma unroll
        for (int n8 = 0; n8 < 8; n8++) {
            s[n8][0] = __expf(s[n8][0] - mn0);
            s[n8][1] = __expf(s[n8][1] - mn0);
            s[n8][2] = __expf(s[n8][2] - mn1);
            s[n8][3] = __expf(s[n8][3] - mn1);
            rs0 += s[n8][0] + s[n8][1];
            rs1 += s[n8][2] + s[n8][3];
        }
        rs0 += __shfl_xor_sync(0xffffffffu, rs0, 1);
        rs0 += __shfl_xor_sync(0xffffffffu, rs0, 2);
        rs1 += __shfl_xor_sync(0xffffffffu, rs1, 1);
        rs1 += __shfl_xor_sync(0xffffffffu, rs1, 2);
        l0 = l0 * a0 + rs0;
        l1 = l1 * a1 + rs1;
        #pragma unroll
        for (int d8 = 0; d8 < 4; d8++) {
            o[d8][0] *= a0; o[d8][1] *= a0; o[d8][2] *= a1; o[d8][3] *= a1;
        }

        // ---- P: C-frags -> bf16 A-frags (register-only) ----
        unsigned pa[4][4];
        #pragma unroll
        for (int j = 0; j < 4; j++) {
            pa[j][0] = pkbf(s[2*j][0],   s[2*j][1]);
            pa[j][1] = pkbf(s[2*j][2],   s[2*j][3]);
            pa[j][2] = pkbf(s[2*j+1][0], s[2*j+1][1]);
            pa[j][3] = pkbf(s[2*j+1][2], s[2*j+1][3]);
        }

        // ---- PV ----
        #pragma unroll
        for (int d8 = 0; d8 < 4; d8++) {
            #pragma unroll
            for (int j = 0; j < 4; j++) {
                unsigned b0 = VsT[d8 * 8 + g][j * 8 + t4];
                unsigned b1 = VsT[d8 * 8 + g][j * 8 + t4 + 4];
                mma_bf16(o[d8], pa[j], b0, b1);
            }
        }
        __syncthreads();
    }

    // ---- epilogue ----
    float inv0 = 1.0f / l0, inv1 = 1.0f / l1;
    #pragma unroll
    for (int d8 = 0; d8 < 4; d8++) {
        int dc = h * 32 + d8 * 8 + 2 * t4;
        if (r0 < Stok)
            *(float2*)(out + ((size_t)b * Stok + r0) * 256 + dc) =
                make_float2(o[d8][0] * inv0, o[d8][1] * inv0);
        if (r1 < Stok)
            *(float2*)(out + ((size_t)b * Stok + r1) * 256 + dc) =
                make_float2(o[d8][2] * inv1, o[d8][3] * inv1);
    }
}

// ---------------- final: out[b][c][p] = m2[p][c] + op[p][c] + x[b][c][p] ----------------
__global__ void k_final(const float* __restrict__ m2, const float* __restrict__ op,
                        const float* __restrict__ x, float* __restrict__ out)
{
    __shared__ float t[32][33];
    int b = blockIdx.z;
    int p0 = blockIdx.x * 32, c0 = blockIdx.y * 32;
    int tx = threadIdx.x, ty = threadIdx.y;
    t[ty][tx] = m2[((size_t)b * HW + p0 + ty) * Cc + c0 + tx]
              + op[((size_t)b * Stok + p0 + ty) * Cc + c0 + tx];
    __syncthreads();
    size_t oi = ((size_t)b * Cc + c0 + ty) * HW + p0 + tx;
    out[oi] = t[tx][ty] + x[oi];
}

// ---------------- launch ----------------
extern "C" void kernel_launch(void* const* d_in, const int* in_sizes, int n_in,
                              void* d_out, int out_size)
{
    const float* x          = (const float*)d_in[0];
    const float* conv_w     = (const float*)d_in[1];
    const float* conv_b     = (const float*)d_in[2];
    const float* ln_local_w = (const float*)d_in[3];
    const float* ln_local_b = (const float*)d_in[4];
    const float* ln_reg_w   = (const float*)d_in[5];
    const float* ln_reg_b   = (const float*)d_in[6];
    const float* in_proj_w  = (const float*)d_in[7];
    const float* in_proj_b  = (const float*)d_in[8];
    const float* out_proj_w = (const float*)d_in[9];
    const float* out_proj_b = (const float*)d_in[10];
    const float* ln_out_w   = (const float*)d_in[11];
    const float* ln_out_b   = (const float*)d_in[12];
    const float* mlp_w1     = (const float*)d_in[13];
    const float* mlp_b1     = (const float*)d_in[14];
    const float* mlp_w2     = (const float*)d_in[15];
    const float* mlp_b2     = (const float*)d_in[16];
    const void*  attn_mask  = (const void*)d_in[17];
    float* out = (float*)d_out;

    float *xT, *xp, *f, *qkv, *o, *op, *hid, *m1, *m2;
    unsigned* mbp;
    cudaGetSymbolAddress((void**)&xT,  g_xT);
    cudaGetSymbolAddress((void**)&xp,  g_xp);
    cudaGetSymbolAddress((void**)&f,   g_f);
    cudaGetSymbolAddress((void**)&qkv, g_qkv);
    cudaGetSymbolAddress((void**)&o,   g_o);
    cudaGetSymbolAddress((void**)&op,  g_op);
    cudaGetSymbolAddress((void**)&hid, g_hid);
    cudaGetSymbolAddress((void**)&m1,  g_m1);
    cudaGetSymbolAddress((void**)&m2,  g_m2);
    cudaGetSymbolAddress((void**)&mbp, g_mb);

    // mask dtype probe + pack
    k_probe<<<1, 256>>>((const unsigned*)attn_mask);
    k_pack_mask<<<(Stok * NW + 255) / 256, 256>>>(attn_mask, mbp);

    // transpose x -> token-major
    k_transpose_in<<<dim3(HW / 32, Cc / 32, Bz), dim3(32, 32)>>>(x, xT);

    // conv (1x1)
    k_mgemm<0><<<dim3(Cc / 64, (Bz * HW + 127) / 128), 256>>>(xT, conv_w, conv_b, xp,
                                                              Bz * HW, Cc, Cc);

    // feats: LN local + pooled LN
    k_ln<<<Bz * HW, 256>>>(xp, HW, ln_local_w, ln_local_b, f, Stok);
    k_pool_ln<<<dim3(144, Bz), 256>>>(xp, ln_reg_w, ln_reg_b, f, 4, HW, 0);
    k_pool_ln<<<dim3(36,  Bz), 256>>>(xp, ln_reg_w, ln_reg_b, f, 8, HW + 144, 1);

    // qkv = f @ in_proj^T + b
    k_mgemm<0><<<dim3(768 / 64, (Bz * Stok + 127) / 128), 256>>>(f, in_proj_w, in_proj_b, qkv,
                                                                 Bz * Stok, 3 * Cc, Cc);

    // attention (bf16 mma)
    k_attn<<<dim3((Stok + 127) / 128, 8, Bz), 256>>>(qkv, mbp, o);

    // out_proj
    k_mgemm<0><<<dim3(Cc / 64, (Bz * Stok + 127) / 128), 256>>>(o, out_proj_w, out_proj_b, op,
                                                                Bz * Stok, Cc, Cc);

    // ln_out on local tokens
    k_ln<<<Bz * HW, 256>>>(op, Stok, ln_out_w, ln_out_b, hid, HW);

    // mlp
    k_mgemm<1><<<dim3(BOT / 64, (Bz * HW + 127) / 128), 256>>>(hid, mlp_w1, mlp_b1, m1,
                                                               Bz * HW, BOT, Cc);
    k_mgemm<0><<<dim3(Cc / 64,  (Bz * HW + 127) / 128), 256>>>(m1, mlp_w2, mlp_b2, m2,
                                                               Bz * HW, Cc, BOT);

    // residual + transpose back + input residual
    k_final<<<dim3(HW / 32, Cc / 32, Bz), dim3(32, 32)>>>(m2, op, x, out);
}

// round 5
// speedup vs baseline: 6.0019x; 1.1694x over previous
#include <cuda_runtime.h>
#include <cuda_bf16.h>
#include <math.h>

#define Bz   4
#define Cc   256
#define Hh   48
#define Ww   48
#define HW   2304
#define Stok 2484
#define NW   78      // ceil(S/32) mask words per row
#define KPAD 2496    // 39 * 64
#define BOT  64

// ---------------- scratch (device globals; no allocations allowed) ----------------
__device__ float g_xT [(size_t)Bz*HW*Cc];
__device__ float g_xp [(size_t)Bz*HW*Cc];
__device__ float g_f  [(size_t)Bz*Stok*Cc];
__device__ float g_qkv[(size_t)Bz*Stok*Cc*3];
__device__ float g_o  [(size_t)Bz*Stok*Cc];
__device__ float g_op [(size_t)Bz*Stok*Cc];
__device__ float g_hid[(size_t)Bz*HW*Cc];
__device__ float g_m1 [(size_t)Bz*HW*BOT];
__device__ float g_m2 [(size_t)Bz*HW*Cc];
__device__ unsigned g_mb[(size_t)Stok*NW];
__device__ __nv_bfloat16 g_Kb [(size_t)Bz*8*KPAD*32];   // [b][h][key][32]
__device__ __nv_bfloat16 g_VbT[(size_t)Bz*8*32*KPAD];   // [b][h][32][key]
__device__ int g_mdt;                          // mask dtype: 0=u8, 1=i32, 2=f32

// ---------------- small helpers ----------------
__device__ __forceinline__ void cpa16(void* dst, const void* src) {
    unsigned d = (unsigned)__cvta_generic_to_shared(dst);
    asm volatile("cp.async.cg.shared.global [%0], [%1], 16;" :: "r"(d), "l"(src));
}
__device__ __forceinline__ void cpa16z(void* dst, const void* src, int sz) {
    unsigned d = (unsigned)__cvta_generic_to_shared(dst);
    asm volatile("cp.async.cg.shared.global [%0], [%1], 16, %2;" :: "r"(d), "l"(src), "r"(sz));
}
__device__ __forceinline__ void cpa_commit() { asm volatile("cp.async.commit_group;"); }
__device__ __forceinline__ void cpa_wait0()  { asm volatile("cp.async.wait_group 0;"); }

__device__ __forceinline__ void mma_tf32(float c[4], const float a[4], float b0, float b1) {
    const unsigned* A = reinterpret_cast<const unsigned*>(a);
    unsigned B0 = __float_as_uint(b0), B1 = __float_as_uint(b1);
    asm volatile(
        "mma.sync.aligned.m16n8k8.row.col.f32.tf32.tf32.f32 "
        "{%0,%1,%2,%3},{%4,%5,%6,%7},{%8,%9},{%0,%1,%2,%3};"
        : "+f"(c[0]), "+f"(c[1]), "+f"(c[2]), "+f"(c[3])
        : "r"(A[0]), "r"(A[1]), "r"(A[2]), "r"(A[3]), "r"(B0), "r"(B1));
}
__device__ __forceinline__ void mma_bf16(float c[4], const unsigned a[4],
                                         unsigned b0, unsigned b1) {
    asm volatile(
        "mma.sync.aligned.m16n8k16.row.col.f32.bf16.bf16.f32 "
        "{%0,%1,%2,%3},{%4,%5,%6,%7},{%8,%9},{%0,%1,%2,%3};"
        : "+f"(c[0]), "+f"(c[1]), "+f"(c[2]), "+f"(c[3])
        : "r"(a[0]), "r"(a[1]), "r"(a[2]), "r"(a[3]), "r"(b0), "r"(b1));
}
__device__ __forceinline__ unsigned pkbf(float lo, float hi) {
    __nv_bfloat162 h = __float22bfloat162_rn(make_float2(lo, hi));
    return *reinterpret_cast<unsigned*>(&h);
}

// ---------------- mask dtype probe ----------------
__global__ void k_probe(const unsigned* __restrict__ m) {
    __shared__ int bad_i32, bad_f32;
    if (threadIdx.x == 0) { bad_i32 = 0; bad_f32 = 0; }
    __syncthreads();
    for (int i = threadIdx.x; i < Stok / 4; i += blockDim.x) {
        unsigned v = m[i];
        if (v != 0u && v != 1u)           bad_i32 = 1;
        if (v != 0u && v != 0x3F800000u)  bad_f32 = 1;
    }
    __syncthreads();
    if (threadIdx.x == 0)
        g_mdt = (!bad_i32) ? 1 : ((!bad_f32) ? 2 : 0);
}

// ---------------- pack mask -> bitmask (bit set = blocked) ----------------
__global__ void k_pack_mask(const void* __restrict__ mv, unsigned* __restrict__ out) {
    int idx = blockIdx.x * blockDim.x + threadIdx.x;
    if (idx >= Stok * NW) return;
    int dt = g_mdt;
    int q = idx / NW, w = idx % NW;
    unsigned bits = 0;
    int c0 = w * 32;
    const unsigned char* mu = (const unsigned char*)mv;
    const int*           mi = (const int*)mv;
    const float*         mf = (const float*)mv;
    #pragma unroll 4
    for (int j = 0; j < 32; j++) {
        int c = c0 + j;
        bool blk;
        if (c >= Stok)      blk = true;
        else if (dt == 1)   blk = mi[(size_t)q * Stok + c] != 0;
        else if (dt == 2)   blk = mf[(size_t)q * Stok + c] != 0.0f;
        else                blk = mu[(size_t)q * Stok + c] != 0;
        if (blk) bits |= 1u << j;
    }
    out[idx] = bits;
}

// ---------------- transpose in ----------------
__global__ void k_transpose_in(const float* __restrict__ x, float* __restrict__ xT) {
    __shared__ float t[32][33];
    int b  = blockIdx.z;
    int p0 = blockIdx.x * 32, c0 = blockIdx.y * 32;
    int tx = threadIdx.x, ty = threadIdx.y;
    t[ty][tx] = x[((size_t)b * Cc + c0 + ty) * HW + p0 + tx];
    __syncthreads();
    xT[((size_t)b * HW + p0 + ty) * Cc + c0 + tx] = t[tx][ty];
}

// ---------------- tf32 mma GEMM, cp.async double-buffered ----------------
__device__ __forceinline__ float gelu_exact(float v) {
    return 0.5f * v * (1.0f + erff(v * 0.70710678118654752f));
}

template<int ACT>
__global__ void __launch_bounds__(256) k_mgemm(
    const float* __restrict__ A, const float* __restrict__ W,
    const float* __restrict__ bias, float* __restrict__ C,
    int M, int N, int K)
{
    __shared__ __align__(16) float As[2][128 * 20];
    __shared__ __align__(16) float Bs[2][64 * 20];
    int tid = threadIdx.x;
    int warp = tid >> 5, lane = tid & 31;
    int g = lane >> 2, t4 = lane & 3;
    int m0 = blockIdx.y * 128, n0 = blockIdx.x * 64;

    auto issue = [&](int k0, int st) {
        #pragma unroll
        for (int i = tid; i < 512; i += 256) {
            int row = i >> 2, c = i & 3;
            int gm = m0 + row;
            int ok = gm < M;
            const float* src = A + (size_t)(ok ? gm : 0) * K + k0 + c * 4;
            cpa16z(&As[st][row * 20 + c * 4], src, ok ? 16 : 0);
        }
        {
            int row = tid >> 2, c = tid & 3;
            cpa16(&Bs[st][row * 20 + c * 4], W + (size_t)(n0 + row) * K + k0 + c * 4);
        }
        cpa_commit();
    };

    float acc[8][4] = {};
    issue(0, 0);
    int nk = K >> 4;
    for (int ki = 0; ki < nk; ki++) {
        cpa_wait0();
        __syncthreads();
        if (ki + 1 < nk) issue((ki + 1) << 4, (ki + 1) & 1);
        const float* as = As[ki & 1];
        const float* bs = Bs[ki & 1];

        float a[2][4];
        #pragma unroll
        for (int ks = 0; ks < 2; ks++) {
            a[ks][0] = as[(warp * 16 + g) * 20 + ks * 8 + t4];
            a[ks][1] = as[(warp * 16 + 8 + g) * 20 + ks * 8 + t4];
            a[ks][2] = as[(warp * 16 + g) * 20 + ks * 8 + t4 + 4];
            a[ks][3] = as[(warp * 16 + 8 + g) * 20 + ks * 8 + t4 + 4];
        }
        #pragma unroll
        for (int n8 = 0; n8 < 8; n8++) {
            #pragma unroll
            for (int ks = 0; ks < 2; ks++) {
                float b0 = bs[(n8 * 8 + g) * 20 + ks * 8 + t4];
                float b1 = bs[(n8 * 8 + g) * 20 + ks * 8 + t4 + 4];
                mma_tf32(acc[n8], a[ks], b0, b1);
            }
        }
    }

    // epilogue
    int gm0 = m0 + warp * 16 + g;
    int gm1 = gm0 + 8;
    #pragma unroll
    for (int n8 = 0; n8 < 8; n8++) {
        int col = n0 + n8 * 8 + 2 * t4;
        float2 bb = *(const float2*)(bias + col);
        float v0 = acc[n8][0] + bb.x, v1 = acc[n8][1] + bb.y;
        float v2 = acc[n8][2] + bb.x, v3 = acc[n8][3] + bb.y;
        if (ACT == 1) {
            v0 = gelu_exact(v0); v1 = gelu_exact(v1);
            v2 = gelu_exact(v2); v3 = gelu_exact(v3);
        }
        if (gm0 < M) *(float2*)(C + (size_t)gm0 * N + col) = make_float2(v0, v1);
        if (gm1 < M) *(float2*)(C + (size_t)gm1 * N + col) = make_float2(v2, v3);
    }
}

// ---------------- warp-per-row layernorm over C=256 ----------------
__global__ void k_ln(const float* __restrict__ in, int inTok,
                     const float* __restrict__ w, const float* __restrict__ bv,
                     float* __restrict__ out, int outTok)
{
    int row = blockIdx.x * 8 + (threadIdx.x >> 5);
    int lane = threadIdx.x & 31;
    int b = row / HW, p = row % HW;
    const float* src = in + ((size_t)b * inTok + p) * Cc;
    float4 v0 = *(const float4*)(src + lane * 4);
    float4 v1 = *(const float4*)(src + 128 + lane * 4);
    float s = v0.x + v0.y + v0.z + v0.w + v1.x + v1.y + v1.z + v1.w;
    #pragma unroll
    for (int o = 16; o > 0; o >>= 1) s += __shfl_xor_sync(0xffffffffu, s, o);
    float mean = s * (1.0f / 256.0f);
    float d0x = v0.x - mean, d0y = v0.y - mean, d0z = v0.z - mean, d0w = v0.w - mean;
    float d1x = v1.x - mean, d1y = v1.y - mean, d1z = v1.z - mean, d1w = v1.w - mean;
    float s2 = d0x*d0x + d0y*d0y + d0z*d0z + d0w*d0w
             + d1x*d1x + d1y*d1y + d1z*d1z + d1w*d1w;
    #pragma unroll
    for (int o = 16; o > 0; o >>= 1) s2 += __shfl_xor_sync(0xffffffffu, s2, o);
    float rs = rsqrtf(s2 * (1.0f / 256.0f) + 1e-5f);
    float4 w0 = *(const float4*)(w + lane * 4);
    float4 w1 = *(const float4*)(w + 128 + lane * 4);
    float4 b0 = *(const float4*)(bv + lane * 4);
    float4 b1 = *(const float4*)(bv + 128 + lane * 4);
    float* dst = out + ((size_t)b * outTok + p) * Cc;
    *(float4*)(dst + lane * 4) =
        make_float4(d0x*rs*w0.x + b0.x, d0y*rs*w0.y + b0.y, d0z*rs*w0.z + b0.z, d0w*rs*w0.w + b0.w);
    *(float4*)(dst + 128 + lane * 4) =
        make_float4(d1x*rs*w1.x + b1.x, d1y*rs*w1.y + b1.y, d1z*rs*w1.z + b1.z, d1w*rs*w1.w + b1.w);
}

// ---------------- pool (ps x ps mean) + layernorm ----------------
__global__ void k_pool_ln(const float* __restrict__ xp,
                          const float* __restrict__ w, const float* __restrict__ bv,
                          float* __restrict__ f, int ps, int off, int reg)
{
    int b = blockIdx.y;
    int t = blockIdx.x;
    int gw = Ww / ps;
    int bh = t / gw, bw = t % gw;
    int c = threadIdx.x;
    float s = 0.f;
    for (int i = 0; i < ps; i++) {
        int prow = (bh * ps + i) * Ww + bw * ps;
        const float* base = xp + ((size_t)b * HW + prow) * Cc + c;
        for (int j = 0; j < ps; j++) s += base[(size_t)j * Cc];
    }
    float v = s / (float)(ps * ps);
    __shared__ float sb[8];
    float ss = v;
    #pragma unroll
    for (int o = 16; o > 0; o >>= 1) ss += __shfl_xor_sync(0xffffffffu, ss, o);
    if ((c & 31) == 0) sb[c >> 5] = ss;
    __syncthreads();
    float tot = 0.f;
    #pragma unroll
    for (int i = 0; i < 8; i++) tot += sb[i];
    float mean = tot * (1.0f / 256.0f);
    __syncthreads();
    float d = v - mean;
    float s2 = d * d;
    #pragma unroll
    for (int o = 16; o > 0; o >>= 1) s2 += __shfl_xor_sync(0xffffffffu, s2, o);
    if ((c & 31) == 0) sb[c >> 5] = s2;
    __syncthreads();
    float tot2 = 0.f;
    #pragma unroll
    for (int i = 0; i < 8; i++) tot2 += sb[i];
    float rs = rsqrtf(tot2 * (1.0f / 256.0f) + 1e-5f);
    f[((size_t)b * Stok + off + t) * Cc + c] = d * rs * w[reg * Cc + c] + bv[reg * Cc + c];
}

// ---------------- pack K (bf16, padded) and V (bf16, transposed) per head ----------------
__global__ void __launch_bounds__(256) k_pack_qkv(const float* __restrict__ qkv,
                                                  __nv_bfloat16* __restrict__ Kb,
                                                  __nv_bfloat16* __restrict__ VbT)
{
    __shared__ float Vt[64][36];
    int kt = blockIdx.x, h = blockIdx.y, b = blockIdx.z;
    int bh = b * 8 + h;
    int tid = threadIdx.x;
    int key = tid >> 2, dg = tid & 3, d0 = dg * 8;
    int gk = kt * 64 + key;

    float4 kv0, kv1, vv0, vv1;
    if (gk < Stok) {
        const float* base = qkv + ((size_t)b * Stok + gk) * 768 + h * 32;
        kv0 = *(const float4*)(base + 256 + d0);
        kv1 = *(const float4*)(base + 256 + d0 + 4);
        vv0 = *(const float4*)(base + 512 + d0);
        vv1 = *(const float4*)(base + 512 + d0 + 4);
    } else {
        kv0 = make_float4(0.f, 0.f, 0.f, 0.f);
        kv1 = kv0; vv0 = kv0; vv1 = kv0;
    }
    // K store: [bh][key][32]
    uint4 kp = make_uint4(pkbf(kv0.x, kv0.y), pkbf(kv0.z, kv0.w),
                          pkbf(kv1.x, kv1.y), pkbf(kv1.z, kv1.w));
    *(uint4*)(Kb + ((size_t)bh * KPAD + kt * 64 + key) * 32 + d0) = kp;

    // V -> smem -> transposed store: [bh][d][key]
    *(float4*)&Vt[key][d0]     = vv0;
    *(float4*)&Vt[key][d0 + 4] = vv1;
    __syncthreads();
    int d = tid >> 3, kq = (tid & 7) * 8;
    uint4 vp = make_uint4(pkbf(Vt[kq + 0][d], Vt[kq + 1][d]),
                          pkbf(Vt[kq + 2][d], Vt[kq + 3][d]),
                          pkbf(Vt[kq + 4][d], Vt[kq + 5][d]),
                          pkbf(Vt[kq + 6][d], Vt[kq + 7][d]));
    *(uint4*)(VbT + ((size_t)bh * 32 + d) * KPAD + kt * 64 + kq) = vp;
}

// ---------------- bf16 mma flash attention, cp.async double-buffered ----------------
#define KV_TILES 39

__global__ void __launch_bounds__(256) k_attn(const float* __restrict__ qkv,
                                              const __nv_bfloat16* __restrict__ Kb,
                                              const __nv_bfloat16* __restrict__ VbT,
                                              const unsigned* __restrict__ mb,
                                              float* __restrict__ out)
{
    __shared__ __align__(16) unsigned char KsB[2][64 * 80];    // [key][40 halves pad]
    __shared__ __align__(16) unsigned char VsB[2][32 * 144];   // [d][72 halves pad]
    __shared__ unsigned Msm[2][256];

    int tid  = threadIdx.x;
    int warp = tid >> 5, lane = tid & 31;
    int g = lane >> 2, t4 = lane & 3;
    int q0 = blockIdx.x * 128, h = blockIdx.y, b = blockIdx.z;
    int bh = b * 8 + h;

    const __nv_bfloat16* Kg = Kb  + (size_t)bh * KPAD * 32;
    const __nv_bfloat16* Vg = VbT + (size_t)bh * 32 * KPAD;
    const float* qb = qkv + ((size_t)b * Stok) * 768 + h * 32;

    const float SC = 0.17677669529663687f;  // 1/sqrt(32)
    int r0 = q0 + warp * 16 + g;
    int r1 = r0 + 8;

    // Q fragments (pre-scaled, bf16-packed)
    unsigned qa[2][4];
    #pragma unroll
    for (int ks = 0; ks < 2; ks++) {
        #pragma unroll
        for (int half = 0; half < 2; half++) {
            int kc = ks * 16 + half * 8 + 2 * t4;
            float2 u0 = (r0 < Stok) ? *(const float2*)(qb + (size_t)r0 * 768 + kc)
                                    : make_float2(0.f, 0.f);
            float2 u1 = (r1 < Stok) ? *(const float2*)(qb + (size_t)r1 * 768 + kc)
                                    : make_float2(0.f, 0.f);
            qa[ks][half * 2 + 0] = pkbf(u0.x * SC, u0.y * SC);
            qa[ks][half * 2 + 1] = pkbf(u1.x * SC, u1.y * SC);
        }
    }

    auto issue = [&](int kt) {
        int k0 = kt * 64, st = kt & 1;
        {   // K tile: 64 rows x 64B, 256 chunks
            int row = tid >> 2, c = tid & 3;
            cpa16(&KsB[st][row * 80 + c * 16], Kg + (size_t)(k0 + row) * 32 + c * 8);
        }
        {   // V tile: 32 rows x 128B, 256 chunks
            int d = tid >> 3, c = tid & 7;
            cpa16(&VsB[st][d * 144 + c * 16], Vg + (size_t)d * KPAD + k0 + c * 8);
        }
        cpa_commit();
        if (tid < 128) {
            int row = tid, gq = q0 + row;
            unsigned w0 = 0xFFFFFFFFu, w1 = 0xFFFFFFFFu;
            if (gq < Stok) {
                w0 = mb[(size_t)gq * NW + kt * 2];
                w1 = mb[(size_t)gq * NW + kt * 2 + 1];
            }
            Msm[st][row * 2] = w0;
            Msm[st][row * 2 + 1] = w1;
        }
    };

    float m0 = -3.0e38f, m1 = -3.0e38f, l0 = 0.f, l1 = 0.f;
    float o[4][4] = {};

    issue(0);
    for (int kt = 0; kt < KV_TILES; kt++) {
        cpa_wait0();
        __syncthreads();
        if (kt + 1 < KV_TILES) issue(kt + 1);

        int cur = kt & 1;
        const unsigned* Kw = (const unsigned*)KsB[cur];
        const unsigned* Vw = (const unsigned*)VsB[cur];

        // ---- QK^T ----
        float s[8][4];
        #pragma unroll
        for (int n8 = 0; n8 < 8; n8++) {
            s[n8][0] = s[n8][1] = s[n8][2] = s[n8][3] = 0.f;
            #pragma unroll
            for (int ks = 0; ks < 2; ks++) {
                unsigned b0 = Kw[(n8 * 8 + g) * 20 + ks * 8 + t4];
                unsigned b1 = Kw[(n8 * 8 + g) * 20 + ks * 8 + t4 + 4];
                mma_bf16(s[n8], qa[ks], b0, b1);
            }
        }

        // ---- mask ----
        unsigned w00 = Msm[cur][(warp * 16 + g) * 2 + 0];
        unsigned w01 = Msm[cur][(warp * 16 + g) * 2 + 1];
        unsigned w10 = Msm[cur][(warp * 16 + 8 + g) * 2 + 0];
        unsigned w11 = Msm[cur][(warp * 16 + 8 + g) * 2 + 1];
        #pragma unroll
        for (int n8 = 0; n8 < 8; n8++) {
            int sh = (n8 * 8 + 2 * t4) & 31;
            unsigned mr0 = (n8 < 4) ? w00 : w01;
            unsigned mr1 = (n8 < 4) ? w10 : w11;
            if ((mr0 >> sh) & 1u)        s[n8][0] = -1.0e9f;
            if ((mr0 >> (sh + 1)) & 1u)  s[n8][1] = -1.0e9f;
            if ((mr1 >> sh) & 1u)        s[n8][2] = -1.0e9f;
            if ((mr1 >> (sh + 1)) & 1u)  s[n8][3] = -1.0e9f;
        }

        // ---- online softmax ----
        float tm0 = -3.0e38f, tm1 = -3.0e38f;
        #pragma unroll
        for (int n8 = 0; n8 < 8; n8++) {
            tm0 = fmaxf(tm0, fmaxf(s[n8][0], s[n8][1]));
            tm1 = fmaxf(tm1, fmaxf(s[n8][2], s[n8][3]));
        }
        tm0 = fmaxf(tm0, __shfl_xor_sync(0xffffffffu, tm0, 1));
        tm0 = fmaxf(tm0, __shfl_xor_sync(0xffffffffu, tm0, 2));
        tm1 = fmaxf(tm1, __shfl_xor_sync(0xffffffffu, tm1, 1));
        tm1 = fmaxf(tm1, __shfl_xor_sync(0xffffffffu, tm1, 2));
        float mn0 = fmaxf(m0, tm0), mn1 = fmaxf(m1, tm1);
        float a0 = __expf(m0 - mn0), a1 = __expf(m1 - mn1);
        m0 = mn0; m1 = mn1;

        float rs0 = 0.f, rs1 = 0.f;
        #pragma unroll
        for (int n8 = 0; n8 < 8; n8++) {
            s[n8][0] = __expf(s[n8][0] - mn0);
            s[n8][1] = __expf(s[n8][1] - mn0);
            s[n8][2] = __expf(s[n8][2] - mn1);
            s[n8][3] = __expf(s[n8][3] - mn1);
            rs0 += s[n8][0] + s[n8][1];
            rs1 += s[n8][2] + s[n8][3];
        }
        rs0 += __shfl_xor_sync(0xffffffffu, rs0, 1);
        rs0 += __shfl_xor_sync(0xffffffffu, rs0, 2);
        rs1 += __shfl_xor_sync(0xffffffffu, rs1, 1);
        rs1 += __shfl_xor_sync(0xffffffffu, rs1, 2);
        l0 = l0 * a0 + rs0;
        l1 = l1 * a1 + rs1;
        #pragma unroll
        for (int d8 = 0; d8 < 4; d8++) {
            o[d8][0] *= a0; o[d8][1] *= a0; o[d8][2] *= a1; o[d8][3] *= a1;
        }

        // ---- P: C-frags -> bf16 A-frags ----
        unsigned pa[4][4];
        #pragma unroll
        for (int j = 0; j < 4; j++) {
            pa[j][0] = pkbf(s[2*j][0],   s[2*j][1]);
            pa[j][1] = pkbf(s[2*j][2],   s[2*j][3]);
            pa[j][2] = pkbf(s[2*j+1][0], s[2*j+1][1]);
            pa[j][3] = pkbf(s[2*j+1][2], s[2*j+1][3]);
        }

        // ---- PV ----
        #pragma unroll
        for (int d8 = 0; d8 < 4; d8++) {
            #pragma unroll
            for (int j = 0; j < 4; j++) {
                unsigned b0 = Vw[(d8 * 8 + g) * 36 + j * 8 + t4];
                unsigned b1 = Vw[(d8 * 8 + g) * 36 + j * 8 + t4 + 4];
                mma_bf16(o[d8], pa[j], b0, b1);
            }
        }
    }

    // ---- epilogue ----
    float inv0 = 1.0f / l0, inv1 = 1.0f / l1;
    #pragma unroll
    for (int d8 = 0; d8 < 4; d8++) {
        int dc = h * 32 + d8 * 8 + 2 * t4;
        if (r0 < Stok)
            *(float2*)(out + ((size_t)b * Stok + r0) * 256 + dc) =
                make_float2(o[d8][0] * inv0, o[d8][1] * inv0);
        if (r1 < Stok)
            *(float2*)(out + ((size_t)b * Stok + r1) * 256 + dc) =
                make_float2(o[d8][2] * inv1, o[d8][3] * inv1);
    }
}

// ---------------- final: out[b][c][p] = m2[p][c] + op[p][c] + x[b][c][p] ----------------
__global__ void k_final(const float* __restrict__ m2, const float* __restrict__ op,
                        const float* __restrict__ x, float* __restrict__ out)
{
    __shared__ float t[32][33];
    int b = blockIdx.z;
    int p0 = blockIdx.x * 32, c0 = blockIdx.y * 32;
    int tx = threadIdx.x, ty = threadIdx.y;
    t[ty][tx] = m2[((size_t)b * HW + p0 + ty) * Cc + c0 + tx]
              + op[((size_t)b * Stok + p0 + ty) * Cc + c0 + tx];
    __syncthreads();
    size_t oi = ((size_t)b * Cc + c0 + ty) * HW + p0 + tx;
    out[oi] = t[tx][ty] + x[oi];
}

// ---------------- launch ----------------
extern "C" void kernel_launch(void* const* d_in, const int* in_sizes, int n_in,
                              void* d_out, int out_size)
{
    const float* x          = (const float*)d_in[0];
    const float* conv_w     = (const float*)d_in[1];
    const float* conv_b     = (const float*)d_in[2];
    const float* ln_local_w = (const float*)d_in[3];
    const float* ln_local_b = (const float*)d_in[4];
    const float* ln_reg_w   = (const float*)d_in[5];
    const float* ln_reg_b   = (const float*)d_in[6];
    const float* in_proj_w  = (const float*)d_in[7];
    const float* in_proj_b  = (const float*)d_in[8];
    const float* out_proj_w = (const float*)d_in[9];
    const float* out_proj_b = (const float*)d_in[10];
    const float* ln_out_w   = (const float*)d_in[11];
    const float* ln_out_b   = (const float*)d_in[12];
    const float* mlp_w1     = (const float*)d_in[13];
    const float* mlp_b1     = (const float*)d_in[14];
    const float* mlp_w2     = (const float*)d_in[15];
    const float* mlp_b2     = (const float*)d_in[16];
    const void*  attn_mask  = (const void*)d_in[17];
    float* out = (float*)d_out;

    float *xT, *xp, *f, *qkv, *o, *op, *hid, *m1, *m2;
    unsigned* mbp;
    __nv_bfloat16 *Kb, *VbT;
    cudaGetSymbolAddress((void**)&xT,  g_xT);
    cudaGetSymbolAddress((void**)&xp,  g_xp);
    cudaGetSymbolAddress((void**)&f,   g_f);
    cudaGetSymbolAddress((void**)&qkv, g_qkv);
    cudaGetSymbolAddress((void**)&o,   g_o);
    cudaGetSymbolAddress((void**)&op,  g_op);
    cudaGetSymbolAddress((void**)&hid, g_hid);
    cudaGetSymbolAddress((void**)&m1,  g_m1);
    cudaGetSymbolAddress((void**)&m2,  g_m2);
    cudaGetSymbolAddress((void**)&mbp, g_mb);
    cudaGetSymbolAddress((void**)&Kb,  g_Kb);
    cudaGetSymbolAddress((void**)&VbT, g_VbT);

    // mask dtype probe + pack
    k_probe<<<1, 256>>>((const unsigned*)attn_mask);
    k_pack_mask<<<(Stok * NW + 255) / 256, 256>>>(attn_mask, mbp);

    // transpose x -> token-major
    k_transpose_in<<<dim3(HW / 32, Cc / 32, Bz), dim3(32, 32)>>>(x, xT);

    // conv (1x1)
    k_mgemm<0><<<dim3(Cc / 64, (Bz * HW + 127) / 128), 256>>>(xT, conv_w, conv_b, xp,
                                                              Bz * HW, Cc, Cc);

    // feats: LN local + pooled LN
    k_ln<<<Bz * HW / 8, 256>>>(xp, HW, ln_local_w, ln_local_b, f, Stok);
    k_pool_ln<<<dim3(144, Bz), 256>>>(xp, ln_reg_w, ln_reg_b, f, 4, HW, 0);
    k_pool_ln<<<dim3(36,  Bz), 256>>>(xp, ln_reg_w, ln_reg_b, f, 8, HW + 144, 1);

    // qkv = f @ in_proj^T + b
    k_mgemm<0><<<dim3(768 / 64, (Bz * Stok + 127) / 128), 256>>>(f, in_proj_w, in_proj_b, qkv,
                                                                 Bz * Stok, 3 * Cc, Cc);

    // pack K/V per head (bf16, V transposed, zero-padded keys)
    k_pack_qkv<<<dim3(KV_TILES, 8, Bz), 256>>>(qkv, Kb, VbT);

    // attention (bf16 mma, pipelined)
    k_attn<<<dim3((Stok + 127) / 128, 8, Bz), 256>>>(qkv, Kb, VbT, mbp, o);

    // out_proj
    k_mgemm<0><<<dim3(Cc / 64, (Bz * Stok + 127) / 128), 256>>>(o, out_proj_w, out_proj_b, op,
                                                                Bz * Stok, Cc, Cc);

    // ln_out on local tokens
    k_ln<<<Bz * HW / 8, 256>>>(op, Stok, ln_out_w, ln_out_b, hid, HW);

    // mlp
    k_mgemm<1><<<dim3(BOT / 64, (Bz * HW + 127) / 128), 256>>>(hid, mlp_w1, mlp_b1, m1,
                                                               Bz * HW, BOT, Cc);
    k_mgemm<0><<<dim3(Cc / 64,  (Bz * HW + 127) / 128), 256>>>(m1, mlp_w2, mlp_b2, m2,
                                                               Bz * HW, Cc, BOT);

    // residual + transpose back + input residual
    k_final<<<dim3(HW / 32, Cc / 32, Bz), dim3(32, 32)>>>(m2, op, x, out);
}

// round 8
// speedup vs baseline: 7.1105x; 1.1847x over previous
#include <cuda_runtime.h>
#include <cuda_bf16.h>
#include <math.h>

#define Bz   4
#define Cc   256
#define Hh   48
#define Ww   48
#define HW   2304
#define Stok 2484
#define NW   78      // ceil(S/32) mask words per row
#define KPAD 2496    // 39 * 64
#define BOT  64

// ---------------- scratch (device globals; no allocations allowed) ----------------
__device__ float g_xp [(size_t)Bz*HW*Cc];
__device__ float g_f  [(size_t)Bz*Stok*Cc];
__device__ float g_qkv[(size_t)Bz*Stok*Cc*3];
__device__ float g_o  [(size_t)Bz*HW*Cc];      // compact: only local tokens
__device__ float g_op [(size_t)Bz*HW*Cc];      // compact
__device__ float g_hid[(size_t)Bz*HW*Cc];
__device__ float g_m1 [(size_t)Bz*HW*BOT];
__device__ float g_m2 [(size_t)Bz*HW*Cc];
__device__ unsigned g_mb[(size_t)Stok*NW];
__device__ __nv_bfloat16 g_Kb [(size_t)Bz*8*KPAD*32];   // [b][h][key][32]
__device__ __nv_bfloat16 g_VbT[(size_t)Bz*8*32*KPAD];   // [b][h][32][key]
__device__ int g_mdt;                          // mask dtype: 0=u8, 1=i32, 2=f32

// ---------------- small helpers ----------------
__device__ __forceinline__ void cpa16(void* dst, const void* src) {
    unsigned d = (unsigned)__cvta_generic_to_shared(dst);
    asm volatile("cp.async.cg.shared.global [%0], [%1], 16;" :: "r"(d), "l"(src));
}
__device__ __forceinline__ void cpa16z(void* dst, const void* src, int sz) {
    unsigned d = (unsigned)__cvta_generic_to_shared(dst);
    asm volatile("cp.async.cg.shared.global [%0], [%1], 16, %2;" :: "r"(d), "l"(src), "r"(sz));
}
__device__ __forceinline__ void cpa_commit() { asm volatile("cp.async.commit_group;"); }
__device__ __forceinline__ void cpa_wait0()  { asm volatile("cp.async.wait_group 0;"); }
__device__ __forceinline__ void cpa_wait1()  { asm volatile("cp.async.wait_group 1;"); }

__device__ __forceinline__ void mma_tf32(float c[4], const float a[4], float b0, float b1) {
    const unsigned* A = reinterpret_cast<const unsigned*>(a);
    unsigned B0 = __float_as_uint(b0), B1 = __float_as_uint(b1);
    asm volatile(
        "mma.sync.aligned.m16n8k8.row.col.f32.tf32.tf32.f32 "
        "{%0,%1,%2,%3},{%4,%5,%6,%7},{%8,%9},{%0,%1,%2,%3};"
        : "+f"(c[0]), "+f"(c[1]), "+f"(c[2]), "+f"(c[3])
        : "r"(A[0]), "r"(A[1]), "r"(A[2]), "r"(A[3]), "r"(B0), "r"(B1));
}
__device__ __forceinline__ void mma_bf16(float c[4], const unsigned a[4],
                                         unsigned b0, unsigned b1) {
    asm volatile(
        "mma.sync.aligned.m16n8k16.row.col.f32.bf16.bf16.f32 "
        "{%0,%1,%2,%3},{%4,%5,%6,%7},{%8,%9},{%0,%1,%2,%3};"
        : "+f"(c[0]), "+f"(c[1]), "+f"(c[2]), "+f"(c[3])
        : "r"(a[0]), "r"(a[1]), "r"(a[2]), "r"(a[3]), "r"(b0), "r"(b1));
}
__device__ __forceinline__ unsigned pkbf(float lo, float hi) {
    __nv_bfloat162 h = __float22bfloat162_rn(make_float2(lo, hi));
    return *reinterpret_cast<unsigned*>(&h);
}

// ---------------- mask dtype probe ----------------
__global__ void k_probe(const unsigned* __restrict__ m) {
    __shared__ int bad_i32, bad_f32;
    if (threadIdx.x == 0) { bad_i32 = 0; bad_f32 = 0; }
    __syncthreads();
    for (int i = threadIdx.x; i < Stok / 4; i += blockDim.x) {
        unsigned v = m[i];
        if (v != 0u && v != 1u)           bad_i32 = 1;
        if (v != 0u && v != 0x3F800000u)  bad_f32 = 1;
    }
    __syncthreads();
    if (threadIdx.x == 0)
        g_mdt = (!bad_i32) ? 1 : ((!bad_f32) ? 2 : 0);
}

// ---------------- pack mask -> bitmask (bit set = blocked) ----------------
__global__ void k_pack_mask(const void* __restrict__ mv, unsigned* __restrict__ out) {
    int idx = blockIdx.x * blockDim.x + threadIdx.x;
    if (idx >= Stok * NW) return;
    int dt = g_mdt;
    int q = idx / NW, w = idx % NW;
    unsigned bits = 0;
    int c0 = w * 32;
    const unsigned char* mu = (const unsigned char*)mv;
    const int*           mi = (const int*)mv;
    const float*         mf = (const float*)mv;
    #pragma unroll 4
    for (int j = 0; j < 32; j++) {
        int c = c0 + j;
        bool blk;
        if (c >= Stok)      blk = true;
        else if (dt == 1)   blk = mi[(size_t)q * Stok + c] != 0;
        else if (dt == 2)   blk = mf[(size_t)q * Stok + c] != 0.0f;
        else                blk = mu[(size_t)q * Stok + c] != 0;
        if (blk) bits |= 1u << j;
    }
    out[idx] = bits;
}

// ---------------- tf32 mma GEMM, 3-stage cp.async pipeline ----------------
// TRANSA=0: A[M,K] row-major. TRANSA=1: A is x[b][k][p] (conv), tile rows within batch.
__device__ __forceinline__ float gelu_exact(float v) {
    return 0.5f * v * (1.0f + erff(v * 0.70710678118654752f));
}

template<int ACT, int TRANSA>
__global__ void __launch_bounds__(256) k_mgemm(
    const float* __restrict__ A, const float* __restrict__ W,
    const float* __restrict__ bias, float* __restrict__ C,
    int M, int N, int K)
{
    // TRANSA=0: As stage uses [128][20] (2560 floats)
    // TRANSA=1: As stage uses [16][136] (2176 floats) -- k-major
    __shared__ __align__(16) float As[3][2560];
    __shared__ __align__(16) float Bs[3][64 * 20];
    int tid = threadIdx.x;
    int warp = tid >> 5, lane = tid & 31;
    int g = lane >> 2, t4 = lane & 3;
    int m0 = blockIdx.y * 128, n0 = blockIdx.x * 64;
    int bb = 0, p0 = 0;
    if (TRANSA) { bb = m0 / HW; p0 = m0 % HW; }

    auto issue = [&](int k0, int st) {
        if (TRANSA) {
            #pragma unroll
            for (int r = 0; r < 2; r++) {
                int i = tid + r * 256;
                int kk = i >> 5, c = i & 31;
                const float* src = A + ((size_t)bb * Cc + k0 + kk) * HW + p0 + c * 4;
                cpa16(&As[st][kk * 136 + c * 4], src);
            }
        } else {
            #pragma unroll
            for (int i = tid; i < 512; i += 256) {
                int row = i >> 2, c = i & 3;
                int gm = m0 + row;
                int ok = gm < M;
                const float* src = A + (size_t)(ok ? gm : 0) * K + k0 + c * 4;
                cpa16z(&As[st][row * 20 + c * 4], src, ok ? 16 : 0);
            }
        }
        {
            int row = tid >> 2, c = tid & 3;
            cpa16(&Bs[st][row * 20 + c * 4], W + (size_t)(n0 + row) * K + k0 + c * 4);
        }
        cpa_commit();
    };

    float acc[8][4] = {};
    int nk = K >> 4;
    issue(0, 0);
    if (nk > 1) issue(16, 1);

    int st = 0;
    for (int ki = 0; ki < nk; ki++) {
        // Need group ki complete. While a later group exists, wait_group 1
        // suffices (the 1 allowed-pending group is ki+1). On the FINAL
        // iteration no later group exists -> must drain fully (wait_group 0).
        if (ki + 1 < nk) cpa_wait1(); else cpa_wait0();
        __syncthreads();
        if (ki + 2 < nk) {
            int nst = st + 2; if (nst >= 3) nst -= 3;
            issue((ki + 2) << 4, nst);
        }
        const float* as = As[st];
        const float* bs = Bs[st];
        if (++st == 3) st = 0;

        float a[2][4];
        #pragma unroll
        for (int ks = 0; ks < 2; ks++) {
            if (TRANSA) {
                a[ks][0] = as[(ks * 8 + t4) * 136 + warp * 16 + g];
                a[ks][1] = as[(ks * 8 + t4) * 136 + warp * 16 + 8 + g];
                a[ks][2] = as[(ks * 8 + t4 + 4) * 136 + warp * 16 + g];
                a[ks][3] = as[(ks * 8 + t4 + 4) * 136 + warp * 16 + 8 + g];
            } else {
                a[ks][0] = as[(warp * 16 + g) * 20 + ks * 8 + t4];
                a[ks][1] = as[(warp * 16 + 8 + g) * 20 + ks * 8 + t4];
                a[ks][2] = as[(warp * 16 + g) * 20 + ks * 8 + t4 + 4];
                a[ks][3] = as[(warp * 16 + 8 + g) * 20 + ks * 8 + t4 + 4];
            }
        }
        #pragma unroll
        for (int n8 = 0; n8 < 8; n8++) {
            #pragma unroll
            for (int ks = 0; ks < 2; ks++) {
                float b0 = bs[(n8 * 8 + g) * 20 + ks * 8 + t4];
                float b1 = bs[(n8 * 8 + g) * 20 + ks * 8 + t4 + 4];
                mma_tf32(acc[n8], a[ks], b0, b1);
            }
        }
    }

    // epilogue
    int gm0 = m0 + warp * 16 + g;
    int gm1 = gm0 + 8;
    #pragma unroll
    for (int n8 = 0; n8 < 8; n8++) {
        int col = n0 + n8 * 8 + 2 * t4;
        float2 bb2 = *(const float2*)(bias + col);
        float v0 = acc[n8][0] + bb2.x, v1 = acc[n8][1] + bb2.y;
        float v2 = acc[n8][2] + bb2.x, v3 = acc[n8][3] + bb2.y;
        if (ACT == 1) {
            v0 = gelu_exact(v0); v1 = gelu_exact(v1);
            v2 = gelu_exact(v2); v3 = gelu_exact(v3);
        }
        if (gm0 < M) *(float2*)(C + (size_t)gm0 * N + col) = make_float2(v0, v1);
        if (gm1 < M) *(float2*)(C + (size_t)gm1 * N + col) = make_float2(v2, v3);
    }
}

// ---------------- warp-per-row layernorm over C=256 ----------------
__global__ void k_ln(const float* __restrict__ in, int inTok,
                     const float* __restrict__ w, const float* __restrict__ bv,
                     float* __restrict__ out, int outTok)
{
    int row = blockIdx.x * 8 + (threadIdx.x >> 5);
    int lane = threadIdx.x & 31;
    int b = row / HW, p = row % HW;
    const float* src = in + ((size_t)b * inTok + p) * Cc;
    float4 v0 = *(const float4*)(src + lane * 4);
    float4 v1 = *(const float4*)(src + 128 + lane * 4);
    float s = v0.x + v0.y + v0.z + v0.w + v1.x + v1.y + v1.z + v1.w;
    #pragma unroll
    for (int o = 16; o > 0; o >>= 1) s += __shfl_xor_sync(0xffffffffu, s, o);
    float mean = s * (1.0f / 256.0f);
    float d0x = v0.x - mean, d0y = v0.y - mean, d0z = v0.z - mean, d0w = v0.w - mean;
    float d1x = v1.x - mean, d1y = v1.y - mean, d1z = v1.z - mean, d1w = v1.w - mean;
    float s2 = d0x*d0x + d0y*d0y + d0z*d0z + d0w*d0w
             + d1x*d1x + d1y*d1y + d1z*d1z + d1w*d1w;
    #pragma unroll
    for (int o = 16; o > 0; o >>= 1) s2 += __shfl_xor_sync(0xffffffffu, s2, o);
    float rs = rsqrtf(s2 * (1.0f / 256.0f) + 1e-5f);
    float4 w0 = *(const float4*)(w + lane * 4);
    float4 w1 = *(const float4*)(w + 128 + lane * 4);
    float4 b0 = *(const float4*)(bv + lane * 4);
    float4 b1 = *(const float4*)(bv + 128 + lane * 4);
    float* dst = out + ((size_t)b * outTok + p) * Cc;
    *(float4*)(dst + lane * 4) =
        make_float4(d0x*rs*w0.x + b0.x, d0y*rs*w0.y + b0.y, d0z*rs*w0.z + b0.z, d0w*rs*w0.w + b0.w);
    *(float4*)(dst + 128 + lane * 4) =
        make_float4(d1x*rs*w1.x + b1.x, d1y*rs*w1.y + b1.y, d1z*rs*w1.z + b1.z, d1w*rs*w1.w + b1.w);
}

// ---------------- pool (ps x ps mean) + layernorm ----------------
__global__ void k_pool_ln(const float* __restrict__ xp,
                          const float* __restrict__ w, const float* __restrict__ bv,
                          float* __restrict__ f, int ps, int off, int reg)
{
    int b = blockIdx.y;
    int t = blockIdx.x;
    int gw = Ww / ps;
    int bh = t / gw, bw = t % gw;
    int c = threadIdx.x;
    float s = 0.f;
    for (int i = 0; i < ps; i++) {
        int prow = (bh * ps + i) * Ww + bw * ps;
        const float* base = xp + ((size_t)b * HW + prow) * Cc + c;
        for (int j = 0; j < ps; j++) s += base[(size_t)j * Cc];
    }
    float v = s / (float)(ps * ps);
    __shared__ float sb[8];
    float ss = v;
    #pragma unroll
    for (int o = 16; o > 0; o >>= 1) ss += __shfl_xor_sync(0xffffffffu, ss, o);
    if ((c & 31) == 0) sb[c >> 5] = ss;
    __syncthreads();
    float tot = 0.f;
    #pragma unroll
    for (int i = 0; i < 8; i++) tot += sb[i];
    float mean = tot * (1.0f / 256.0f);
    __syncthreads();
    float d = v - mean;
    float s2 = d * d;
    #pragma unroll
    for (int o = 16; o > 0; o >>= 1) s2 += __shfl_xor_sync(0xffffffffu, s2, o);
    if ((c & 31) == 0) sb[c >> 5] = s2;
    __syncthreads();
    float tot2 = 0.f;
    #pragma unroll
    for (int i = 0; i < 8; i++) tot2 += sb[i];
    float rs = rsqrtf(tot2 * (1.0f / 256.0f) + 1e-5f);
    f[((size_t)b * Stok + off + t) * Cc + c] = d * rs * w[reg * Cc + c] + bv[reg * Cc + c];
}

// ---------------- pack K (bf16, padded) and V (bf16, transposed) per head ----------------
__global__ void __launch_bounds__(256) k_pack_qkv(const float* __restrict__ qkv,
                                                  __nv_bfloat16* __restrict__ Kb,
                                                  __nv_bfloat16* __restrict__ VbT)
{
    __shared__ float Vt[64][36];
    int kt = blockIdx.x, h = blockIdx.y, b = blockIdx.z;
    int bh = b * 8 + h;
    int tid = threadIdx.x;
    int key = tid >> 2, dg = tid & 3, d0 = dg * 8;
    int gk = kt * 64 + key;

    float4 kv0, kv1, vv0, vv1;
    if (gk < Stok) {
        const float* base = qkv + ((size_t)b * Stok + gk) * 768 + h * 32;
        kv0 = *(const float4*)(base + 256 + d0);
        kv1 = *(const float4*)(base + 256 + d0 + 4);
        vv0 = *(const float4*)(base + 512 + d0);
        vv1 = *(const float4*)(base + 512 + d0 + 4);
    } else {
        kv0 = make_float4(0.f, 0.f, 0.f, 0.f);
        kv1 = kv0; vv0 = kv0; vv1 = kv0;
    }
    uint4 kp = make_uint4(pkbf(kv0.x, kv0.y), pkbf(kv0.z, kv0.w),
                          pkbf(kv1.x, kv1.y), pkbf(kv1.z, kv1.w));
    *(uint4*)(Kb + ((size_t)bh * KPAD + kt * 64 + key) * 32 + d0) = kp;

    *(float4*)&Vt[key][d0]     = vv0;
    *(float4*)&Vt[key][d0 + 4] = vv1;
    __syncthreads();
    int d = tid >> 3, kq = (tid & 7) * 8;
    uint4 vp = make_uint4(pkbf(Vt[kq + 0][d], Vt[kq + 1][d]),
                          pkbf(Vt[kq + 2][d], Vt[kq + 3][d]),
                          pkbf(Vt[kq + 4][d], Vt[kq + 5][d]),
                          pkbf(Vt[kq + 6][d], Vt[kq + 7][d]));
    *(uint4*)(VbT + ((size_t)bh * 32 + d) * KPAD + kt * 64 + kq) = vp;
}

// ---------------- bf16 mma flash attention, fixed-shift softmax ----------------
#define KV_TILES 39
#define MSHIFT   5.7708f     // 4.0 * log2(e): constant softmax shift (cancels in o/l)

__global__ void __launch_bounds__(256) k_attn(const float* __restrict__ qkv,
                                              const __nv_bfloat16* __restrict__ Kb,
                                              const __nv_bfloat16* __restrict__ VbT,
                                              const unsigned* __restrict__ mb,
                                              float* __restrict__ out)
{
    __shared__ __align__(16) unsigned char KsB[2][64 * 80];
    __shared__ __align__(16) unsigned char VsB[2][32 * 144];
    __shared__ unsigned Msm[2][256];

    int tid  = threadIdx.x;
    int warp = tid >> 5, lane = tid & 31;
    int g = lane >> 2, t4 = lane & 3;
    int q0 = blockIdx.x * 128, h = blockIdx.y, b = blockIdx.z;
    int bh = b * 8 + h;

    const __nv_bfloat16* Kg = Kb  + (size_t)bh * KPAD * 32;
    const __nv_bfloat16* Vg = VbT + (size_t)bh * 32 * KPAD;
    const float* qb = qkv + ((size_t)b * Stok) * 768 + h * 32;

    // scores computed directly in log2 domain: Q pre-scaled by 1/sqrt(32)*log2(e)
    const float SC = 0.17677669529663687f * 1.4426950408889634f;
    int r0 = q0 + warp * 16 + g;   // always < HW (grid covers exactly local tokens)
    int r1 = r0 + 8;

    unsigned qa[2][4];
    #pragma unroll
    for (int ks = 0; ks < 2; ks++) {
        #pragma unroll
        for (int half = 0; half < 2; half++) {
            int kc = ks * 16 + half * 8 + 2 * t4;
            float2 u0 = *(const float2*)(qb + (size_t)r0 * 768 + kc);
            float2 u1 = *(const float2*)(qb + (size_t)r1 * 768 + kc);
            qa[ks][half * 2 + 0] = pkbf(u0.x * SC, u0.y * SC);
            qa[ks][half * 2 + 1] = pkbf(u1.x * SC, u1.y * SC);
        }
    }

    auto issue = [&](int kt) {
        int k0 = kt * 64, st = kt & 1;
        {
            int row = tid >> 2, c = tid & 3;
            cpa16(&KsB[st][row * 80 + c * 16], Kg + (size_t)(k0 + row) * 32 + c * 8);
        }
        {
            int d = tid >> 3, c = tid & 7;
            cpa16(&VsB[st][d * 144 + c * 16], Vg + (size_t)d * KPAD + k0 + c * 8);
        }
        cpa_commit();
        if (tid < 128) {
            int row = tid, gq = q0 + row;
            Msm[st][row * 2]     = mb[(size_t)gq * NW + kt * 2];
            Msm[st][row * 2 + 1] = mb[(size_t)gq * NW + kt * 2 + 1];
        }
    };

    float l0 = 0.f, l1 = 0.f;
    float o[4][4] = {};

    issue(0);
    for (int kt = 0; kt < KV_TILES; kt++) {
        cpa_wait0();
        __syncthreads();
        if (kt + 1 < KV_TILES) issue(kt + 1);

        int cur = kt & 1;
        const unsigned* Kw = (const unsigned*)KsB[cur];
        const unsigned* Vw = (const unsigned*)VsB[cur];

        // ---- QK^T (log2-domain scores) ----
        float s[8][4];
        #pragma unroll
        for (int n8 = 0; n8 < 8; n8++) {
            s[n8][0] = s[n8][1] = s[n8][2] = s[n8][3] = 0.f;
            #pragma unroll
            for (int ks = 0; ks < 2; ks++) {
                unsigned b0 = Kw[(n8 * 8 + g) * 20 + ks * 8 + t4];
                unsigned b1 = Kw[(n8 * 8 + g) * 20 + ks * 8 + t4 + 4];
                mma_bf16(s[n8], qa[ks], b0, b1);
            }
        }

        // ---- mask ----
        unsigned w00 = Msm[cur][(warp * 16 + g) * 2 + 0];
        unsigned w01 = Msm[cur][(warp * 16 + g) * 2 + 1];
        unsigned w10 = Msm[cur][(warp * 16 + 8 + g) * 2 + 0];
        unsigned w11 = Msm[cur][(warp * 16 + 8 + g) * 2 + 1];
        #pragma unroll
        for (int n8 = 0; n8 < 8; n8++) {
            int sh = (n8 * 8 + 2 * t4) & 31;
            unsigned mr0 = (n8 < 4) ? w00 : w01;
            unsigned mr1 = (n8 < 4) ? w10 : w11;
            if ((mr0 >> sh) & 1u)        s[n8][0] = -1.0e9f;
            if ((mr0 >> (sh + 1)) & 1u)  s[n8][1] = -1.0e9f;
            if ((mr1 >> sh) & 1u)        s[n8][2] = -1.0e9f;
            if ((mr1 >> (sh + 1)) & 1u)  s[n8][3] = -1.0e9f;
        }

        // ---- fixed-shift softmax: p = 2^(s - MSHIFT) ----
        #pragma unroll
        for (int n8 = 0; n8 < 8; n8++) {
            s[n8][0] = exp2f(s[n8][0] - MSHIFT);
            s[n8][1] = exp2f(s[n8][1] - MSHIFT);
            s[n8][2] = exp2f(s[n8][2] - MSHIFT);
            s[n8][3] = exp2f(s[n8][3] - MSHIFT);
        }

        // ---- P: C-frags -> bf16 A-frags; l summed from the ROUNDED values
        //      so numerator (PV on bf16 P) and denominator match exactly ----
        unsigned pa[4][4];
        float rs0 = 0.f, rs1 = 0.f;
        #pragma unroll
        for (int j = 0; j < 4; j++) {
            pa[j][0] = pkbf(s[2*j][0],   s[2*j][1]);
            pa[j][1] = pkbf(s[2*j][2],   s[2*j][3]);
            pa[j][2] = pkbf(s[2*j+1][0], s[2*j+1][1]);
            pa[j][3] = pkbf(s[2*j+1][2], s[2*j+1][3]);
            float2 u;
            u = __bfloat1622float2(*(__nv_bfloat162*)&pa[j][0]); rs0 += u.x + u.y;
            u = __bfloat1622float2(*(__nv_bfloat162*)&pa[j][2]); rs0 += u.x + u.y;
            u = __bfloat1622float2(*(__nv_bfloat162*)&pa[j][1]); rs1 += u.x + u.y;
            u = __bfloat1622float2(*(__nv_bfloat162*)&pa[j][3]); rs1 += u.x + u.y;
        }
        l0 += rs0;
        l1 += rs1;

        // ---- PV ----
        #pragma unroll
        for (int d8 = 0; d8 < 4; d8++) {
            #pragma unroll
            for (int j = 0; j < 4; j++) {
                unsigned b0 = Vw[(d8 * 8 + g) * 36 + j * 8 + t4];
                unsigned b1 = Vw[(d8 * 8 + g) * 36 + j * 8 + t4 + 4];
                mma_bf16(o[d8], pa[j], b0, b1);
            }
        }
    }

    // ---- reduce l across quad, epilogue (compact o: [b*HW + r]) ----
    l0 += __shfl_xor_sync(0xffffffffu, l0, 1);
    l0 += __shfl_xor_sync(0xffffffffu, l0, 2);
    l1 += __shfl_xor_sync(0xffffffffu, l1, 1);
    l1 += __shfl_xor_sync(0xffffffffu, l1, 2);
    float inv0 = 1.0f / l0, inv1 = 1.0f / l1;
    #pragma unroll
    for (int d8 = 0; d8 < 4; d8++) {
        int dc = h * 32 + d8 * 8 + 2 * t4;
        *(float2*)(out + ((size_t)b * HW + r0) * 256 + dc) =
            make_float2(o[d8][0] * inv0, o[d8][1] * inv0);
        *(float2*)(out + ((size_t)b * HW + r1) * 256 + dc) =
            make_float2(o[d8][2] * inv1, o[d8][3] * inv1);
    }
}

// ---------------- final: out[b][c][p] = m2[p][c] + op[p][c] + x[b][c][p] ----------------
__global__ void k_final(const float* __restrict__ m2, const float* __restrict__ op,
                        const float* __restrict__ x, float* __restrict__ out)
{
    __shared__ float t[32][33];
    int b = blockIdx.z;
    int p0 = blockIdx.x * 32, c0 = blockIdx.y * 32;
    int tx = threadIdx.x, ty = threadIdx.y;
    t[ty][tx] = m2[((size_t)b * HW + p0 + ty) * Cc + c0 + tx]
              + op[((size_t)b * HW + p0 + ty) * Cc + c0 + tx];
    __syncthreads();
    size_t oi = ((size_t)b * Cc + c0 + ty) * HW + p0 + tx;
    out[oi] = t[tx][ty] + x[oi];
}

// ---------------- launch ----------------
extern "C" void kernel_launch(void* const* d_in, const int* in_sizes, int n_in,
                              void* d_out, int out_size)
{
    const float* x          = (const float*)d_in[0];
    const float* conv_w     = (const float*)d_in[1];
    const float* conv_b     = (const float*)d_in[2];
    const float* ln_local_w = (const float*)d_in[3];
    const float* ln_local_b = (const float*)d_in[4];
    const float* ln_reg_w   = (const float*)d_in[5];
    const float* ln_reg_b   = (const float*)d_in[6];
    const float* in_proj_w  = (const float*)d_in[7];
    const float* in_proj_b  = (const float*)d_in[8];
    const float* out_proj_w = (const float*)d_in[9];
    const float* out_proj_b = (const float*)d_in[10];
    const float* ln_out_w   = (const float*)d_in[11];
    const float* ln_out_b   = (const float*)d_in[12];
    const float* mlp_w1     = (const float*)d_in[13];
    const float* mlp_b1     = (const float*)d_in[14];
    const float* mlp_w2     = (const float*)d_in[15];
    const float* mlp_b2     = (const float*)d_in[16];
    const void*  attn_mask  = (const void*)d_in[17];
    float* out = (float*)d_out;

    float *xp, *f, *qkv, *o, *op, *hid, *m1, *m2;
    unsigned* mbp;
    __nv_bfloat16 *Kb, *VbT;
    cudaGetSymbolAddress((void**)&xp,  g_xp);
    cudaGetSymbolAddress((void**)&f,   g_f);
    cudaGetSymbolAddress((void**)&qkv, g_qkv);
    cudaGetSymbolAddress((void**)&o,   g_o);
    cudaGetSymbolAddress((void**)&op,  g_op);
    cudaGetSymbolAddress((void**)&hid, g_hid);
    cudaGetSymbolAddress((void**)&m1,  g_m1);
    cudaGetSymbolAddress((void**)&m2,  g_m2);
    cudaGetSymbolAddress((void**)&mbp, g_mb);
    cudaGetSymbolAddress((void**)&Kb,  g_Kb);
    cudaGetSymbolAddress((void**)&VbT, g_VbT);

    // mask dtype probe + pack
    k_probe<<<1, 256>>>((const unsigned*)attn_mask);
    k_pack_mask<<<(Stok * NW + 255) / 256, 256>>>(attn_mask, mbp);

    // conv (1x1), reading x[b][c][p] directly (fused transpose)
    k_mgemm<0, 1><<<dim3(Cc / 64, (Bz * HW) / 128), 256>>>(x, conv_w, conv_b, xp,
                                                           Bz * HW, Cc, Cc);

    // feats: LN local + pooled LN
    k_ln<<<Bz * HW / 8, 256>>>(xp, HW, ln_local_w, ln_local_b, f, Stok);
    k_pool_ln<<<dim3(144, Bz), 256>>>(xp, ln_reg_w, ln_reg_b, f, 4, HW, 0);
    k_pool_ln<<<dim3(36,  Bz), 256>>>(xp, ln_reg_w, ln_reg_b, f, 8, HW + 144, 1);

    // qkv = f @ in_proj^T + b
    k_mgemm<0, 0><<<dim3(768 / 64, (Bz * Stok + 127) / 128), 256>>>(f, in_proj_w, in_proj_b,
                                                                    qkv, Bz * Stok, 3 * Cc, Cc);

    // pack K/V per head (bf16, V transposed, zero-padded keys)
    k_pack_qkv<<<dim3(KV_TILES, 8, Bz), 256>>>(qkv, Kb, VbT);

    // attention — only local q tokens (HW = 18 tiles of 128 exactly)
    k_attn<<<dim3(HW / 128, 8, Bz), 256>>>(qkv, Kb, VbT, mbp, o);

    // out_proj on local tokens only (compact)
    k_mgemm<0, 0><<<dim3(Cc / 64, (Bz * HW) / 128), 256>>>(o, out_proj_w, out_proj_b, op,
                                                           Bz * HW, Cc, Cc);

    // ln_out on local tokens
    k_ln<<<Bz * HW / 8, 256>>>(op, HW, ln_out_w, ln_out_b, hid, HW);

    // mlp
    k_mgemm<1, 0><<<dim3(BOT / 64, (Bz * HW) / 128), 256>>>(hid, mlp_w1, mlp_b1, m1,
                                                            Bz * HW, BOT, Cc);
    k_mgemm<0, 0><<<dim3(Cc / 64,  (Bz * HW) / 128), 256>>>(m1, mlp_w2, mlp_b2, m2,
                                                            Bz * HW, Cc, BOT);

    // residual + transpose back + input residual
    k_final<<<dim3(HW / 32, Cc / 32, Bz), dim3(32, 32)>>>(m2, op, x, out);
}

// round 9
// speedup vs baseline: 7.9747x; 1.1215x over previous
#include <cuda_runtime.h>
#include <cuda_bf16.h>
#include <math.h>

#define Bz   4
#define Cc   256
#define Hh   48
#define Ww   48
#define HW   2304
#define Stok 2484
#define NW   78      // ceil(S/32) mask words per row
#define KPAD 2496    // 39 * 64
#define BOT  64

// ---------------- scratch (device globals; no allocations allowed) ----------------
__device__ float g_xp [(size_t)Bz*HW*Cc];
__device__ float g_f  [(size_t)Bz*Stok*Cc];
__device__ float g_q  [(size_t)Bz*HW*Cc];      // Q, local tokens only, f32
__device__ float g_o  [(size_t)Bz*HW*Cc];      // attention out (compact)
__device__ float g_op [(size_t)Bz*HW*Cc];
__device__ float g_hid[(size_t)Bz*HW*Cc];
__device__ float g_m1 [(size_t)Bz*HW*BOT];
__device__ float g_m2 [(size_t)Bz*HW*Cc];      // mlp2 + op (fused)
__device__ unsigned g_mb[(size_t)Stok*NW];
__device__ __nv_bfloat16 g_Kb [(size_t)Bz*8*KPAD*32];   // [b][h][key][32]
__device__ __nv_bfloat16 g_Vb [(size_t)Bz*8*KPAD*32];   // [b][h][key][32] (pre-transpose)
__device__ __nv_bfloat16 g_VbT[(size_t)Bz*8*32*KPAD];   // [b][h][32][key]
__device__ int g_mdt;                          // mask dtype: 0=u8, 1=i32, 2=f32

// ---------------- small helpers ----------------
__device__ __forceinline__ void cpa16(void* dst, const void* src) {
    unsigned d = (unsigned)__cvta_generic_to_shared(dst);
    asm volatile("cp.async.cg.shared.global [%0], [%1], 16;" :: "r"(d), "l"(src));
}
__device__ __forceinline__ void cpa16z(void* dst, const void* src, int sz) {
    unsigned d = (unsigned)__cvta_generic_to_shared(dst);
    asm volatile("cp.async.cg.shared.global [%0], [%1], 16, %2;" :: "r"(d), "l"(src), "r"(sz));
}
__device__ __forceinline__ void cpa_commit() { asm volatile("cp.async.commit_group;"); }
__device__ __forceinline__ void cpa_wait0()  { asm volatile("cp.async.wait_group 0;"); }
__device__ __forceinline__ void cpa_wait1()  { asm volatile("cp.async.wait_group 1;"); }

__device__ __forceinline__ void mma_tf32(float c[4], const float a[4], float b0, float b1) {
    const unsigned* A = reinterpret_cast<const unsigned*>(a);
    unsigned B0 = __float_as_uint(b0), B1 = __float_as_uint(b1);
    asm volatile(
        "mma.sync.aligned.m16n8k8.row.col.f32.tf32.tf32.f32 "
        "{%0,%1,%2,%3},{%4,%5,%6,%7},{%8,%9},{%0,%1,%2,%3};"
        : "+f"(c[0]), "+f"(c[1]), "+f"(c[2]), "+f"(c[3])
        : "r"(A[0]), "r"(A[1]), "r"(A[2]), "r"(A[3]), "r"(B0), "r"(B1));
}
__device__ __forceinline__ void mma_bf16(float c[4], const unsigned a[4],
                                         unsigned b0, unsigned b1) {
    asm volatile(
        "mma.sync.aligned.m16n8k16.row.col.f32.bf16.bf16.f32 "
        "{%0,%1,%2,%3},{%4,%5,%6,%7},{%8,%9},{%0,%1,%2,%3};"
        : "+f"(c[0]), "+f"(c[1]), "+f"(c[2]), "+f"(c[3])
        : "r"(a[0]), "r"(a[1]), "r"(a[2]), "r"(a[3]), "r"(b0), "r"(b1));
}
__device__ __forceinline__ unsigned pkbf(float lo, float hi) {
    __nv_bfloat162 h = __float22bfloat162_rn(make_float2(lo, hi));
    return *reinterpret_cast<unsigned*>(&h);
}

// ---------------- mask dtype probe ----------------
__global__ void k_probe(const unsigned* __restrict__ m) {
    __shared__ int bad_i32, bad_f32;
    if (threadIdx.x == 0) { bad_i32 = 0; bad_f32 = 0; }
    __syncthreads();
    for (int i = threadIdx.x; i < Stok / 4; i += blockDim.x) {
        unsigned v = m[i];
        if (v != 0u && v != 1u)           bad_i32 = 1;
        if (v != 0u && v != 0x3F800000u)  bad_f32 = 1;
    }
    __syncthreads();
    if (threadIdx.x == 0)
        g_mdt = (!bad_i32) ? 1 : ((!bad_f32) ? 2 : 0);
}

// ---------------- pack mask -> bitmask (bit set = blocked) ----------------
__global__ void k_pack_mask(const void* __restrict__ mv, unsigned* __restrict__ out) {
    int idx = blockIdx.x * blockDim.x + threadIdx.x;
    if (idx >= Stok * NW) return;
    int dt = g_mdt;
    int q = idx / NW, w = idx % NW;
    unsigned bits = 0;
    int c0 = w * 32;
    const unsigned char* mu = (const unsigned char*)mv;
    const int*           mi = (const int*)mv;
    const float*         mf = (const float*)mv;
    #pragma unroll 4
    for (int j = 0; j < 32; j++) {
        int c = c0 + j;
        bool blk;
        if (c >= Stok)      blk = true;
        else if (dt == 1)   blk = mi[(size_t)q * Stok + c] != 0;
        else if (dt == 2)   blk = mf[(size_t)q * Stok + c] != 0.0f;
        else                blk = mu[(size_t)q * Stok + c] != 0;
        if (blk) bits |= 1u << j;
    }
    out[idx] = bits;
}

// ---------------- tf32 mma GEMM, 3-stage cp.async pipeline ----------------
// TRANSA=0: A[M,K] row-major. TRANSA=1: A is x[b][k][p] (conv).
// MODE=0: normal store. MODE=1: qkv split (Q->C f32 compact, K/V->g_Kb/g_Vb bf16).
// MODE=2: store C + D (residual add).
__device__ __forceinline__ float gelu_exact(float v) {
    return 0.5f * v * (1.0f + erff(v * 0.70710678118654752f));
}

template<int ACT, int TRANSA, int MODE>
__global__ void __launch_bounds__(256) k_mgemm(
    const float* __restrict__ A, const float* __restrict__ W,
    const float* __restrict__ bias, const float* __restrict__ D,
    float* __restrict__ C, int M, int N, int K)
{
    __shared__ __align__(16) float As[3][2560];
    __shared__ __align__(16) float Bs[3][64 * 20];
    int tid = threadIdx.x;
    int warp = tid >> 5, lane = tid & 31;
    int g = lane >> 2, t4 = lane & 3;
    int m0 = blockIdx.y * 128, n0 = blockIdx.x * 64;
    int bb = 0, p0 = 0;
    if (TRANSA) { bb = m0 / HW; p0 = m0 % HW; }

    auto issue = [&](int k0, int st) {
        if (TRANSA) {
            #pragma unroll
            for (int r = 0; r < 2; r++) {
                int i = tid + r * 256;
                int kk = i >> 5, c = i & 31;
                const float* src = A + ((size_t)bb * Cc + k0 + kk) * HW + p0 + c * 4;
                cpa16(&As[st][kk * 136 + c * 4], src);
            }
        } else {
            #pragma unroll
            for (int i = tid; i < 512; i += 256) {
                int row = i >> 2, c = i & 3;
                int gm = m0 + row;
                int ok = gm < M;
                const float* src = A + (size_t)(ok ? gm : 0) * K + k0 + c * 4;
                cpa16z(&As[st][row * 20 + c * 4], src, ok ? 16 : 0);
            }
        }
        {
            int row = tid >> 2, c = tid & 3;
            cpa16(&Bs[st][row * 20 + c * 4], W + (size_t)(n0 + row) * K + k0 + c * 4);
        }
        cpa_commit();
    };

    float acc[8][4] = {};
    int nk = K >> 4;
    issue(0, 0);
    if (nk > 1) issue(16, 1);

    int st = 0;
    for (int ki = 0; ki < nk; ki++) {
        if (ki + 1 < nk) cpa_wait1(); else cpa_wait0();   // final iter must fully drain
        __syncthreads();
        if (ki + 2 < nk) {
            int nst = st + 2; if (nst >= 3) nst -= 3;
            issue((ki + 2) << 4, nst);
        }
        const float* as = As[st];
        const float* bs = Bs[st];
        if (++st == 3) st = 0;

        float a[2][4];
        #pragma unroll
        for (int ks = 0; ks < 2; ks++) {
            if (TRANSA) {
                a[ks][0] = as[(ks * 8 + t4) * 136 + warp * 16 + g];
                a[ks][1] = as[(ks * 8 + t4) * 136 + warp * 16 + 8 + g];
                a[ks][2] = as[(ks * 8 + t4 + 4) * 136 + warp * 16 + g];
                a[ks][3] = as[(ks * 8 + t4 + 4) * 136 + warp * 16 + 8 + g];
            } else {
                a[ks][0] = as[(warp * 16 + g) * 20 + ks * 8 + t4];
                a[ks][1] = as[(warp * 16 + 8 + g) * 20 + ks * 8 + t4];
                a[ks][2] = as[(warp * 16 + g) * 20 + ks * 8 + t4 + 4];
                a[ks][3] = as[(warp * 16 + 8 + g) * 20 + ks * 8 + t4 + 4];
            }
        }
        #pragma unroll
        for (int n8 = 0; n8 < 8; n8++) {
            #pragma unroll
            for (int ks = 0; ks < 2; ks++) {
                float b0 = bs[(n8 * 8 + g) * 20 + ks * 8 + t4];
                float b1 = bs[(n8 * 8 + g) * 20 + ks * 8 + t4 + 4];
                mma_tf32(acc[n8], a[ks], b0, b1);
            }
        }
    }

    // epilogue
    int gm0 = m0 + warp * 16 + g;
    int gm1 = gm0 + 8;

    if (MODE == 1) {
        int region = n0 >> 8;    // 0=Q, 1=K, 2=V (256-col aligned regions)
        int b0i = gm0 / Stok, s0 = gm0 - b0i * Stok;
        int b1i = gm1 / Stok, s1 = gm1 - b1i * Stok;
        #pragma unroll
        for (int n8 = 0; n8 < 8; n8++) {
            int col = n0 + n8 * 8 + 2 * t4;
            float2 bb2 = *(const float2*)(bias + col);
            float v0 = acc[n8][0] + bb2.x, v1 = acc[n8][1] + bb2.y;
            float v2 = acc[n8][2] + bb2.x, v3 = acc[n8][3] + bb2.y;
            if (region == 0) {
                if (gm0 < M && s0 < HW)
                    *(float2*)(C + ((size_t)b0i * HW + s0) * 256 + col) = make_float2(v0, v1);
                if (gm1 < M && s1 < HW)
                    *(float2*)(C + ((size_t)b1i * HW + s1) * 256 + col) = make_float2(v2, v3);
            } else {
                int dd = col & 31, hh = (col >> 5) & 7;
                __nv_bfloat16* dst = (region == 1) ? g_Kb : g_Vb;
                if (gm0 < M)
                    *(unsigned*)(dst + ((size_t)(b0i * 8 + hh) * KPAD + s0) * 32 + dd) = pkbf(v0, v1);
                if (gm1 < M)
                    *(unsigned*)(dst + ((size_t)(b1i * 8 + hh) * KPAD + s1) * 32 + dd) = pkbf(v2, v3);
            }
        }
        return;
    }

    #pragma unroll
    for (int n8 = 0; n8 < 8; n8++) {
        int col = n0 + n8 * 8 + 2 * t4;
        float2 bb2 = *(const float2*)(bias + col);
        float v0 = acc[n8][0] + bb2.x, v1 = acc[n8][1] + bb2.y;
        float v2 = acc[n8][2] + bb2.x, v3 = acc[n8][3] + bb2.y;
        if (ACT == 1) {
            v0 = gelu_exact(v0); v1 = gelu_exact(v1);
            v2 = gelu_exact(v2); v3 = gelu_exact(v3);
        }
        if (MODE == 2) {
            if (gm0 < M) {
                float2 d0 = *(const float2*)(D + (size_t)gm0 * N + col);
                v0 += d0.x; v1 += d0.y;
            }
            if (gm1 < M) {
                float2 d1 = *(const float2*)(D + (size_t)gm1 * N + col);
                v2 += d1.x; v3 += d1.y;
            }
        }
        if (gm0 < M) *(float2*)(C + (size_t)gm0 * N + col) = make_float2(v0, v1);
        if (gm1 < M) *(float2*)(C + (size_t)gm1 * N + col) = make_float2(v2, v3);
    }
}

// ---------------- warp-per-row layernorm over C=256 ----------------
__global__ void k_ln(const float* __restrict__ in, int inTok,
                     const float* __restrict__ w, const float* __restrict__ bv,
                     float* __restrict__ out, int outTok)
{
    int row = blockIdx.x * 8 + (threadIdx.x >> 5);
    int lane = threadIdx.x & 31;
    int b = row / HW, p = row % HW;
    const float* src = in + ((size_t)b * inTok + p) * Cc;
    float4 v0 = *(const float4*)(src + lane * 4);
    float4 v1 = *(const float4*)(src + 128 + lane * 4);
    float s = v0.x + v0.y + v0.z + v0.w + v1.x + v1.y + v1.z + v1.w;
    #pragma unroll
    for (int o = 16; o > 0; o >>= 1) s += __shfl_xor_sync(0xffffffffu, s, o);
    float mean = s * (1.0f / 256.0f);
    float d0x = v0.x - mean, d0y = v0.y - mean, d0z = v0.z - mean, d0w = v0.w - mean;
    float d1x = v1.x - mean, d1y = v1.y - mean, d1z = v1.z - mean, d1w = v1.w - mean;
    float s2 = d0x*d0x + d0y*d0y + d0z*d0z + d0w*d0w
             + d1x*d1x + d1y*d1y + d1z*d1z + d1w*d1w;
    #pragma unroll
    for (int o = 16; o > 0; o >>= 1) s2 += __shfl_xor_sync(0xffffffffu, s2, o);
    float rs = rsqrtf(s2 * (1.0f / 256.0f) + 1e-5f);
    float4 w0 = *(const float4*)(w + lane * 4);
    float4 w1 = *(const float4*)(w + 128 + lane * 4);
    float4 b0 = *(const float4*)(bv + lane * 4);
    float4 b1 = *(const float4*)(bv + 128 + lane * 4);
    float* dst = out + ((size_t)b * outTok + p) * Cc;
    *(float4*)(dst + lane * 4) =
        make_float4(d0x*rs*w0.x + b0.x, d0y*rs*w0.y + b0.y, d0z*rs*w0.z + b0.z, d0w*rs*w0.w + b0.w);
    *(float4*)(dst + 128 + lane * 4) =
        make_float4(d1x*rs*w1.x + b1.x, d1y*rs*w1.y + b1.y, d1z*rs*w1.z + b1.z, d1w*rs*w1.w + b1.w);
}

// ---------------- pool (ps x ps mean) + layernorm ----------------
__global__ void k_pool_ln(const float* __restrict__ xp,
                          const float* __restrict__ w, const float* __restrict__ bv,
                          float* __restrict__ f, int ps, int off, int reg)
{
    int b = blockIdx.y;
    int t = blockIdx.x;
    int gw = Ww / ps;
    int bh = t / gw, bw = t % gw;
    int c = threadIdx.x;
    float s = 0.f;
    for (int i = 0; i < ps; i++) {
        int prow = (bh * ps + i) * Ww + bw * ps;
        const float* base = xp + ((size_t)b * HW + prow) * Cc + c;
        for (int j = 0; j < ps; j++) s += base[(size_t)j * Cc];
    }
    float v = s / (float)(ps * ps);
    __shared__ float sb[8];
    float ss = v;
    #pragma unroll
    for (int o = 16; o > 0; o >>= 1) ss += __shfl_xor_sync(0xffffffffu, ss, o);
    if ((c & 31) == 0) sb[c >> 5] = ss;
    __syncthreads();
    float tot = 0.f;
    #pragma unroll
    for (int i = 0; i < 8; i++) tot += sb[i];
    float mean = tot * (1.0f / 256.0f);
    __syncthreads();
    float d = v - mean;
    float s2 = d * d;
    #pragma unroll
    for (int o = 16; o > 0; o >>= 1) s2 += __shfl_xor_sync(0xffffffffu, s2, o);
    if ((c & 31) == 0) sb[c >> 5] = s2;
    __syncthreads();
    float tot2 = 0.f;
    #pragma unroll
    for (int i = 0; i < 8; i++) tot2 += sb[i];
    float rs = rsqrtf(tot2 * (1.0f / 256.0f) + 1e-5f);
    f[((size_t)b * Stok + off + t) * Cc + c] = d * rs * w[reg * Cc + c] + bv[reg * Cc + c];
}

// ---------------- transpose V: g_Vb [bh][key][32] -> g_VbT [bh][32][key] ----------------
__global__ void __launch_bounds__(256) k_pack_v(const __nv_bfloat16* __restrict__ Vb,
                                                __nv_bfloat16* __restrict__ VbT)
{
    __shared__ __nv_bfloat16 Vt[64][40];
    int kt = blockIdx.x, h = blockIdx.y, b = blockIdx.z;
    int bh = b * 8 + h;
    int tid = threadIdx.x;
    int key = tid >> 2, d0 = (tid & 3) * 8;
    uint4 v = *(const uint4*)(Vb + ((size_t)bh * KPAD + kt * 64 + key) * 32 + d0);
    *(uint4*)&Vt[key][d0] = v;
    __syncthreads();
    int d = tid >> 3, kq = (tid & 7) * 8;
    __nv_bfloat16 r[8];
    #pragma unroll
    for (int i = 0; i < 8; i++) r[i] = Vt[kq + i][d];
    *(uint4*)(VbT + ((size_t)bh * 32 + d) * KPAD + kt * 64 + kq) = *(uint4*)r;
}

// ---------------- bf16 mma flash attention, fixed-shift softmax ----------------
#define KV_TILES 39

__global__ void __launch_bounds__(256) k_attn(const float* __restrict__ qv,
                                              const __nv_bfloat16* __restrict__ Kb,
                                              const __nv_bfloat16* __restrict__ VbT,
                                              const unsigned* __restrict__ mb,
                                              float* __restrict__ out)
{
    __shared__ __align__(16) unsigned char KsB[2][64 * 80];
    __shared__ __align__(16) unsigned char VsB[2][32 * 144];
    __shared__ unsigned Msm[2][256];

    int tid  = threadIdx.x;
    int warp = tid >> 5, lane = tid & 31;
    int g = lane >> 2, t4 = lane & 3;
    int q0 = blockIdx.x * 128, h = blockIdx.y, b = blockIdx.z;
    int bh = b * 8 + h;

    const __nv_bfloat16* Kg = Kb  + (size_t)bh * KPAD * 32;
    const __nv_bfloat16* Vg = VbT + (size_t)bh * 32 * KPAD;
    const float* qb = qv + ((size_t)b * HW) * 256 + h * 32;

    // Q pre-scaled by 1/sqrt(32)*log2(e); softmax computed as p = 2^s (shift-free,
    // scores are LN-bounded ~O(1); constant shift cancels in o/l anyway)
    const float SC = 0.17677669529663687f * 1.4426950408889634f;
    int r0 = q0 + warp * 16 + g;   // always < HW
    int r1 = r0 + 8;

    unsigned qa[2][4];
    #pragma unroll
    for (int ks = 0; ks < 2; ks++) {
        #pragma unroll
        for (int half = 0; half < 2; half++) {
            int kc = ks * 16 + half * 8 + 2 * t4;
            float2 u0 = *(const float2*)(qb + (size_t)r0 * 256 + kc);
            float2 u1 = *(const float2*)(qb + (size_t)r1 * 256 + kc);
            qa[ks][half * 2 + 0] = pkbf(u0.x * SC, u0.y * SC);
            qa[ks][half * 2 + 1] = pkbf(u1.x * SC, u1.y * SC);
        }
    }

    auto issue = [&](int kt) {
        int k0 = kt * 64, st = kt & 1;
        {
            int row = tid >> 2, c = tid & 3;
            cpa16(&KsB[st][row * 80 + c * 16], Kg + (size_t)(k0 + row) * 32 + c * 8);
        }
        {
            int d = tid >> 3, c = tid & 7;
            cpa16(&VsB[st][d * 144 + c * 16], Vg + (size_t)d * KPAD + k0 + c * 8);
        }
        cpa_commit();
        if (tid < 128) {
            int row = tid, gq = q0 + row;
            Msm[st][row * 2]     = mb[(size_t)gq * NW + kt * 2];
            Msm[st][row * 2 + 1] = mb[(size_t)gq * NW + kt * 2 + 1];
        }
    };

    float l0 = 0.f, l1 = 0.f;
    float o[4][4] = {};

    issue(0);
    for (int kt = 0; kt < KV_TILES; kt++) {
        cpa_wait0();
        __syncthreads();
        if (kt + 1 < KV_TILES) issue(kt + 1);

        int cur = kt & 1;
        const unsigned* Kw = (const unsigned*)KsB[cur];
        const unsigned* Vw = (const unsigned*)VsB[cur];

        // ---- QK^T (log2-domain scores) ----
        float s[8][4];
        #pragma unroll
        for (int n8 = 0; n8 < 8; n8++) {
            s[n8][0] = s[n8][1] = s[n8][2] = s[n8][3] = 0.f;
            #pragma unroll
            for (int ks = 0; ks < 2; ks++) {
                unsigned b0 = Kw[(n8 * 8 + g) * 20 + ks * 8 + t4];
                unsigned b1 = Kw[(n8 * 8 + g) * 20 + ks * 8 + t4 + 4];
                mma_bf16(s[n8], qa[ks], b0, b1);
            }
        }

        // ---- mask ----
        unsigned w00 = Msm[cur][(warp * 16 + g) * 2 + 0];
        unsigned w01 = Msm[cur][(warp * 16 + g) * 2 + 1];
        unsigned w10 = Msm[cur][(warp * 16 + 8 + g) * 2 + 0];
        unsigned w11 = Msm[cur][(warp * 16 + 8 + g) * 2 + 1];
        #pragma unroll
        for (int n8 = 0; n8 < 8; n8++) {
            int sh = (n8 * 8 + 2 * t4) & 31;
            unsigned mr0 = (n8 < 4) ? w00 : w01;
            unsigned mr1 = (n8 < 4) ? w10 : w11;
            if ((mr0 >> sh) & 1u)        s[n8][0] = -1.0e9f;
            if ((mr0 >> (sh + 1)) & 1u)  s[n8][1] = -1.0e9f;
            if ((mr1 >> sh) & 1u)        s[n8][2] = -1.0e9f;
            if ((mr1 >> (sh + 1)) & 1u)  s[n8][3] = -1.0e9f;
        }

        // ---- softmax weights: p = 2^s (masked -> 0) ----
        float rs0 = 0.f, rs1 = 0.f;
        #pragma unroll
        for (int n8 = 0; n8 < 8; n8++) {
            s[n8][0] = exp2f(s[n8][0]);
            s[n8][1] = exp2f(s[n8][1]);
            s[n8][2] = exp2f(s[n8][2]);
            s[n8][3] = exp2f(s[n8][3]);
            rs0 += s[n8][0] + s[n8][1];
            rs1 += s[n8][2] + s[n8][3];
        }
        l0 += rs0;
        l1 += rs1;

        // ---- P: C-frags -> bf16 A-frags ----
        unsigned pa[4][4];
        #pragma unroll
        for (int j = 0; j < 4; j++) {
            pa[j][0] = pkbf(s[2*j][0],   s[2*j][1]);
            pa[j][1] = pkbf(s[2*j][2],   s[2*j][3]);
            pa[j][2] = pkbf(s[2*j+1][0], s[2*j+1][1]);
            pa[j][3] = pkbf(s[2*j+1][2], s[2*j+1][3]);
        }

        // ---- PV ----
        #pragma unroll
        for (int d8 = 0; d8 < 4; d8++) {
            #pragma unroll
            for (int j = 0; j < 4; j++) {
                unsigned b0 = Vw[(d8 * 8 + g) * 36 + j * 8 + t4];
                unsigned b1 = Vw[(d8 * 8 + g) * 36 + j * 8 + t4 + 4];
                mma_bf16(o[d8], pa[j], b0, b1);
            }
        }
    }

    // ---- reduce l across quad, epilogue (compact o: [b*HW + r]) ----
    l0 += __shfl_xor_sync(0xffffffffu, l0, 1);
    l0 += __shfl_xor_sync(0xffffffffu, l0, 2);
    l1 += __shfl_xor_sync(0xffffffffu, l1, 1);
    l1 += __shfl_xor_sync(0xffffffffu, l1, 2);
    float inv0 = 1.0f / l0, inv1 = 1.0f / l1;
    #pragma unroll
    for (int d8 = 0; d8 < 4; d8++) {
        int dc = h * 32 + d8 * 8 + 2 * t4;
        *(float2*)(out + ((size_t)b * HW + r0) * 256 + dc) =
            make_float2(o[d8][0] * inv0, o[d8][1] * inv0);
        *(float2*)(out + ((size_t)b * HW + r1) * 256 + dc) =
            make_float2(o[d8][2] * inv1, o[d8][3] * inv1);
    }
}

// ---------------- final: out[b][c][p] = m2[p][c] + x[b][c][p]  (m2 already includes op) ----------------
__global__ void k_final(const float* __restrict__ m2,
                        const float* __restrict__ x, float* __restrict__ out)
{
    __shared__ float t[32][33];
    int b = blockIdx.z;
    int p0 = blockIdx.x * 32, c0 = blockIdx.y * 32;
    int tx = threadIdx.x, ty = threadIdx.y;
    t[ty][tx] = m2[((size_t)b * HW + p0 + ty) * Cc + c0 + tx];
    __syncthreads();
    size_t oi = ((size_t)b * Cc + c0 + ty) * HW + p0 + tx;
    out[oi] = t[tx][ty] + x[oi];
}

// ---------------- launch ----------------
extern "C" void kernel_launch(void* const* d_in, const int* in_sizes, int n_in,
                              void* d_out, int out_size)
{
    const float* x          = (const float*)d_in[0];
    const float* conv_w     = (const float*)d_in[1];
    const float* conv_b     = (const float*)d_in[2];
    const float* ln_local_w = (const float*)d_in[3];
    const float* ln_local_b = (const float*)d_in[4];
    const float* ln_reg_w   = (const float*)d_in[5];
    const float* ln_reg_b   = (const float*)d_in[6];
    const float* in_proj_w  = (const float*)d_in[7];
    const float* in_proj_b  = (const float*)d_in[8];
    const float* out_proj_w = (const float*)d_in[9];
    const float* out_proj_b = (const float*)d_in[10];
    const float* ln_out_w   = (const float*)d_in[11];
    const float* ln_out_b   = (const float*)d_in[12];
    const float* mlp_w1     = (const float*)d_in[13];
    const float* mlp_b1     = (const float*)d_in[14];
    const float* mlp_w2     = (const float*)d_in[15];
    const float* mlp_b2     = (const float*)d_in[16];
    const void*  attn_mask  = (const void*)d_in[17];
    float* out = (float*)d_out;

    float *xp, *f, *q, *o, *op, *hid, *m1, *m2;
    unsigned* mbp;
    __nv_bfloat16 *Kb, *Vb, *VbT;
    cudaGetSymbolAddress((void**)&xp,  g_xp);
    cudaGetSymbolAddress((void**)&f,   g_f);
    cudaGetSymbolAddress((void**)&q,   g_q);
    cudaGetSymbolAddress((void**)&o,   g_o);
    cudaGetSymbolAddress((void**)&op,  g_op);
    cudaGetSymbolAddress((void**)&hid, g_hid);
    cudaGetSymbolAddress((void**)&m1,  g_m1);
    cudaGetSymbolAddress((void**)&m2,  g_m2);
    cudaGetSymbolAddress((void**)&mbp, g_mb);
    cudaGetSymbolAddress((void**)&Kb,  g_Kb);
    cudaGetSymbolAddress((void**)&Vb,  g_Vb);
    cudaGetSymbolAddress((void**)&VbT, g_VbT);

    // mask dtype probe + pack
    k_probe<<<1, 256>>>((const unsigned*)attn_mask);
    k_pack_mask<<<(Stok * NW + 255) / 256, 256>>>(attn_mask, mbp);

    // conv (1x1), reading x[b][c][p] directly (fused transpose)
    k_mgemm<0, 1, 0><<<dim3(Cc / 64, (Bz * HW) / 128), 256>>>(x, conv_w, conv_b, nullptr, xp,
                                                              Bz * HW, Cc, Cc);

    // feats: LN local + pooled LN
    k_ln<<<Bz * HW / 8, 256>>>(xp, HW, ln_local_w, ln_local_b, f, Stok);
    k_pool_ln<<<dim3(144, Bz), 256>>>(xp, ln_reg_w, ln_reg_b, f, 4, HW, 0);
    k_pool_ln<<<dim3(36,  Bz), 256>>>(xp, ln_reg_w, ln_reg_b, f, 8, HW + 144, 1);

    // qkv GEMM with split epilogue: Q -> g_q f32 (local only), K/V -> g_Kb/g_Vb bf16
    k_mgemm<0, 0, 1><<<dim3(768 / 64, (Bz * Stok + 127) / 128), 256>>>(f, in_proj_w, in_proj_b,
                                                                       nullptr, q,
                                                                       Bz * Stok, 3 * Cc, Cc);

    // transpose V (bf16 -> bf16)
    k_pack_v<<<dim3(KV_TILES, 8, Bz), 256>>>(Vb, VbT);

    // attention — only local q tokens (HW = 18 tiles of 128 exactly)
    k_attn<<<dim3(HW / 128, 8, Bz), 256>>>(q, Kb, VbT, mbp, o);

    // out_proj on local tokens only (compact)
    k_mgemm<0, 0, 0><<<dim3(Cc / 64, (Bz * HW) / 128), 256>>>(o, out_proj_w, out_proj_b,
                                                              nullptr, op, Bz * HW, Cc, Cc);

    // ln_out on local tokens
    k_ln<<<Bz * HW / 8, 256>>>(op, HW, ln_out_w, ln_out_b, hid, HW);

    // mlp (mlp2 fuses +op residual)
    k_mgemm<1, 0, 0><<<dim3(BOT / 64, (Bz * HW) / 128), 256>>>(hid, mlp_w1, mlp_b1, nullptr, m1,
                                                               Bz * HW, BOT, Cc);
    k_mgemm<0, 0, 2><<<dim3(Cc / 64,  (Bz * HW) / 128), 256>>>(m1, mlp_w2, mlp_b2, op, m2,
                                                               Bz * HW, Cc, BOT);

    // transpose back + input residual
    k_final<<<dim3(HW / 32, Cc / 32, Bz), dim3(32, 32)>>>(m2, x, out);
}

// round 10
// speedup vs baseline: 8.6547x; 1.0853x over previous
#include <cuda_runtime.h>
#include <cuda_bf16.h>
#include <math.h>

#define Bz   4
#define Cc   256
#define Hh   48
#define Ww   48
#define HW   2304
#define Stok 2484
#define NW   78      // ceil(S/32) mask words per row
#define KPAD 2496    // 39 * 64
#define BOT  64

typedef __nv_bfloat16 bf16;

// ---------------- scratch (device globals; zero-initialized, no allocs) ----------------
__device__ float g_xp [(size_t)Bz*HW*Cc];
__device__ bf16  g_f  [(size_t)Bz*Stok*Cc];    // LN features (bf16)
__device__ float g_q  [(size_t)Bz*HW*Cc];      // Q, local tokens only, f32
__device__ bf16  g_ob [(size_t)Bz*HW*Cc];      // attention out (bf16)
__device__ float g_op [(size_t)Bz*HW*Cc];
__device__ bf16  g_hid[(size_t)Bz*HW*Cc];      // ln_out (bf16)
__device__ bf16  g_m1 [(size_t)Bz*HW*BOT];     // gelu(mlp1) (bf16)
__device__ float g_m2 [(size_t)Bz*HW*Cc];      // mlp2 + op (fused)
__device__ unsigned g_mb[(size_t)Stok*NW];
__device__ bf16 g_Kb [(size_t)Bz*8*KPAD*32];   // [b][h][key][32]
__device__ bf16 g_Vb [(size_t)Bz*8*KPAD*32];   // [b][h][key][32] (pre-transpose)
__device__ bf16 g_VbT[(size_t)Bz*8*32*KPAD];   // [b][h][32][key]
__device__ bf16 g_wqkv[768*256];               // converted weights
__device__ bf16 g_wout[256*256];
__device__ bf16 g_wm1 [BOT*256];
__device__ bf16 g_wm2 [256*BOT];
__device__ int g_mdt;                          // mask dtype: 0=u8, 1=i32, 2=f32

// ---------------- small helpers ----------------
__device__ __forceinline__ void cpa16(void* dst, const void* src) {
    unsigned d = (unsigned)__cvta_generic_to_shared(dst);
    asm volatile("cp.async.cg.shared.global [%0], [%1], 16;" :: "r"(d), "l"(src));
}
__device__ __forceinline__ void cpa16z(void* dst, const void* src, int sz) {
    unsigned d = (unsigned)__cvta_generic_to_shared(dst);
    asm volatile("cp.async.cg.shared.global [%0], [%1], 16, %2;" :: "r"(d), "l"(src), "r"(sz));
}
__device__ __forceinline__ void cpa_commit() { asm volatile("cp.async.commit_group;"); }
__device__ __forceinline__ void cpa_wait0()  { asm volatile("cp.async.wait_group 0;"); }
__device__ __forceinline__ void cpa_wait1()  { asm volatile("cp.async.wait_group 1;"); }

__device__ __forceinline__ void mma_tf32(float c[4], const float a[4], float b0, float b1) {
    const unsigned* A = reinterpret_cast<const unsigned*>(a);
    unsigned B0 = __float_as_uint(b0), B1 = __float_as_uint(b1);
    asm volatile(
        "mma.sync.aligned.m16n8k8.row.col.f32.tf32.tf32.f32 "
        "{%0,%1,%2,%3},{%4,%5,%6,%7},{%8,%9},{%0,%1,%2,%3};"
        : "+f"(c[0]), "+f"(c[1]), "+f"(c[2]), "+f"(c[3])
        : "r"(A[0]), "r"(A[1]), "r"(A[2]), "r"(A[3]), "r"(B0), "r"(B1));
}
__device__ __forceinline__ void mma_bf16(float c[4], const unsigned a[4],
                                         unsigned b0, unsigned b1) {
    asm volatile(
        "mma.sync.aligned.m16n8k16.row.col.f32.bf16.bf16.f32 "
        "{%0,%1,%2,%3},{%4,%5,%6,%7},{%8,%9},{%0,%1,%2,%3};"
        : "+f"(c[0]), "+f"(c[1]), "+f"(c[2]), "+f"(c[3])
        : "r"(a[0]), "r"(a[1]), "r"(a[2]), "r"(a[3]), "r"(b0), "r"(b1));
}
__device__ __forceinline__ unsigned pkbf(float lo, float hi) {
    __nv_bfloat162 h = __float22bfloat162_rn(make_float2(lo, hi));
    return *reinterpret_cast<unsigned*>(&h);
}

// ---------------- mask dtype probe ----------------
__global__ void k_probe(const unsigned* __restrict__ m) {
    __shared__ int bad_i32, bad_f32;
    if (threadIdx.x == 0) { bad_i32 = 0; bad_f32 = 0; }
    __syncthreads();
    for (int i = threadIdx.x; i < Stok / 4; i += blockDim.x) {
        unsigned v = m[i];
        if (v != 0u && v != 1u)           bad_i32 = 1;
        if (v != 0u && v != 0x3F800000u)  bad_f32 = 1;
    }
    __syncthreads();
    if (threadIdx.x == 0)
        g_mdt = (!bad_i32) ? 1 : ((!bad_f32) ? 2 : 0);
}

// ---------------- pack mask -> bitmask (bit set = blocked) ----------------
__global__ void k_pack_mask(const void* __restrict__ mv, unsigned* __restrict__ out) {
    int idx = blockIdx.x * blockDim.x + threadIdx.x;
    if (idx >= Stok * NW) return;
    int dt = g_mdt;
    int q = idx / NW, w = idx % NW;
    unsigned bits = 0;
    int c0 = w * 32;
    const unsigned char* mu = (const unsigned char*)mv;
    const int*           mi = (const int*)mv;
    const float*         mf = (const float*)mv;
    #pragma unroll 4
    for (int j = 0; j < 32; j++) {
        int c = c0 + j;
        bool blk;
        if (c >= Stok)      blk = true;
        else if (dt == 1)   blk = mi[(size_t)q * Stok + c] != 0;
        else if (dt == 2)   blk = mf[(size_t)q * Stok + c] != 0.0f;
        else                blk = mu[(size_t)q * Stok + c] != 0;
        if (blk) bits |= 1u << j;
    }
    out[idx] = bits;
}

// ---------------- f32 -> bf16 weight conversion ----------------
__global__ void k_cvtw(const float* __restrict__ src, bf16* __restrict__ dst, int n) {
    int i = (blockIdx.x * blockDim.x + threadIdx.x) * 4;
    if (i >= n) return;
    float4 v = *(const float4*)(src + i);
    uint2 p = make_uint2(pkbf(v.x, v.y), pkbf(v.z, v.w));
    *(uint2*)(dst + i) = p;
}

// ---------------- tf32 mma GEMM for conv (fused transpose A) ----------------
__device__ __forceinline__ float gelu_exact(float v) {
    return 0.5f * v * (1.0f + erff(v * 0.70710678118654752f));
}

__global__ void __launch_bounds__(256) k_conv(
    const float* __restrict__ A, const float* __restrict__ W,
    const float* __restrict__ bias, float* __restrict__ C,
    int M, int N, int K)
{
    __shared__ __align__(16) float As[3][16 * 136];
    __shared__ __align__(16) float Bs[3][64 * 20];
    int tid = threadIdx.x;
    int warp = tid >> 5, lane = tid & 31;
    int g = lane >> 2, t4 = lane & 3;
    int m0 = blockIdx.y * 128, n0 = blockIdx.x * 64;
    int bb = m0 / HW, p0 = m0 % HW;

    auto issue = [&](int k0, int st) {
        #pragma unroll
        for (int r = 0; r < 2; r++) {
            int i = tid + r * 256;
            int kk = i >> 5, c = i & 31;
            const float* src = A + ((size_t)bb * Cc + k0 + kk) * HW + p0 + c * 4;
            cpa16(&As[st][kk * 136 + c * 4], src);
        }
        {
            int row = tid >> 2, c = tid & 3;
            cpa16(&Bs[st][row * 20 + c * 4], W + (size_t)(n0 + row) * K + k0 + c * 4);
        }
        cpa_commit();
    };

    float acc[8][4] = {};
    int nk = K >> 4;
    issue(0, 0);
    issue(16, 1);

    int st = 0;
    for (int ki = 0; ki < nk; ki++) {
        if (ki + 1 < nk) cpa_wait1(); else cpa_wait0();
        __syncthreads();
        if (ki + 2 < nk) {
            int nst = st + 2; if (nst >= 3) nst -= 3;
            issue((ki + 2) << 4, nst);
        }
        const float* as = As[st];
        const float* bs = Bs[st];
        if (++st == 3) st = 0;

        float a[2][4];
        #pragma unroll
        for (int ks = 0; ks < 2; ks++) {
            a[ks][0] = as[(ks * 8 + t4) * 136 + warp * 16 + g];
            a[ks][1] = as[(ks * 8 + t4) * 136 + warp * 16 + 8 + g];
            a[ks][2] = as[(ks * 8 + t4 + 4) * 136 + warp * 16 + g];
            a[ks][3] = as[(ks * 8 + t4 + 4) * 136 + warp * 16 + 8 + g];
        }
        #pragma unroll
        for (int n8 = 0; n8 < 8; n8++) {
            #pragma unroll
            for (int ks = 0; ks < 2; ks++) {
                float b0 = bs[(n8 * 8 + g) * 20 + ks * 8 + t4];
                float b1 = bs[(n8 * 8 + g) * 20 + ks * 8 + t4 + 4];
                mma_tf32(acc[n8], a[ks], b0, b1);
            }
        }
    }

    int gm0 = m0 + warp * 16 + g;
    int gm1 = gm0 + 8;
    #pragma unroll
    for (int n8 = 0; n8 < 8; n8++) {
        int col = n0 + n8 * 8 + 2 * t4;
        float2 bb2 = *(const float2*)(bias + col);
        *(float2*)(C + (size_t)gm0 * N + col) = make_float2(acc[n8][0] + bb2.x, acc[n8][1] + bb2.y);
        *(float2*)(C + (size_t)gm1 * N + col) = make_float2(acc[n8][2] + bb2.x, acc[n8][3] + bb2.y);
    }
}

// ---------------- bf16 mma GEMM, 3-stage cp.async pipeline ----------------
// MODE=0: f32 C. MODE=1: qkv split (Q->f32 compact C, K/V->g_Kb/g_Vb bf16).
// MODE=2: f32 C = acc + bias + D. MODE=3: bf16 C.
template<int ACT, int MODE>
__global__ void __launch_bounds__(256) k_bgemm(
    const bf16* __restrict__ A, const bf16* __restrict__ W,
    const float* __restrict__ bias, const float* __restrict__ D,
    void* __restrict__ Cv, int M, int N, int K)
{
    __shared__ __align__(16) unsigned As[3][128 * 20];   // rows of 16 bf16x2 + pad 4
    __shared__ __align__(16) unsigned Bs[3][64 * 20];
    int tid = threadIdx.x;
    int warp = tid >> 5, lane = tid & 31;
    int g = lane >> 2, t4 = lane & 3;
    int m0 = blockIdx.y * 128, n0 = blockIdx.x * 64;

    auto issue = [&](int k0, int st) {
        #pragma unroll
        for (int i = tid; i < 512; i += 256) {
            int row = i >> 2, c = i & 3;
            int gm = m0 + row;
            int ok = gm < M;
            const bf16* src = A + (size_t)(ok ? gm : 0) * K + k0 + c * 8;
            cpa16z(&As[st][row * 20 + c * 4], src, ok ? 16 : 0);
        }
        {
            int row = tid >> 2, c = tid & 3;
            cpa16(&Bs[st][row * 20 + c * 4], W + (size_t)(n0 + row) * K + k0 + c * 8);
        }
        cpa_commit();
    };

    float acc[8][4] = {};
    int nk = K >> 5;                 // k-step 32
    issue(0, 0);
    if (nk > 1) issue(32, 1);

    int st = 0;
    for (int ki = 0; ki < nk; ki++) {
        if (ki + 1 < nk) cpa_wait1(); else cpa_wait0();
        __syncthreads();
        if (ki + 2 < nk) {
            int nst = st + 2; if (nst >= 3) nst -= 3;
            issue((ki + 2) << 5, nst);
        }
        const unsigned* as = As[st];
        const unsigned* bs = Bs[st];
        if (++st == 3) st = 0;

        unsigned a[2][4];
        #pragma unroll
        for (int ks = 0; ks < 2; ks++) {
            a[ks][0] = as[(warp * 16 + g) * 20 + ks * 8 + t4];
            a[ks][1] = as[(warp * 16 + 8 + g) * 20 + ks * 8 + t4];
            a[ks][2] = as[(warp * 16 + g) * 20 + ks * 8 + t4 + 4];
            a[ks][3] = as[(warp * 16 + 8 + g) * 20 + ks * 8 + t4 + 4];
        }
        #pragma unroll
        for (int n8 = 0; n8 < 8; n8++) {
            #pragma unroll
            for (int ks = 0; ks < 2; ks++) {
                unsigned b0 = bs[(n8 * 8 + g) * 20 + ks * 8 + t4];
                unsigned b1 = bs[(n8 * 8 + g) * 20 + ks * 8 + t4 + 4];
                mma_bf16(acc[n8], a[ks], b0, b1);
            }
        }
    }

    // epilogue
    int gm0 = m0 + warp * 16 + g;
    int gm1 = gm0 + 8;

    if (MODE == 1) {
        float* C = (float*)Cv;
        int region = n0 >> 8;    // 0=Q, 1=K, 2=V
        int b0i = gm0 / Stok, s0 = gm0 - b0i * Stok;
        int b1i = gm1 / Stok, s1 = gm1 - b1i * Stok;
        #pragma unroll
        for (int n8 = 0; n8 < 8; n8++) {
            int col = n0 + n8 * 8 + 2 * t4;
            float2 bb2 = *(const float2*)(bias + col);
            float v0 = acc[n8][0] + bb2.x, v1 = acc[n8][1] + bb2.y;
            float v2 = acc[n8][2] + bb2.x, v3 = acc[n8][3] + bb2.y;
            if (region == 0) {
                if (gm0 < M && s0 < HW)
                    *(float2*)(C + ((size_t)b0i * HW + s0) * 256 + col) = make_float2(v0, v1);
                if (gm1 < M && s1 < HW)
                    *(float2*)(C + ((size_t)b1i * HW + s1) * 256 + col) = make_float2(v2, v3);
            } else {
                int dd = col & 31, hh = (col >> 5) & 7;
                bf16* dst = (region == 1) ? g_Kb : g_Vb;
                if (gm0 < M)
                    *(unsigned*)(dst + ((size_t)(b0i * 8 + hh) * KPAD + s0) * 32 + dd) = pkbf(v0, v1);
                if (gm1 < M)
                    *(unsigned*)(dst + ((size_t)(b1i * 8 + hh) * KPAD + s1) * 32 + dd) = pkbf(v2, v3);
            }
        }
        return;
    }

    #pragma unroll
    for (int n8 = 0; n8 < 8; n8++) {
        int col = n0 + n8 * 8 + 2 * t4;
        float2 bb2 = *(const float2*)(bias + col);
        float v0 = acc[n8][0] + bb2.x, v1 = acc[n8][1] + bb2.y;
        float v2 = acc[n8][2] + bb2.x, v3 = acc[n8][3] + bb2.y;
        if (ACT == 1) {
            v0 = gelu_exact(v0); v1 = gelu_exact(v1);
            v2 = gelu_exact(v2); v3 = gelu_exact(v3);
        }
        if (MODE == 2) {
            const float* Df = D;
            if (gm0 < M) {
                float2 d0 = *(const float2*)(Df + (size_t)gm0 * N + col);
                v0 += d0.x; v1 += d0.y;
            }
            if (gm1 < M) {
                float2 d1 = *(const float2*)(Df + (size_t)gm1 * N + col);
                v2 += d1.x; v3 += d1.y;
            }
        }
        if (MODE == 3) {
            bf16* C = (bf16*)Cv;
            if (gm0 < M) *(unsigned*)(C + (size_t)gm0 * N + col) = pkbf(v0, v1);
            if (gm1 < M) *(unsigned*)(C + (size_t)gm1 * N + col) = pkbf(v2, v3);
        } else {
            float* C = (float*)Cv;
            if (gm0 < M) *(float2*)(C + (size_t)gm0 * N + col) = make_float2(v0, v1);
            if (gm1 < M) *(float2*)(C + (size_t)gm1 * N + col) = make_float2(v2, v3);
        }
    }
}

// ---------------- warp-per-row layernorm over C=256 (bf16 output) ----------------
__global__ void k_ln(const float* __restrict__ in, int inTok,
                     const float* __restrict__ w, const float* __restrict__ bv,
                     bf16* __restrict__ out, int outTok)
{
    int row = blockIdx.x * 8 + (threadIdx.x >> 5);
    int lane = threadIdx.x & 31;
    int b = row / HW, p = row % HW;
    const float* src = in + ((size_t)b * inTok + p) * Cc;
    float4 v0 = *(const float4*)(src + lane * 4);
    float4 v1 = *(const float4*)(src + 128 + lane * 4);
    float s = v0.x + v0.y + v0.z + v0.w + v1.x + v1.y + v1.z + v1.w;
    #pragma unroll
    for (int o = 16; o > 0; o >>= 1) s += __shfl_xor_sync(0xffffffffu, s, o);
    float mean = s * (1.0f / 256.0f);
    float d0x = v0.x - mean, d0y = v0.y - mean, d0z = v0.z - mean, d0w = v0.w - mean;
    float d1x = v1.x - mean, d1y = v1.y - mean, d1z = v1.z - mean, d1w = v1.w - mean;
    float s2 = d0x*d0x + d0y*d0y + d0z*d0z + d0w*d0w
             + d1x*d1x + d1y*d1y + d1z*d1z + d1w*d1w;
    #pragma unroll
    for (int o = 16; o > 0; o >>= 1) s2 += __shfl_xor_sync(0xffffffffu, s2, o);
    float rs = rsqrtf(s2 * (1.0f / 256.0f) + 1e-5f);
    float4 w0 = *(const float4*)(w + lane * 4);
    float4 w1 = *(const float4*)(w + 128 + lane * 4);
    float4 b0 = *(const float4*)(bv + lane * 4);
    float4 b1 = *(const float4*)(bv + 128 + lane * 4);
    bf16* dst = out + ((size_t)b * outTok + p) * Cc;
    uint2 r0 = make_uint2(pkbf(d0x*rs*w0.x + b0.x, d0y*rs*w0.y + b0.y),
                          pkbf(d0z*rs*w0.z + b0.z, d0w*rs*w0.w + b0.w));
    uint2 r1 = make_uint2(pkbf(d1x*rs*w1.x + b1.x, d1y*rs*w1.y + b1.y),
                          pkbf(d1z*rs*w1.z + b1.z, d1w*rs*w1.w + b1.w));
    *(uint2*)(dst + lane * 4) = r0;
    *(uint2*)(dst + 128 + lane * 4) = r1;
}

// ---------------- pool (ps x ps mean) + layernorm (bf16 output) ----------------
__global__ void k_pool_ln(const float* __restrict__ xp,
                          const float* __restrict__ w, const float* __restrict__ bv,
                          bf16* __restrict__ f, int ps, int off, int reg)
{
    int b = blockIdx.y;
    int t = blockIdx.x;
    int gw = Ww / ps;
    int bh = t / gw, bw = t % gw;
    int c = threadIdx.x;
    float s = 0.f;
    for (int i = 0; i < ps; i++) {
        int prow = (bh * ps + i) * Ww + bw * ps;
        const float* base = xp + ((size_t)b * HW + prow) * Cc + c;
        for (int j = 0; j < ps; j++) s += base[(size_t)j * Cc];
    }
    float v = s / (float)(ps * ps);
    __shared__ float sb[8];
    float ss = v;
    #pragma unroll
    for (int o = 16; o > 0; o >>= 1) ss += __shfl_xor_sync(0xffffffffu, ss, o);
    if ((c & 31) == 0) sb[c >> 5] = ss;
    __syncthreads();
    float tot = 0.f;
    #pragma unroll
    for (int i = 0; i < 8; i++) tot += sb[i];
    float mean = tot * (1.0f / 256.0f);
    __syncthreads();
    float d = v - mean;
    float s2 = d * d;
    #pragma unroll
    for (int o = 16; o > 0; o >>= 1) s2 += __shfl_xor_sync(0xffffffffu, s2, o);
    if ((c & 31) == 0) sb[c >> 5] = s2;
    __syncthreads();
    float tot2 = 0.f;
    #pragma unroll
    for (int i = 0; i < 8; i++) tot2 += sb[i];
    float rs = rsqrtf(tot2 * (1.0f / 256.0f) + 1e-5f);
    f[((size_t)b * Stok + off + t) * Cc + c] =
        __float2bfloat16_rn(d * rs * w[reg * Cc + c] + bv[reg * Cc + c]);
}

// ---------------- transpose V: g_Vb [bh][key][32] -> g_VbT [bh][32][key] ----------------
__global__ void __launch_bounds__(256) k_pack_v(const bf16* __restrict__ Vb,
                                                bf16* __restrict__ VbT)
{
    __shared__ bf16 Vt[64][40];
    int kt = blockIdx.x, h = blockIdx.y, b = blockIdx.z;
    int bh = b * 8 + h;
    int tid = threadIdx.x;
    int key = tid >> 2, d0 = (tid & 3) * 8;
    uint4 v = *(const uint4*)(Vb + ((size_t)bh * KPAD + kt * 64 + key) * 32 + d0);
    *(uint4*)&Vt[key][d0] = v;
    __syncthreads();
    int d = tid >> 3, kq = (tid & 7) * 8;
    bf16 r[8];
    #pragma unroll
    for (int i = 0; i < 8; i++) r[i] = Vt[kq + i][d];
    *(uint4*)(VbT + ((size_t)bh * 32 + d) * KPAD + kt * 64 + kq) = *(uint4*)r;
}

// ---------------- bf16 mma flash attention, shift-free log2 softmax ----------------
#define KV_TILES 39

__global__ void __launch_bounds__(256) k_attn(const float* __restrict__ qv,
                                              const bf16* __restrict__ Kb,
                                              const bf16* __restrict__ VbT,
                                              const unsigned* __restrict__ mb,
                                              bf16* __restrict__ out)
{
    __shared__ __align__(16) unsigned char KsB[2][64 * 80];
    __shared__ __align__(16) unsigned char VsB[2][32 * 144];
    __shared__ unsigned Msm[2][256];

    int tid  = threadIdx.x;
    int warp = tid >> 5, lane = tid & 31;
    int g = lane >> 2, t4 = lane & 3;
    int q0 = blockIdx.x * 128, h = blockIdx.y, b = blockIdx.z;
    int bh = b * 8 + h;

    const bf16* Kg = Kb  + (size_t)bh * KPAD * 32;
    const bf16* Vg = VbT + (size_t)bh * 32 * KPAD;
    const float* qb = qv + ((size_t)b * HW) * 256 + h * 32;

    const float SC = 0.17677669529663687f * 1.4426950408889634f;  // 1/sqrt(32)*log2e
    int r0 = q0 + warp * 16 + g;
    int r1 = r0 + 8;

    unsigned qa[2][4];
    #pragma unroll
    for (int ks = 0; ks < 2; ks++) {
        #pragma unroll
        for (int half = 0; half < 2; half++) {
            int kc = ks * 16 + half * 8 + 2 * t4;
            float2 u0 = *(const float2*)(qb + (size_t)r0 * 256 + kc);
            float2 u1 = *(const float2*)(qb + (size_t)r1 * 256 + kc);
            qa[ks][half * 2 + 0] = pkbf(u0.x * SC, u0.y * SC);
            qa[ks][half * 2 + 1] = pkbf(u1.x * SC, u1.y * SC);
        }
    }

    auto issue = [&](int kt) {
        int k0 = kt * 64, st = kt & 1;
        {
            int row = tid >> 2, c = tid & 3;
            cpa16(&KsB[st][row * 80 + c * 16], Kg + (size_t)(k0 + row) * 32 + c * 8);
        }
        {
            int d = tid >> 3, c = tid & 7;
            cpa16(&VsB[st][d * 144 + c * 16], Vg + (size_t)d * KPAD + k0 + c * 8);
        }
        cpa_commit();
        if (tid < 128) {
            int row = tid, gq = q0 + row;
            Msm[st][row * 2]     = mb[(size_t)gq * NW + kt * 2];
            Msm[st][row * 2 + 1] = mb[(size_t)gq * NW + kt * 2 + 1];
        }
    };

    float l0 = 0.f, l1 = 0.f;
    float o[4][4] = {};

    issue(0);
    for (int kt = 0; kt < KV_TILES; kt++) {
        cpa_wait0();
        __syncthreads();
        if (kt + 1 < KV_TILES) issue(kt + 1);

        int cur = kt & 1;
        const unsigned* Kw = (const unsigned*)KsB[cur];
        const unsigned* Vw = (const unsigned*)VsB[cur];

        float s[8][4];
        #pragma unroll
        for (int n8 = 0; n8 < 8; n8++) {
            s[n8][0] = s[n8][1] = s[n8][2] = s[n8][3] = 0.f;
            #pragma unroll
            for (int ks = 0; ks < 2; ks++) {
                unsigned b0 = Kw[(n8 * 8 + g) * 20 + ks * 8 + t4];
                unsigned b1 = Kw[(n8 * 8 + g) * 20 + ks * 8 + t4 + 4];
                mma_bf16(s[n8], qa[ks], b0, b1);
            }
        }

        unsigned w00 = Msm[cur][(warp * 16 + g) * 2 + 0];
        unsigned w01 = Msm[cur][(warp * 16 + g) * 2 + 1];
        unsigned w10 = Msm[cur][(warp * 16 + 8 + g) * 2 + 0];
        unsigned w11 = Msm[cur][(warp * 16 + 8 + g) * 2 + 1];
        #pragma unroll
        for (int n8 = 0; n8 < 8; n8++) {
            int sh = (n8 * 8 + 2 * t4) & 31;
            unsigned mr0 = (n8 < 4) ? w00 : w01;
            unsigned mr1 = (n8 < 4) ? w10 : w11;
            if ((mr0 >> sh) & 1u)        s[n8][0] = -1.0e9f;
            if ((mr0 >> (sh + 1)) & 1u)  s[n8][1] = -1.0e9f;
            if ((mr1 >> sh) & 1u)        s[n8][2] = -1.0e9f;
            if ((mr1 >> (sh + 1)) & 1u)  s[n8][3] = -1.0e9f;
        }

        float rs0 = 0.f, rs1 = 0.f;
        #pragma unroll
        for (int n8 = 0; n8 < 8; n8++) {
            s[n8][0] = exp2f(s[n8][0]);
            s[n8][1] = exp2f(s[n8][1]);
            s[n8][2] = exp2f(s[n8][2]);
            s[n8][3] = exp2f(s[n8][3]);
            rs0 += s[n8][0] + s[n8][1];
            rs1 += s[n8][2] + s[n8][3];
        }
        l0 += rs0;
        l1 += rs1;

        unsigned pa[4][4];
        #pragma unroll
        for (int j = 0; j < 4; j++) {
            pa[j][0] = pkbf(s[2*j][0],   s[2*j][1]);
            pa[j][1] = pkbf(s[2*j][2],   s[2*j][3]);
            pa[j][2] = pkbf(s[2*j+1][0], s[2*j+1][1]);
            pa[j][3] = pkbf(s[2*j+1][2], s[2*j+1][3]);
        }

        #pragma unroll
        for (int d8 = 0; d8 < 4; d8++) {
            #pragma unroll
            for (int j = 0; j < 4; j++) {
                unsigned b0 = Vw[(d8 * 8 + g) * 36 + j * 8 + t4];
                unsigned b1 = Vw[(d8 * 8 + g) * 36 + j * 8 + t4 + 4];
                mma_bf16(o[d8], pa[j], b0, b1);
            }
        }
    }

    l0 += __shfl_xor_sync(0xffffffffu, l0, 1);
    l0 += __shfl_xor_sync(0xffffffffu, l0, 2);
    l1 += __shfl_xor_sync(0xffffffffu, l1, 1);
    l1 += __shfl_xor_sync(0xffffffffu, l1, 2);
    float inv0 = 1.0f / l0, inv1 = 1.0f / l1;
    #pragma unroll
    for (int d8 = 0; d8 < 4; d8++) {
        int dc = h * 32 + d8 * 8 + 2 * t4;
        *(unsigned*)(out + ((size_t)b * HW + r0) * 256 + dc) =
            pkbf(o[d8][0] * inv0, o[d8][1] * inv0);
        *(unsigned*)(out + ((size_t)b * HW + r1) * 256 + dc) =
            pkbf(o[d8][2] * inv1, o[d8][3] * inv1);
    }
}

// ---------------- final: out[b][c][p] = m2[p][c] + x[b][c][p]  (m2 includes op) ----------------
__global__ void k_final(const float* __restrict__ m2,
                        const float* __restrict__ x, float* __restrict__ out)
{
    __shared__ float t[32][33];
    int b = blockIdx.z;
    int p0 = blockIdx.x * 32, c0 = blockIdx.y * 32;
    int tx = threadIdx.x, ty = threadIdx.y;
    t[ty][tx] = m2[((size_t)b * HW + p0 + ty) * Cc + c0 + tx];
    __syncthreads();
    size_t oi = ((size_t)b * Cc + c0 + ty) * HW + p0 + tx;
    out[oi] = t[tx][ty] + x[oi];
}

// ---------------- launch ----------------
extern "C" void kernel_launch(void* const* d_in, const int* in_sizes, int n_in,
                              void* d_out, int out_size)
{
    const float* x          = (const float*)d_in[0];
    const float* conv_w     = (const float*)d_in[1];
    const float* conv_b     = (const float*)d_in[2];
    const float* ln_local_w = (const float*)d_in[3];
    const float* ln_local_b = (const float*)d_in[4];
    const float* ln_reg_w   = (const float*)d_in[5];
    const float* ln_reg_b   = (const float*)d_in[6];
    const float* in_proj_w  = (const float*)d_in[7];
    const float* in_proj_b  = (const float*)d_in[8];
    const float* out_proj_w = (const float*)d_in[9];
    const float* out_proj_b = (const float*)d_in[10];
    const float* ln_out_w   = (const float*)d_in[11];
    const float* ln_out_b   = (const float*)d_in[12];
    const float* mlp_w1     = (const float*)d_in[13];
    const float* mlp_b1     = (const float*)d_in[14];
    const float* mlp_w2     = (const float*)d_in[15];
    const float* mlp_b2     = (const float*)d_in[16];
    const void*  attn_mask  = (const void*)d_in[17];
    float* out = (float*)d_out;

    float *xp, *q, *op, *m2;
    bf16 *f, *ob, *hid, *m1, *Kb, *Vb, *VbT, *wqkv, *wout, *wm1, *wm2;
    unsigned* mbp;
    cudaGetSymbolAddress((void**)&xp,  g_xp);
    cudaGetSymbolAddress((void**)&f,   g_f);
    cudaGetSymbolAddress((void**)&q,   g_q);
    cudaGetSymbolAddress((void**)&ob,  g_ob);
    cudaGetSymbolAddress((void**)&op,  g_op);
    cudaGetSymbolAddress((void**)&hid, g_hid);
    cudaGetSymbolAddress((void**)&m1,  g_m1);
    cudaGetSymbolAddress((void**)&m2,  g_m2);
    cudaGetSymbolAddress((void**)&mbp, g_mb);
    cudaGetSymbolAddress((void**)&Kb,  g_Kb);
    cudaGetSymbolAddress((void**)&Vb,  g_Vb);
    cudaGetSymbolAddress((void**)&VbT, g_VbT);
    cudaGetSymbolAddress((void**)&wqkv, g_wqkv);
    cudaGetSymbolAddress((void**)&wout, g_wout);
    cudaGetSymbolAddress((void**)&wm1,  g_wm1);
    cudaGetSymbolAddress((void**)&wm2,  g_wm2);

    // mask dtype probe + pack; weight conversions (independent)
    k_probe<<<1, 256>>>((const unsigned*)attn_mask);
    k_pack_mask<<<(Stok * NW + 255) / 256, 256>>>(attn_mask, mbp);
    k_cvtw<<<(768 * 256 / 4 + 255) / 256, 256>>>(in_proj_w,  wqkv, 768 * 256);
    k_cvtw<<<(256 * 256 / 4 + 255) / 256, 256>>>(out_proj_w, wout, 256 * 256);
    k_cvtw<<<(BOT * 256 / 4 + 255) / 256, 256>>>(mlp_w1,     wm1,  BOT * 256);
    k_cvtw<<<(256 * BOT / 4 + 255) / 256, 256>>>(mlp_w2,     wm2,  256 * BOT);

    // conv (1x1), reading x[b][c][p] directly (fused transpose, tf32)
    k_conv<<<dim3(Cc / 64, (Bz * HW) / 128), 256>>>(x, conv_w, conv_b, xp, Bz * HW, Cc, Cc);

    // feats: LN local + pooled LN (bf16 out)
    k_ln<<<Bz * HW / 8, 256>>>(xp, HW, ln_local_w, ln_local_b, f, Stok);
    k_pool_ln<<<dim3(144, Bz), 256>>>(xp, ln_reg_w, ln_reg_b, f, 4, HW, 0);
    k_pool_ln<<<dim3(36,  Bz), 256>>>(xp, ln_reg_w, ln_reg_b, f, 8, HW + 144, 1);

    // qkv bf16 GEMM, split epilogue: Q -> g_q f32 (local only), K/V -> g_Kb/g_Vb bf16
    k_bgemm<0, 1><<<dim3(768 / 64, (Bz * Stok + 127) / 128), 256>>>(
        f, wqkv, in_proj_b, nullptr, q, Bz * Stok, 3 * Cc, Cc);

    // transpose V (bf16 -> bf16)
    k_pack_v<<<dim3(KV_TILES, 8, Bz), 256>>>(Vb, VbT);

    // attention — only local q tokens; bf16 output
    k_attn<<<dim3(HW / 128, 8, Bz), 256>>>(q, Kb, VbT, mbp, ob);

    // out_proj (bf16 in, f32 out)
    k_bgemm<0, 0><<<dim3(Cc / 64, (Bz * HW) / 128), 256>>>(
        ob, wout, out_proj_b, nullptr, op, Bz * HW, Cc, Cc);

    // ln_out on local tokens (bf16 out)
    k_ln<<<Bz * HW / 8, 256>>>(op, HW, ln_out_w, ln_out_b, hid, HW);

    // mlp: mlp1 bf16->bf16 with GELU; mlp2 bf16 in, f32 out + op residual
    k_bgemm<1, 3><<<dim3(BOT / 64, (Bz * HW) / 128), 256>>>(
        hid, wm1, mlp_b1, nullptr, m1, Bz * HW, BOT, Cc);
    k_bgemm<0, 2><<<dim3(Cc / 64, (Bz * HW) / 128), 256>>>(
        m1, wm2, mlp_b2, op, m2, Bz * HW, Cc, BOT);

    // transpose back + input residual
    k_final<<<dim3(HW / 32, Cc / 32, Bz), dim3(32, 32)>>>(m2, x, out);
}

// round 12
// speedup vs baseline: 8.6757x; 1.0024x over previous
#include <cuda_runtime.h>
#include <cuda_bf16.h>
#include <math.h>

#define Bz   4
#define Cc   256
#define Hh   48
#define Ww   48
#define HW   2304
#define Stok 2484
#define NW   78      // ceil(S/32) mask words per row
#define KPAD 2496    // 39 * 64
#define BOT  64

typedef __nv_bfloat16 bf16;

// ---------------- scratch (device globals; zero-initialized, no allocs) ----------------
__device__ float g_xp [(size_t)Bz*HW*Cc];
__device__ bf16  g_f  [(size_t)Bz*Stok*Cc];    // LN features (bf16)
__device__ float g_q  [(size_t)Bz*HW*Cc];      // Q, local tokens only, f32
__device__ bf16  g_ob [(size_t)Bz*HW*Cc];      // attention out (bf16)
__device__ float g_op [(size_t)Bz*HW*Cc];
__device__ bf16  g_hid[(size_t)Bz*HW*Cc];      // ln_out (bf16)
__device__ bf16  g_m1 [(size_t)Bz*HW*BOT];     // gelu(mlp1) (bf16)
__device__ float g_m2 [(size_t)Bz*HW*Cc];      // mlp2 + op (fused)
__device__ unsigned g_mb[(size_t)Stok*NW];
__device__ bf16 g_Kb [(size_t)Bz*8*KPAD*32];   // [b][h][key][32]
__device__ bf16 g_Vb [(size_t)Bz*8*KPAD*32];   // [b][h][key][32] (pre-transpose)
__device__ bf16 g_VbT[(size_t)Bz*8*32*KPAD];   // [b][h][32][key]
__device__ bf16 g_wqkv[768*256];               // converted weights
__device__ bf16 g_wout[256*256];
__device__ bf16 g_wm1 [BOT*256];
__device__ bf16 g_wm2 [256*BOT];

// ---------------- small helpers ----------------
__device__ __forceinline__ void cpa16(void* dst, const void* src) {
    unsigned d = (unsigned)__cvta_generic_to_shared(dst);
    asm volatile("cp.async.cg.shared.global [%0], [%1], 16;" :: "r"(d), "l"(src));
}
__device__ __forceinline__ void cpa16z(void* dst, const void* src, int sz) {
    unsigned d = (unsigned)__cvta_generic_to_shared(dst);
    asm volatile("cp.async.cg.shared.global [%0], [%1], 16, %2;" :: "r"(d), "l"(src), "r"(sz));
}
__device__ __forceinline__ void cpa_commit() { asm volatile("cp.async.commit_group;"); }
__device__ __forceinline__ void cpa_wait0()  { asm volatile("cp.async.wait_group 0;"); }
__device__ __forceinline__ void cpa_wait1()  { asm volatile("cp.async.wait_group 1;"); }

__device__ __forceinline__ void mma_tf32(float c[4], const float a[4], float b0, float b1) {
    const unsigned* A = reinterpret_cast<const unsigned*>(a);
    unsigned B0 = __float_as_uint(b0), B1 = __float_as_uint(b1);
    asm volatile(
        "mma.sync.aligned.m16n8k8.row.col.f32.tf32.tf32.f32 "
        "{%0,%1,%2,%3},{%4,%5,%6,%7},{%8,%9},{%0,%1,%2,%3};"
        : "+f"(c[0]), "+f"(c[1]), "+f"(c[2]), "+f"(c[3])
        : "r"(A[0]), "r"(A[1]), "r"(A[2]), "r"(A[3]), "r"(B0), "r"(B1));
}
__device__ __forceinline__ void mma_bf16(float c[4], const unsigned a[4],
                                         unsigned b0, unsigned b1) {
    asm volatile(
        "mma.sync.aligned.m16n8k16.row.col.f32.bf16.bf16.f32 "
        "{%0,%1,%2,%3},{%4,%5,%6,%7},{%8,%9},{%0,%1,%2,%3};"
        : "+f"(c[0]), "+f"(c[1]), "+f"(c[2]), "+f"(c[3])
        : "r"(a[0]), "r"(a[1]), "r"(a[2]), "r"(a[3]), "r"(b0), "r"(b1));
}
__device__ __forceinline__ unsigned pkbf(float lo, float hi) {
    __nv_bfloat162 h = __float22bfloat162_rn(make_float2(lo, hi));
    return *reinterpret_cast<unsigned*>(&h);
}

// ---------------- pack mask -> bitmask, with inline dtype probe ----------------
__global__ void k_pack_mask(const void* __restrict__ mv, unsigned* __restrict__ out) {
    __shared__ int bad_i32, bad_f32;
    if (threadIdx.x == 0) { bad_i32 = 0; bad_f32 = 0; }
    __syncthreads();
    {
        const unsigned* m = (const unsigned*)mv;
        for (int i = threadIdx.x; i < Stok / 4; i += blockDim.x) {
            unsigned v = m[i];
            if (v != 0u && v != 1u)           bad_i32 = 1;   // benign race: all write 1
            if (v != 0u && v != 0x3F800000u)  bad_f32 = 1;
        }
    }
    __syncthreads();
    int dt = (!bad_i32) ? 1 : ((!bad_f32) ? 2 : 0);

    int idx = blockIdx.x * blockDim.x + threadIdx.x;
    if (idx >= Stok * NW) return;
    int q = idx / NW, w = idx % NW;
    unsigned bits = 0;
    int c0 = w * 32;
    const unsigned char* mu = (const unsigned char*)mv;
    const int*           mi = (const int*)mv;
    const float*         mf = (const float*)mv;
    #pragma unroll 4
    for (int j = 0; j < 32; j++) {
        int c = c0 + j;
        bool blk;
        if (c >= Stok)      blk = true;
        else if (dt == 1)   blk = mi[(size_t)q * Stok + c] != 0;
        else if (dt == 2)   blk = mf[(size_t)q * Stok + c] != 0.0f;
        else                blk = mu[(size_t)q * Stok + c] != 0;
        if (blk) bits |= 1u << j;
    }
    out[idx] = bits;
}

// ---------------- all weight conversions in ONE launch ----------------
#define WQKV_N (768*256)
#define WOUT_N (256*256)
#define WM1_N  (BOT*256)
#define WM2_N  (256*BOT)
#define WTOT   (WQKV_N + WOUT_N + WM1_N + WM2_N)

__global__ void k_cvtw_all(const float* __restrict__ s0, const float* __restrict__ s1,
                           const float* __restrict__ s2, const float* __restrict__ s3)
{
    int i = (blockIdx.x * blockDim.x + threadIdx.x) * 4;
    const float* src; bf16* dst; int base;
    if (i < WQKV_N)                       { src = s0; dst = g_wqkv; base = 0; }
    else if (i < WQKV_N + WOUT_N)         { src = s1; dst = g_wout; base = WQKV_N; }
    else if (i < WQKV_N + WOUT_N + WM1_N) { src = s2; dst = g_wm1;  base = WQKV_N + WOUT_N; }
    else if (i < WTOT)                    { src = s3; dst = g_wm2;  base = WQKV_N + WOUT_N + WM1_N; }
    else return;
    int k = i - base;
    float4 v = *(const float4*)(src + k);
    *(uint2*)(dst + k) = make_uint2(pkbf(v.x, v.y), pkbf(v.z, v.w));
}

// ---------------- tf32 mma GEMM for conv (fused transpose A) ----------------
__device__ __forceinline__ float gelu_exact(float v) {
    return 0.5f * v * (1.0f + erff(v * 0.70710678118654752f));
}

__global__ void __launch_bounds__(256) k_conv(
    const float* __restrict__ A, const float* __restrict__ W,
    const float* __restrict__ bias, float* __restrict__ C,
    int M, int N, int K)
{
    __shared__ __align__(16) float As[3][16 * 136];
    __shared__ __align__(16) float Bs[3][64 * 20];
    int tid = threadIdx.x;
    int warp = tid >> 5, lane = tid & 31;
    int g = lane >> 2, t4 = lane & 3;
    int m0 = blockIdx.y * 128, n0 = blockIdx.x * 64;
    int bb = m0 / HW, p0 = m0 % HW;

    auto issue = [&](int k0, int st) {
        #pragma unroll
        for (int r = 0; r < 2; r++) {
            int i = tid + r * 256;
            int kk = i >> 5, c = i & 31;
            const float* src = A + ((size_t)bb * Cc + k0 + kk) * HW + p0 + c * 4;
            cpa16(&As[st][kk * 136 + c * 4], src);
        }
        {
            int row = tid >> 2, c = tid & 3;
            cpa16(&Bs[st][row * 20 + c * 4], W + (size_t)(n0 + row) * K + k0 + c * 4);
        }
        cpa_commit();
    };

    float acc[8][4] = {};
    int nk = K >> 4;
    issue(0, 0);
    issue(16, 1);

    int st = 0;
    for (int ki = 0; ki < nk; ki++) {
        if (ki + 1 < nk) cpa_wait1(); else cpa_wait0();
        __syncthreads();
        if (ki + 2 < nk) {
            int nst = st + 2; if (nst >= 3) nst -= 3;
            issue((ki + 2) << 4, nst);
        }
        const float* as = As[st];
        const float* bs = Bs[st];
        if (++st == 3) st = 0;

        float a[2][4];
        #pragma unroll
        for (int ks = 0; ks < 2; ks++) {
            a[ks][0] = as[(ks * 8 + t4) * 136 + warp * 16 + g];
            a[ks][1] = as[(ks * 8 + t4) * 136 + warp * 16 + 8 + g];
            a[ks][2] = as[(ks * 8 + t4 + 4) * 136 + warp * 16 + g];
            a[ks][3] = as[(ks * 8 + t4 + 4) * 136 + warp * 16 + 8 + g];
        }
        #pragma unroll
        for (int n8 = 0; n8 < 8; n8++) {
            #pragma unroll
            for (int ks = 0; ks < 2; ks++) {
                float b0 = bs[(n8 * 8 + g) * 20 + ks * 8 + t4];
                float b1 = bs[(n8 * 8 + g) * 20 + ks * 8 + t4 + 4];
                mma_tf32(acc[n8], a[ks], b0, b1);
            }
        }
    }

    int gm0 = m0 + warp * 16 + g;
    int gm1 = gm0 + 8;
    #pragma unroll
    for (int n8 = 0; n8 < 8; n8++) {
        int col = n0 + n8 * 8 + 2 * t4;
        float2 bb2 = *(const float2*)(bias + col);
        *(float2*)(C + (size_t)gm0 * N + col) = make_float2(acc[n8][0] + bb2.x, acc[n8][1] + bb2.y);
        *(float2*)(C + (size_t)gm1 * N + col) = make_float2(acc[n8][2] + bb2.x, acc[n8][3] + bb2.y);
    }
}

// ---------------- bf16 mma GEMM, 3-stage cp.async pipeline ----------------
// MODE=0: f32 C. MODE=1: qkv split (Q->f32 compact C, K/V->g_Kb/g_Vb bf16).
// MODE=2: f32 C = acc + bias + D. MODE=3: bf16 C.
template<int ACT, int MODE>
__global__ void __launch_bounds__(256) k_bgemm(
    const bf16* __restrict__ A, const bf16* __restrict__ W,
    const float* __restrict__ bias, const float* __restrict__ D,
    void* __restrict__ Cv, int M, int N, int K)
{
    __shared__ __align__(16) unsigned As[3][128 * 20];
    __shared__ __align__(16) unsigned Bs[3][64 * 20];
    int tid = threadIdx.x;
    int warp = tid >> 5, lane = tid & 31;
    int g = lane >> 2, t4 = lane & 3;
    int m0 = blockIdx.y * 128, n0 = blockIdx.x * 64;

    auto issue = [&](int k0, int st) {
        #pragma unroll
        for (int i = tid; i < 512; i += 256) {
            int row = i >> 2, c = i & 3;
            int gm = m0 + row;
            int ok = gm < M;
            const bf16* src = A + (size_t)(ok ? gm : 0) * K + k0 + c * 8;
            cpa16z(&As[st][row * 20 + c * 4], src, ok ? 16 : 0);
        }
        {
            int row = tid >> 2, c = tid & 3;
            cpa16(&Bs[st][row * 20 + c * 4], W + (size_t)(n0 + row) * K + k0 + c * 8);
        }
        cpa_commit();
    };

    float acc[8][4] = {};
    int nk = K >> 5;
    issue(0, 0);
    if (nk > 1) issue(32, 1);

    int st = 0;
    for (int ki = 0; ki < nk; ki++) {
        if (ki + 1 < nk) cpa_wait1(); else cpa_wait0();
        __syncthreads();
        if (ki + 2 < nk) {
            int nst = st + 2; if (nst >= 3) nst -= 3;
            issue((ki + 2) << 5, nst);
        }
        const unsigned* as = As[st];
        const unsigned* bs = Bs[st];
        if (++st == 3) st = 0;

        unsigned a[2][4];
        #pragma unroll
        for (int ks = 0; ks < 2; ks++) {
            a[ks][0] = as[(warp * 16 + g) * 20 + ks * 8 + t4];
            a[ks][1] = as[(warp * 16 + 8 + g) * 20 + ks * 8 + t4];
            a[ks][2] = as[(warp * 16 + g) * 20 + ks * 8 + t4 + 4];
            a[ks][3] = as[(warp * 16 + 8 + g) * 20 + ks * 8 + t4 + 4];
        }
        #pragma unroll
        for (int n8 = 0; n8 < 8; n8++) {
            #pragma unroll
            for (int ks = 0; ks < 2; ks++) {
                unsigned b0 = bs[(n8 * 8 + g) * 20 + ks * 8 + t4];
                unsigned b1 = bs[(n8 * 8 + g) * 20 + ks * 8 + t4 + 4];
                mma_bf16(acc[n8], a[ks], b0, b1);
            }
        }
    }

    int gm0 = m0 + warp * 16 + g;
    int gm1 = gm0 + 8;

    if (MODE == 1) {
        float* C = (float*)Cv;
        int region = n0 >> 8;    // 0=Q, 1=K, 2=V
        int b0i = gm0 / Stok, s0 = gm0 - b0i * Stok;
        int b1i = gm1 / Stok, s1 = gm1 - b1i * Stok;
        #pragma unroll
        for (int n8 = 0; n8 < 8; n8++) {
            int col = n0 + n8 * 8 + 2 * t4;
            float2 bb2 = *(const float2*)(bias + col);
            float v0 = acc[n8][0] + bb2.x, v1 = acc[n8][1] + bb2.y;
            float v2 = acc[n8][2] + bb2.x, v3 = acc[n8][3] + bb2.y;
            if (region == 0) {
                if (gm0 < M && s0 < HW)
                    *(float2*)(C + ((size_t)b0i * HW + s0) * 256 + col) = make_float2(v0, v1);
                if (gm1 < M && s1 < HW)
                    *(float2*)(C + ((size_t)b1i * HW + s1) * 256 + col) = make_float2(v2, v3);
            } else {
                int dd = col & 31, hh = (col >> 5) & 7;
                bf16* dst = (region == 1) ? g_Kb : g_Vb;
                if (gm0 < M)
                    *(unsigned*)(dst + ((size_t)(b0i * 8 + hh) * KPAD + s0) * 32 + dd) = pkbf(v0, v1);
                if (gm1 < M)
                    *(unsigned*)(dst + ((size_t)(b1i * 8 + hh) * KPAD + s1) * 32 + dd) = pkbf(v2, v3);
            }
        }
        return;
    }

    #pragma unroll
    for (int n8 = 0; n8 < 8; n8++) {
        int col = n0 + n8 * 8 + 2 * t4;
        float2 bb2 = *(const float2*)(bias + col);
        float v0 = acc[n8][0] + bb2.x, v1 = acc[n8][1] + bb2.y;
        float v2 = acc[n8][2] + bb2.x, v3 = acc[n8][3] + bb2.y;
        if (ACT == 1) {
            v0 = gelu_exact(v0); v1 = gelu_exact(v1);
            v2 = gelu_exact(v2); v3 = gelu_exact(v3);
        }
        if (MODE == 2) {
            const float* Df = D;
            if (gm0 < M) {
                float2 d0 = *(const float2*)(Df + (size_t)gm0 * N + col);
                v0 += d0.x; v1 += d0.y;
            }
            if (gm1 < M) {
                float2 d1 = *(const float2*)(Df + (size_t)gm1 * N + col);
                v2 += d1.x; v3 += d1.y;
            }
        }
        if (MODE == 3) {
            bf16* C = (bf16*)Cv;
            if (gm0 < M) *(unsigned*)(C + (size_t)gm0 * N + col) = pkbf(v0, v1);
            if (gm1 < M) *(unsigned*)(C + (size_t)gm1 * N + col) = pkbf(v2, v3);
        } else {
            float* C = (float*)Cv;
            if (gm0 < M) *(float2*)(C + (size_t)gm0 * N + col) = make_float2(v0, v1);
            if (gm1 < M) *(float2*)(C + (size_t)gm1 * N + col) = make_float2(v2, v3);
        }
    }
}

// ---------------- warp-per-row layernorm over C=256 (bf16 output) ----------------
__global__ void k_ln(const float* __restrict__ in, int inTok,
                     const float* __restrict__ w, const float* __restrict__ bv,
                     bf16* __restrict__ out, int outTok)
{
    int row = blockIdx.x * 8 + (threadIdx.x >> 5);
    int lane = threadIdx.x & 31;
    int b = row / HW, p = row % HW;
    const float* src = in + ((size_t)b * inTok + p) * Cc;
    float4 v0 = *(const float4*)(src + lane * 4);
    float4 v1 = *(const float4*)(src + 128 + lane * 4);
    float s = v0.x + v0.y + v0.z + v0.w + v1.x + v1.y + v1.z + v1.w;
    #pragma unroll
    for (int o = 16; o > 0; o >>= 1) s += __shfl_xor_sync(0xffffffffu, s, o);
    float mean = s * (1.0f / 256.0f);
    float d0x = v0.x - mean, d0y = v0.y - mean, d0z = v0.z - mean, d0w = v0.w - mean;
    float d1x = v1.x - mean, d1y = v1.y - mean, d1z = v1.z - mean, d1w = v1.w - mean;
    float s2 = d0x*d0x + d0y*d0y + d0z*d0z + d0w*d0w
             + d1x*d1x + d1y*d1y + d1z*d1z + d1w*d1w;
    #pragma unroll
    for (int o = 16; o > 0; o >>= 1) s2 += __shfl_xor_sync(0xffffffffu, s2, o);
    float rs = rsqrtf(s2 * (1.0f / 256.0f) + 1e-5f);
    float4 w0 = *(const float4*)(w + lane * 4);
    float4 w1 = *(const float4*)(w + 128 + lane * 4);
    float4 b0 = *(const float4*)(bv + lane * 4);
    float4 b1 = *(const float4*)(bv + 128 + lane * 4);
    bf16* dst = out + ((size_t)b * outTok + p) * Cc;
    uint2 r0 = make_uint2(pkbf(d0x*rs*w0.x + b0.x, d0y*rs*w0.y + b0.y),
                          pkbf(d0z*rs*w0.z + b0.z, d0w*rs*w0.w + b0.w));
    uint2 r1 = make_uint2(pkbf(d1x*rs*w1.x + b1.x, d1y*rs*w1.y + b1.y),
                          pkbf(d1z*rs*w1.z + b1.z, d1w*rs*w1.w + b1.w));
    *(uint2*)(dst + lane * 4) = r0;
    *(uint2*)(dst + 128 + lane * 4) = r1;
}

// ---------------- pool (ps x ps mean) + layernorm (bf16 output) ----------------
__global__ void k_pool_ln(const float* __restrict__ xp,
                          const float* __restrict__ w, const float* __restrict__ bv,
                          bf16* __restrict__ f, int ps, int off, int reg)
{
    int b = blockIdx.y;
    int t = blockIdx.x;
    int gw = Ww / ps;
    int bh = t / gw, bw = t % gw;
    int c = threadIdx.x;
    float s = 0.f;
    for (int i = 0; i < ps; i++) {
        int prow = (bh * ps + i) * Ww + bw * ps;
        const float* base = xp + ((size_t)b * HW + prow) * Cc + c;
        for (int j = 0; j < ps; j++) s += base[(size_t)j * Cc];
    }
    float v = s / (float)(ps * ps);
    __shared__ float sb[8];
    float ss = v;
    #pragma unroll
    for (int o = 16; o > 0; o >>= 1) ss += __shfl_xor_sync(0xffffffffu, ss, o);
    if ((c & 31) == 0) sb[c >> 5] = ss;
    __syncthreads();
    float tot = 0.f;
    #pragma unroll
    for (int i = 0; i < 8; i++) tot += sb[i];
    float mean = tot * (1.0f / 256.0f);
    __syncthreads();
    float d = v - mean;
    float s2 = d * d;
    #pragma unroll
    for (int o = 16; o > 0; o >>= 1) s2 += __shfl_xor_sync(0xffffffffu, s2, o);
    if ((c & 31) == 0) sb[c >> 5] = s2;
    __syncthreads();
    float tot2 = 0.f;
    #pragma unroll
    for (int i = 0; i < 8; i++) tot2 += sb[i];
    float rs = rsqrtf(tot2 * (1.0f / 256.0f) + 1e-5f);
    f[((size_t)b * Stok + off + t) * Cc + c] =
        __float2bfloat16_rn(d * rs * w[reg * Cc + c] + bv[reg * Cc + c]);
}

// ---------------- transpose V: g_Vb [bh][key][32] -> g_VbT [bh][32][key] ----------------
__global__ void __launch_bounds__(256) k_pack_v(const bf16* __restrict__ Vb,
                                                bf16* __restrict__ VbT)
{
    __shared__ bf16 Vt[64][40];
    int kt = blockIdx.x, h = blockIdx.y, b = blockIdx.z;
    int bh = b * 8 + h;
    int tid = threadIdx.x;
    int key = tid >> 2, d0 = (tid & 3) * 8;
    uint4 v = *(const uint4*)(Vb + ((size_t)bh * KPAD + kt * 64 + key) * 32 + d0);
    *(uint4*)&Vt[key][d0] = v;
    __syncthreads();
    int d = tid >> 3, kq = (tid & 7) * 8;
    bf16 r[8];
    #pragma unroll
    for (int i = 0; i < 8; i++) r[i] = Vt[kq + i][d];
    *(uint4*)(VbT + ((size_t)bh * 32 + d) * KPAD + kt * 64 + kq) = *(uint4*)r;
}

// ---------------- bf16 mma flash attention, interleaved exp/mma pipeline ----------------
#define KV_TILES 39

__global__ void __launch_bounds__(256) k_attn(const float* __restrict__ qv,
                                              const bf16* __restrict__ Kb,
                                              const bf16* __restrict__ VbT,
                                              const unsigned* __restrict__ mb,
                                              bf16* __restrict__ out)
{
    __shared__ __align__(16) unsigned char KsB[2][64 * 80];
    __shared__ __align__(16) unsigned char VsB[2][32 * 144];
    __shared__ unsigned Msm[2][256];

    int tid  = threadIdx.x;
    int warp = tid >> 5, lane = tid & 31;
    int g = lane >> 2, t4 = lane & 3;
    int q0 = blockIdx.x * 128, h = blockIdx.y, b = blockIdx.z;
    int bh = b * 8 + h;

    const bf16* Kg = Kb  + (size_t)bh * KPAD * 32;
    const bf16* Vg = VbT + (size_t)bh * 32 * KPAD;
    const float* qb = qv + ((size_t)b * HW) * 256 + h * 32;

    const float SC = 0.17677669529663687f * 1.4426950408889634f;  // 1/sqrt(32)*log2e
    int r0 = q0 + warp * 16 + g;
    int r1 = r0 + 8;

    unsigned qa[2][4];
    #pragma unroll
    for (int ks = 0; ks < 2; ks++) {
        #pragma unroll
        for (int half = 0; half < 2; half++) {
            int kc = ks * 16 + half * 8 + 2 * t4;
            float2 u0 = *(const float2*)(qb + (size_t)r0 * 256 + kc);
            float2 u1 = *(const float2*)(qb + (size_t)r1 * 256 + kc);
            qa[ks][half * 2 + 0] = pkbf(u0.x * SC, u0.y * SC);
            qa[ks][half * 2 + 1] = pkbf(u1.x * SC, u1.y * SC);
        }
    }

    auto issue = [&](int kt) {
        int k0 = kt * 64, st = kt & 1;
        {
            int row = tid >> 2, c = tid & 3;
            cpa16(&KsB[st][row * 80 + c * 16], Kg + (size_t)(k0 + row) * 32 + c * 8);
        }
        {
            int d = tid >> 3, c = tid & 7;
            cpa16(&VsB[st][d * 144 + c * 16], Vg + (size_t)d * KPAD + k0 + c * 8);
        }
        cpa_commit();
        if (tid < 128) {
            int row = tid, gq = q0 + row;
            Msm[st][row * 2]     = mb[(size_t)gq * NW + kt * 2];
            Msm[st][row * 2 + 1] = mb[(size_t)gq * NW + kt * 2 + 1];
        }
    };

    float l0 = 0.f, l1 = 0.f;
    float o[4][4] = {};

    issue(0);
    for (int kt = 0; kt < KV_TILES; kt++) {
        cpa_wait0();
        __syncthreads();
        if (kt + 1 < KV_TILES) issue(kt + 1);

        int cur = kt & 1;
        const unsigned* Kw = (const unsigned*)KsB[cur];
        const unsigned* Vw = (const unsigned*)VsB[cur];

        unsigned w00 = Msm[cur][(warp * 16 + g) * 2 + 0];
        unsigned w01 = Msm[cur][(warp * 16 + g) * 2 + 1];
        unsigned w10 = Msm[cur][(warp * 16 + 8 + g) * 2 + 0];
        unsigned w11 = Msm[cur][(warp * 16 + 8 + g) * 2 + 1];

        float rs0 = 0.f, rs1 = 0.f;

        // interleaved j-slices: QK(2 n8) -> mask -> exp -> pack -> PV(4 d8)
        #pragma unroll
        for (int j = 0; j < 4; j++) {
            int n8a = 2 * j, n8b = 2 * j + 1;
            float s0[4] = {0.f, 0.f, 0.f, 0.f};
            float s1[4] = {0.f, 0.f, 0.f, 0.f};
            #pragma unroll
            for (int ks = 0; ks < 2; ks++) {
                mma_bf16(s0, qa[ks], Kw[(n8a * 8 + g) * 20 + ks * 8 + t4],
                                     Kw[(n8a * 8 + g) * 20 + ks * 8 + t4 + 4]);
                mma_bf16(s1, qa[ks], Kw[(n8b * 8 + g) * 20 + ks * 8 + t4],
                                     Kw[(n8b * 8 + g) * 20 + ks * 8 + t4 + 4]);
            }
            unsigned mr0 = (j < 2) ? w00 : w01;
            unsigned mr1 = (j < 2) ? w10 : w11;
            int sha = (n8a * 8 + 2 * t4) & 31;
            int shb = (n8b * 8 + 2 * t4) & 31;
            if ((mr0 >> sha) & 1u)        s0[0] = -1.0e9f;
            if ((mr0 >> (sha + 1)) & 1u)  s0[1] = -1.0e9f;
            if ((mr1 >> sha) & 1u)        s0[2] = -1.0e9f;
            if ((mr1 >> (sha + 1)) & 1u)  s0[3] = -1.0e9f;
            if ((mr0 >> shb) & 1u)        s1[0] = -1.0e9f;
            if ((mr0 >> (shb + 1)) & 1u)  s1[1] = -1.0e9f;
            if ((mr1 >> shb) & 1u)        s1[2] = -1.0e9f;
            if ((mr1 >> (shb + 1)) & 1u)  s1[3] = -1.0e9f;
            s0[0] = exp2f(s0[0]); s0[1] = exp2f(s0[1]);
            s0[2] = exp2f(s0[2]); s0[3] = exp2f(s0[3]);
            s1[0] = exp2f(s1[0]); s1[1] = exp2f(s1[1]);
            s1[2] = exp2f(s1[2]); s1[3] = exp2f(s1[3]);
            rs0 += s0[0] + s0[1] + s1[0] + s1[1];
            rs1 += s0[2] + s0[3] + s1[2] + s1[3];
            unsigned paj[4];
            paj[0] = pkbf(s0[0], s0[1]);
            paj[1] = pkbf(s0[2], s0[3]);
            paj[2] = pkbf(s1[0], s1[1]);
            paj[3] = pkbf(s1[2], s1[3]);
            #pragma unroll
            for (int d8 = 0; d8 < 4; d8++) {
                mma_bf16(o[d8], paj, Vw[(d8 * 8 + g) * 36 + j * 8 + t4],
                                     Vw[(d8 * 8 + g) * 36 + j * 8 + t4 + 4]);
            }
        }
        l0 += rs0;
        l1 += rs1;
    }

    l0 += __shfl_xor_sync(0xffffffffu, l0, 1);
    l0 += __shfl_xor_sync(0xffffffffu, l0, 2);
    l1 += __shfl_xor_sync(0xffffffffu, l1, 1);
    l1 += __shfl_xor_sync(0xffffffffu, l1, 2);
    float inv0 = 1.0f / l0, inv1 = 1.0f / l1;
    #pragma unroll
    for (int d8 = 0; d8 < 4; d8++) {
        int dc = h * 32 + d8 * 8 + 2 * t4;
        *(unsigned*)(out + ((size_t)b * HW + r0) * 256 + dc) =
            pkbf(o[d8][0] * inv0, o[d8][1] * inv0);
        *(unsigned*)(out + ((size_t)b * HW + r1) * 256 + dc) =
            pkbf(o[d8][2] * inv1, o[d8][3] * inv1);
    }
}

// ---------------- final: out[b][c][p] = m2[p][c] + x[b][c][p]  (m2 includes op) ----------------
__global__ void k_final(const float* __restrict__ m2,
                        const float* __restrict__ x, float* __restrict__ out)
{
    __shared__ float t[32][33];
    int b = blockIdx.z;
    int p0 = blockIdx.x * 32, c0 = blockIdx.y * 32;
    int tx = threadIdx.x, ty = threadIdx.y;
    t[ty][tx] = m2[((size_t)b * HW + p0 + ty) * Cc + c0 + tx];
    __syncthreads();
    size_t oi = ((size_t)b * Cc + c0 + ty) * HW + p0 + tx;
    out[oi] = t[tx][ty] + x[oi];
}

// ---------------- launch ----------------
extern "C" void kernel_launch(void* const* d_in, const int* in_sizes, int n_in,
                              void* d_out, int out_size)
{
    const float* x          = (const float*)d_in[0];
    const float* conv_w     = (const float*)d_in[1];
    const float* conv_b     = (const float*)d_in[2];
    const float* ln_local_w = (const float*)d_in[3];
    const float* ln_local_b = (const float*)d_in[4];
    const float* ln_reg_w   = (const float*)d_in[5];
    const float* ln_reg_b   = (const float*)d_in[6];
    const float* in_proj_w  = (const float*)d_in[7];
    const float* in_proj_b  = (const float*)d_in[8];
    const float* out_proj_w = (const float*)d_in[9];
    const float* out_proj_b = (const float*)d_in[10];
    const float* ln_out_w   = (const float*)d_in[11];
    const float* ln_out_b   = (const float*)d_in[12];
    const float* mlp_w1     = (const float*)d_in[13];
    const float* mlp_b1     = (const float*)d_in[14];
    const float* mlp_w2     = (const float*)d_in[15];
    const float* mlp_b2     = (const float*)d_in[16];
    const void*  attn_mask  = (const void*)d_in[17];
    float* out = (float*)d_out;

    float *xp, *q, *op, *m2;
    bf16 *f, *ob, *hid, *m1, *Kb, *Vb, *VbT, *wqkv, *wout, *wm1, *wm2;
    unsigned* mbp;
    cudaGetSymbolAddress((void**)&xp,  g_xp);
    cudaGetSymbolAddress((void**)&f,   g_f);
    cudaGetSymbolAddress((void**)&q,   g_q);
    cudaGetSymbolAddress((void**)&ob,  g_ob);
    cudaGetSymbolAddress((void**)&op,  g_op);
    cudaGetSymbolAddress((void**)&hid, g_hid);
    cudaGetSymbolAddress((void**)&m1,  g_m1);
    cudaGetSymbolAddress((void**)&m2,  g_m2);
    cudaGetSymbolAddress((void**)&mbp, g_mb);
    cudaGetSymbolAddress((void**)&Kb,  g_Kb);
    cudaGetSymbolAddress((void**)&Vb,  g_Vb);
    cudaGetSymbolAddress((void**)&VbT, g_VbT);
    cudaGetSymbolAddress((void**)&wqkv, g_wqkv);
    cudaGetSymbolAddress((void**)&wout, g_wout);
    cudaGetSymbolAddress((void**)&wm1,  g_wm1);
    cudaGetSymbolAddress((void**)&wm2,  g_wm2);

    // preamble: mask pack (with inline probe) + all weight conversions (2 launches)
    k_pack_mask<<<(Stok * NW + 255) / 256, 256>>>(attn_mask, mbp);
    k_cvtw_all<<<(WTOT / 4 + 255) / 256, 256>>>(in_proj_w, out_proj_w, mlp_w1, mlp_w2);

    // conv (1x1), reading x[b][c][p] directly (fused transpose, tf32)
    k_conv<<<dim3(Cc / 64, (Bz * HW) / 128), 256>>>(x, conv_w, conv_b, xp, Bz * HW, Cc, Cc);

    // feats: LN local + pooled LN (bf16 out)
    k_ln<<<Bz * HW / 8, 256>>>(xp, HW, ln_local_w, ln_local_b, f, Stok);
    k_pool_ln<<<dim3(144, Bz), 256>>>(xp, ln_reg_w, ln_reg_b, f, 4, HW, 0);
    k_pool_ln<<<dim3(36,  Bz), 256>>>(xp, ln_reg_w, ln_reg_b, f, 8, HW + 144, 1);

    // qkv bf16 GEMM, split epilogue: Q -> g_q f32 (local only), K/V -> g_Kb/g_Vb bf16
    k_bgemm<0, 1><<<dim3(768 / 64, (Bz * Stok + 127) / 128), 256>>>(
        f, wqkv, in_proj_b, nullptr, q, Bz * Stok, 3 * Cc, Cc);

    // transpose V (bf16 -> bf16)
    k_pack_v<<<dim3(KV_TILES, 8, Bz), 256>>>(Vb, VbT);

    // attention — only local q tokens; bf16 output
    k_attn<<<dim3(HW / 128, 8, Bz), 256>>>(q, Kb, VbT, mbp, ob);

    // out_proj (bf16 in, f32 out)
    k_bgemm<0, 0><<<dim3(Cc / 64, (Bz * HW) / 128), 256>>>(
        ob, wout, out_proj_b, nullptr, op, Bz * HW, Cc, Cc);

    // ln_out on local tokens (bf16 out)
    k_ln<<<Bz * HW / 8, 256>>>(op, HW, ln_out_w, ln_out_b, hid, HW);

    // mlp: mlp1 bf16->bf16 with GELU; mlp2 bf16 in, f32 out + op residual
    k_bgemm<1, 3><<<dim3(BOT / 64, (Bz * HW) / 128), 256>>>(
        hid, wm1, mlp_b1, nullptr, m1, Bz * HW, BOT, Cc);
    k_bgemm<0, 2><<<dim3(Cc / 64, (Bz * HW) / 128), 256>>>(
        m1, wm2, mlp_b2, op, m2, Bz * HW, Cc, BOT);

    // transpose back + input residual
    k_final<<<dim3(HW / 32, Cc / 32, Bz), dim3(32, 32)>>>(m2, x, out);
}

// round 13
// speedup vs baseline: 9.7122x; 1.1195x over previous
#include <cuda_runtime.h>
#include <cuda_bf16.h>
#include <math.h>

#define Bz   4
#define Cc   256
#define Hh   48
#define Ww   48
#define HW   2304
#define Stok 2484
#define NW   78      // ceil(S/32) mask words per row
#define KPAD 2496    // 39 * 64
#define BOT  64

typedef __nv_bfloat16 bf16;

// ---------------- scratch (device globals; zero-initialized, no allocs) ----------------
__device__ float g_xp [(size_t)Bz*HW*Cc];
__device__ bf16  g_f  [(size_t)Bz*Stok*Cc];    // LN features (bf16)
__device__ float g_q  [(size_t)Bz*HW*Cc];      // Q, local tokens only, f32
__device__ bf16  g_ob [(size_t)Bz*HW*Cc];      // attention out (bf16)
__device__ float g_op [(size_t)Bz*HW*Cc];
__device__ bf16  g_hid[(size_t)Bz*HW*Cc];      // ln_out (bf16)
__device__ bf16  g_m1 [(size_t)Bz*HW*BOT];     // gelu(mlp1) (bf16)
__device__ unsigned g_mb[(size_t)Stok*NW];
__device__ bf16 g_Kb [(size_t)Bz*8*KPAD*32];   // [b][h][key][32]
__device__ bf16 g_Vb [(size_t)Bz*8*KPAD*32];   // [b][h][key][32] (pre-transpose)
__device__ bf16 g_VbT[(size_t)Bz*8*32*KPAD];   // [b][h][32][key]
__device__ bf16 g_wqkv[768*256];               // converted weights
__device__ bf16 g_wout[256*256];
__device__ bf16 g_wm1 [BOT*256];
__device__ bf16 g_wm2 [256*BOT];

// ---------------- small helpers ----------------
__device__ __forceinline__ void cpa16(void* dst, const void* src) {
    unsigned d = (unsigned)__cvta_generic_to_shared(dst);
    asm volatile("cp.async.cg.shared.global [%0], [%1], 16;" :: "r"(d), "l"(src));
}
__device__ __forceinline__ void cpa16z(void* dst, const void* src, int sz) {
    unsigned d = (unsigned)__cvta_generic_to_shared(dst);
    asm volatile("cp.async.cg.shared.global [%0], [%1], 16, %2;" :: "r"(d), "l"(src), "r"(sz));
}
__device__ __forceinline__ void cpa_commit() { asm volatile("cp.async.commit_group;"); }
__device__ __forceinline__ void cpa_wait0()  { asm volatile("cp.async.wait_group 0;"); }
__device__ __forceinline__ void cpa_wait1()  { asm volatile("cp.async.wait_group 1;"); }

__device__ __forceinline__ void mma_tf32(float c[4], const float a[4], float b0, float b1) {
    const unsigned* A = reinterpret_cast<const unsigned*>(a);
    unsigned B0 = __float_as_uint(b0), B1 = __float_as_uint(b1);
    asm volatile(
        "mma.sync.aligned.m16n8k8.row.col.f32.tf32.tf32.f32 "
        "{%0,%1,%2,%3},{%4,%5,%6,%7},{%8,%9},{%0,%1,%2,%3};"
        : "+f"(c[0]), "+f"(c[1]), "+f"(c[2]), "+f"(c[3])
        : "r"(A[0]), "r"(A[1]), "r"(A[2]), "r"(A[3]), "r"(B0), "r"(B1));
}
__device__ __forceinline__ void mma_bf16(float c[4], const unsigned a[4],
                                         unsigned b0, unsigned b1) {
    asm volatile(
        "mma.sync.aligned.m16n8k16.row.col.f32.bf16.bf16.f32 "
        "{%0,%1,%2,%3},{%4,%5,%6,%7},{%8,%9},{%0,%1,%2,%3};"
        : "+f"(c[0]), "+f"(c[1]), "+f"(c[2]), "+f"(c[3])
        : "r"(a[0]), "r"(a[1]), "r"(a[2]), "r"(a[3]), "r"(b0), "r"(b1));
}
__device__ __forceinline__ unsigned pkbf(float lo, float hi) {
    __nv_bfloat162 h = __float22bfloat162_rn(make_float2(lo, hi));
    return *reinterpret_cast<unsigned*>(&h);
}

// ---------------- pack mask -> bitmask, with inline dtype probe ----------------
__global__ void k_pack_mask(const void* __restrict__ mv, unsigned* __restrict__ out) {
    __shared__ int bad_i32, bad_f32;
    if (threadIdx.x == 0) { bad_i32 = 0; bad_f32 = 0; }
    __syncthreads();
    {
        const unsigned* m = (const unsigned*)mv;
        for (int i = threadIdx.x; i < Stok / 4; i += blockDim.x) {
            unsigned v = m[i];
            if (v != 0u && v != 1u)           bad_i32 = 1;   // benign race: all write 1
            if (v != 0u && v != 0x3F800000u)  bad_f32 = 1;
        }
    }
    __syncthreads();
    int dt = (!bad_i32) ? 1 : ((!bad_f32) ? 2 : 0);

    int idx = blockIdx.x * blockDim.x + threadIdx.x;
    if (idx >= Stok * NW) return;
    int q = idx / NW, w = idx % NW;
    unsigned bits = 0;
    int c0 = w * 32;
    const unsigned char* mu = (const unsigned char*)mv;
    const int*           mi = (const int*)mv;
    const float*         mf = (const float*)mv;
    #pragma unroll 4
    for (int j = 0; j < 32; j++) {
        int c = c0 + j;
        bool blk;
        if (c >= Stok)      blk = true;
        else if (dt == 1)   blk = mi[(size_t)q * Stok + c] != 0;
        else if (dt == 2)   blk = mf[(size_t)q * Stok + c] != 0.0f;
        else                blk = mu[(size_t)q * Stok + c] != 0;
        if (blk) bits |= 1u << j;
    }
    out[idx] = bits;
}

// ---------------- all weight conversions in ONE launch ----------------
#define WQKV_N (768*256)
#define WOUT_N (256*256)
#define WM1_N  (BOT*256)
#define WM2_N  (256*BOT)
#define WTOT   (WQKV_N + WOUT_N + WM1_N + WM2_N)

__global__ void k_cvtw_all(const float* __restrict__ s0, const float* __restrict__ s1,
                           const float* __restrict__ s2, const float* __restrict__ s3)
{
    int i = (blockIdx.x * blockDim.x + threadIdx.x) * 4;
    const float* src; bf16* dst; int base;
    if (i < WQKV_N)                       { src = s0; dst = g_wqkv; base = 0; }
    else if (i < WQKV_N + WOUT_N)         { src = s1; dst = g_wout; base = WQKV_N; }
    else if (i < WQKV_N + WOUT_N + WM1_N) { src = s2; dst = g_wm1;  base = WQKV_N + WOUT_N; }
    else if (i < WTOT)                    { src = s3; dst = g_wm2;  base = WQKV_N + WOUT_N + WM1_N; }
    else return;
    int k = i - base;
    float4 v = *(const float4*)(src + k);
    *(uint2*)(dst + k) = make_uint2(pkbf(v.x, v.y), pkbf(v.z, v.w));
}

// ---------------- tf32 mma GEMM for conv (fused transpose A) ----------------
__device__ __forceinline__ float gelu_exact(float v) {
    return 0.5f * v * (1.0f + erff(v * 0.70710678118654752f));
}

__global__ void __launch_bounds__(256) k_conv(
    const float* __restrict__ A, const float* __restrict__ W,
    const float* __restrict__ bias, float* __restrict__ C,
    int M, int N, int K)
{
    __shared__ __align__(16) float As[3][16 * 136];
    __shared__ __align__(16) float Bs[3][64 * 20];
    int tid = threadIdx.x;
    int warp = tid >> 5, lane = tid & 31;
    int g = lane >> 2, t4 = lane & 3;
    int m0 = blockIdx.y * 128, n0 = blockIdx.x * 64;
    int bb = m0 / HW, p0 = m0 % HW;

    auto issue = [&](int k0, int st) {
        #pragma unroll
        for (int r = 0; r < 2; r++) {
            int i = tid + r * 256;
            int kk = i >> 5, c = i & 31;
            const float* src = A + ((size_t)bb * Cc + k0 + kk) * HW + p0 + c * 4;
            cpa16(&As[st][kk * 136 + c * 4], src);
        }
        {
            int row = tid >> 2, c = tid & 3;
            cpa16(&Bs[st][row * 20 + c * 4], W + (size_t)(n0 + row) * K + k0 + c * 4);
        }
        cpa_commit();
    };

    float acc[8][4] = {};
    int nk = K >> 4;
    issue(0, 0);
    issue(16, 1);

    int st = 0;
    for (int ki = 0; ki < nk; ki++) {
        if (ki + 1 < nk) cpa_wait1(); else cpa_wait0();
        __syncthreads();
        if (ki + 2 < nk) {
            int nst = st + 2; if (nst >= 3) nst -= 3;
            issue((ki + 2) << 4, nst);
        }
        const float* as = As[st];
        const float* bs = Bs[st];
        if (++st == 3) st = 0;

        float a[2][4];
        #pragma unroll
        for (int ks = 0; ks < 2; ks++) {
            a[ks][0] = as[(ks * 8 + t4) * 136 + warp * 16 + g];
            a[ks][1] = as[(ks * 8 + t4) * 136 + warp * 16 + 8 + g];
            a[ks][2] = as[(ks * 8 + t4 + 4) * 136 + warp * 16 + g];
            a[ks][3] = as[(ks * 8 + t4 + 4) * 136 + warp * 16 + 8 + g];
        }
        #pragma unroll
        for (int n8 = 0; n8 < 8; n8++) {
            #pragma unroll
            for (int ks = 0; ks < 2; ks++) {
                float b0 = bs[(n8 * 8 + g) * 20 + ks * 8 + t4];
                float b1 = bs[(n8 * 8 + g) * 20 + ks * 8 + t4 + 4];
                mma_tf32(acc[n8], a[ks], b0, b1);
            }
        }
    }

    int gm0 = m0 + warp * 16 + g;
    int gm1 = gm0 + 8;
    #pragma unroll
    for (int n8 = 0; n8 < 8; n8++) {
        int col = n0 + n8 * 8 + 2 * t4;
        float2 bb2 = *(const float2*)(bias + col);
        *(float2*)(C + (size_t)gm0 * N + col) = make_float2(acc[n8][0] + bb2.x, acc[n8][1] + bb2.y);
        *(float2*)(C + (size_t)gm1 * N + col) = make_float2(acc[n8][2] + bb2.x, acc[n8][3] + bb2.y);
    }
}

// ---------------- bf16 mma GEMM, 3-stage cp.async pipeline ----------------
// MODE=0: f32 C. MODE=1: qkv split (Q->f32 compact C, K/V->g_Kb/g_Vb bf16).
// MODE=2: f32 C = acc + bias + D. MODE=3: bf16 C.
// MODE=4: transposed final store: out[b][c][p] = acc + bias + D[p][c] + X[b][c][p].
template<int ACT, int MODE>
__global__ void __launch_bounds__(256) k_bgemm(
    const bf16* __restrict__ A, const bf16* __restrict__ W,
    const float* __restrict__ bias, const float* __restrict__ D,
    const float* __restrict__ X, void* __restrict__ Cv, int M, int N, int K)
{
    __shared__ __align__(16) unsigned As[3][128 * 20];
    __shared__ __align__(16) unsigned Bs[3][64 * 20];
    int tid = threadIdx.x;
    int warp = tid >> 5, lane = tid & 31;
    int g = lane >> 2, t4 = lane & 3;
    int m0 = blockIdx.y * 128, n0 = blockIdx.x * 64;

    auto issue = [&](int k0, int st) {
        #pragma unroll
        for (int i = tid; i < 512; i += 256) {
            int row = i >> 2, c = i & 3;
            int gm = m0 + row;
            int ok = gm < M;
            const bf16* src = A + (size_t)(ok ? gm : 0) * K + k0 + c * 8;
            cpa16z(&As[st][row * 20 + c * 4], src, ok ? 16 : 0);
        }
        {
            int row = tid >> 2, c = tid & 3;
            cpa16(&Bs[st][row * 20 + c * 4], W + (size_t)(n0 + row) * K + k0 + c * 8);
        }
        cpa_commit();
    };

    float acc[8][4] = {};
    int nk = K >> 5;
    issue(0, 0);
    if (nk > 1) issue(32, 1);

    int st = 0;
    for (int ki = 0; ki < nk; ki++) {
        if (ki + 1 < nk) cpa_wait1(); else cpa_wait0();
        __syncthreads();
        if (ki + 2 < nk) {
            int nst = st + 2; if (nst >= 3) nst -= 3;
            issue((ki + 2) << 5, nst);
        }
        const unsigned* as = As[st];
        const unsigned* bs = Bs[st];
        if (++st == 3) st = 0;

        unsigned a[2][4];
        #pragma unroll
        for (int ks = 0; ks < 2; ks++) {
            a[ks][0] = as[(warp * 16 + g) * 20 + ks * 8 + t4];
            a[ks][1] = as[(warp * 16 + 8 + g) * 20 + ks * 8 + t4];
            a[ks][2] = as[(warp * 16 + g) * 20 + ks * 8 + t4 + 4];
            a[ks][3] = as[(warp * 16 + 8 + g) * 20 + ks * 8 + t4 + 4];
        }
        #pragma unroll
        for (int n8 = 0; n8 < 8; n8++) {
            #pragma unroll
            for (int ks = 0; ks < 2; ks++) {
                unsigned b0 = bs[(n8 * 8 + g) * 20 + ks * 8 + t4];
                unsigned b1 = bs[(n8 * 8 + g) * 20 + ks * 8 + t4 + 4];
                mma_bf16(acc[n8], a[ks], b0, b1);
            }
        }
    }

    int gm0 = m0 + warp * 16 + g;
    int gm1 = gm0 + 8;

    if (MODE == 1) {
        float* C = (float*)Cv;
        int region = n0 >> 8;    // 0=Q, 1=K, 2=V
        int b0i = gm0 / Stok, s0 = gm0 - b0i * Stok;
        int b1i = gm1 / Stok, s1 = gm1 - b1i * Stok;
        #pragma unroll
        for (int n8 = 0; n8 < 8; n8++) {
            int col = n0 + n8 * 8 + 2 * t4;
            float2 bb2 = *(const float2*)(bias + col);
            float v0 = acc[n8][0] + bb2.x, v1 = acc[n8][1] + bb2.y;
            float v2 = acc[n8][2] + bb2.x, v3 = acc[n8][3] + bb2.y;
            if (region == 0) {
                if (gm0 < M && s0 < HW)
                    *(float2*)(C + ((size_t)b0i * HW + s0) * 256 + col) = make_float2(v0, v1);
                if (gm1 < M && s1 < HW)
                    *(float2*)(C + ((size_t)b1i * HW + s1) * 256 + col) = make_float2(v2, v3);
            } else {
                int dd = col & 31, hh = (col >> 5) & 7;
                bf16* dst = (region == 1) ? g_Kb : g_Vb;
                if (gm0 < M)
                    *(unsigned*)(dst + ((size_t)(b0i * 8 + hh) * KPAD + s0) * 32 + dd) = pkbf(v0, v1);
                if (gm1 < M)
                    *(unsigned*)(dst + ((size_t)(b1i * 8 + hh) * KPAD + s1) * 32 + dd) = pkbf(v2, v3);
            }
        }
        return;
    }

    if (MODE == 4) {
        // out[b][c][p] = acc + bias + D[token][c] + X[b][c][p]; M = Bz*HW (multiple of 128)
        float* C = (float*)Cv;
        int b0i = gm0 / HW, p0 = gm0 - b0i * HW;
        int b1i = gm1 / HW, p1 = gm1 - b1i * HW;
        #pragma unroll
        for (int n8 = 0; n8 < 8; n8++) {
            int col = n0 + n8 * 8 + 2 * t4;
            float2 bb2 = *(const float2*)(bias + col);
            float2 d0 = *(const float2*)(D + (size_t)gm0 * N + col);
            float2 d1 = *(const float2*)(D + (size_t)gm1 * N + col);
            size_t i00 = ((size_t)b0i * Cc + col) * HW + p0;
            size_t i01 = ((size_t)b0i * Cc + col + 1) * HW + p0;
            size_t i10 = ((size_t)b1i * Cc + col) * HW + p1;
            size_t i11 = ((size_t)b1i * Cc + col + 1) * HW + p1;
            C[i00] = acc[n8][0] + bb2.x + d0.x + X[i00];
            C[i01] = acc[n8][1] + bb2.y + d0.y + X[i01];
            C[i10] = acc[n8][2] + bb2.x + d1.x + X[i10];
            C[i11] = acc[n8][3] + bb2.y + d1.y + X[i11];
        }
        return;
    }

    #pragma unroll
    for (int n8 = 0; n8 < 8; n8++) {
        int col = n0 + n8 * 8 + 2 * t4;
        float2 bb2 = *(const float2*)(bias + col);
        float v0 = acc[n8][0] + bb2.x, v1 = acc[n8][1] + bb2.y;
        float v2 = acc[n8][2] + bb2.x, v3 = acc[n8][3] + bb2.y;
        if (ACT == 1) {
            v0 = gelu_exact(v0); v1 = gelu_exact(v1);
            v2 = gelu_exact(v2); v3 = gelu_exact(v3);
        }
        if (MODE == 2) {
            if (gm0 < M) {
                float2 d0 = *(const float2*)(D + (size_t)gm0 * N + col);
                v0 += d0.x; v1 += d0.y;
            }
            if (gm1 < M) {
                float2 d1 = *(const float2*)(D + (size_t)gm1 * N + col);
                v2 += d1.x; v3 += d1.y;
            }
        }
        if (MODE == 3) {
            bf16* C = (bf16*)Cv;
            if (gm0 < M) *(unsigned*)(C + (size_t)gm0 * N + col) = pkbf(v0, v1);
            if (gm1 < M) *(unsigned*)(C + (size_t)gm1 * N + col) = pkbf(v2, v3);
        } else {
            float* C = (float*)Cv;
            if (gm0 < M) *(float2*)(C + (size_t)gm0 * N + col) = make_float2(v0, v1);
            if (gm1 < M) *(float2*)(C + (size_t)gm1 * N + col) = make_float2(v2, v3);
        }
    }
}

// ---------------- warp-per-row layernorm over C=256 (bf16 output) ----------------
__global__ void k_ln(const float* __restrict__ in, int inTok,
                     const float* __restrict__ w, const float* __restrict__ bv,
                     bf16* __restrict__ out, int outTok)
{
    int row = blockIdx.x * 8 + (threadIdx.x >> 5);
    int lane = threadIdx.x & 31;
    int b = row / HW, p = row % HW;
    const float* src = in + ((size_t)b * inTok + p) * Cc;
    float4 v0 = *(const float4*)(src + lane * 4);
    float4 v1 = *(const float4*)(src + 128 + lane * 4);
    float s = v0.x + v0.y + v0.z + v0.w + v1.x + v1.y + v1.z + v1.w;
    #pragma unroll
    for (int o = 16; o > 0; o >>= 1) s += __shfl_xor_sync(0xffffffffu, s, o);
    float mean = s * (1.0f / 256.0f);
    float d0x = v0.x - mean, d0y = v0.y - mean, d0z = v0.z - mean, d0w = v0.w - mean;
    float d1x = v1.x - mean, d1y = v1.y - mean, d1z = v1.z - mean, d1w = v1.w - mean;
    float s2 = d0x*d0x + d0y*d0y + d0z*d0z + d0w*d0w
             + d1x*d1x + d1y*d1y + d1z*d1z + d1w*d1w;
    #pragma unroll
    for (int o = 16; o > 0; o >>= 1) s2 += __shfl_xor_sync(0xffffffffu, s2, o);
    float rs = rsqrtf(s2 * (1.0f / 256.0f) + 1e-5f);
    float4 w0 = *(const float4*)(w + lane * 4);
    float4 w1 = *(const float4*)(w + 128 + lane * 4);
    float4 b0 = *(const float4*)(bv + lane * 4);
    float4 b1 = *(const float4*)(bv + 128 + lane * 4);
    bf16* dst = out + ((size_t)b * outTok + p) * Cc;
    uint2 r0 = make_uint2(pkbf(d0x*rs*w0.x + b0.x, d0y*rs*w0.y + b0.y),
                          pkbf(d0z*rs*w0.z + b0.z, d0w*rs*w0.w + b0.w));
    uint2 r1 = make_uint2(pkbf(d1x*rs*w1.x + b1.x, d1y*rs*w1.y + b1.y),
                          pkbf(d1z*rs*w1.z + b1.z, d1w*rs*w1.w + b1.w));
    *(uint2*)(dst + lane * 4) = r0;
    *(uint2*)(dst + 128 + lane * 4) = r1;
}

// ---------------- pool (ps x ps mean) + layernorm (bf16 output) ----------------
__global__ void k_pool_ln(const float* __restrict__ xp,
                          const float* __restrict__ w, const float* __restrict__ bv,
                          bf16* __restrict__ f, int ps, int off, int reg)
{
    int b = blockIdx.y;
    int t = blockIdx.x;
    int gw = Ww / ps;
    int bh = t / gw, bw = t % gw;
    int c = threadIdx.x;
    float s = 0.f;
    for (int i = 0; i < ps; i++) {
        int prow = (bh * ps + i) * Ww + bw * ps;
        const float* base = xp + ((size_t)b * HW + prow) * Cc + c;
        for (int j = 0; j < ps; j++) s += base[(size_t)j * Cc];
    }
    float v = s / (float)(ps * ps);
    __shared__ float sb[8];
    float ss = v;
    #pragma unroll
    for (int o = 16; o > 0; o >>= 1) ss += __shfl_xor_sync(0xffffffffu, ss, o);
    if ((c & 31) == 0) sb[c >> 5] = ss;
    __syncthreads();
    float tot = 0.f;
    #pragma unroll
    for (int i = 0; i < 8; i++) tot += sb[i];
    float mean = tot * (1.0f / 256.0f);
    __syncthreads();
    float d = v - mean;
    float s2 = d * d;
    #pragma unroll
    for (int o = 16; o > 0; o >>= 1) s2 += __shfl_xor_sync(0xffffffffu, s2, o);
    if ((c & 31) == 0) sb[c >> 5] = s2;
    __syncthreads();
    float tot2 = 0.f;
    #pragma unroll
    for (int i = 0; i < 8; i++) tot2 += sb[i];
    float rs = rsqrtf(tot2 * (1.0f / 256.0f) + 1e-5f);
    f[((size_t)b * Stok + off + t) * Cc + c] =
        __float2bfloat16_rn(d * rs * w[reg * Cc + c] + bv[reg * Cc + c]);
}

// ---------------- transpose V: g_Vb [bh][key][32] -> g_VbT [bh][32][key] ----------------
__global__ void __launch_bounds__(256) k_pack_v(const bf16* __restrict__ Vb,
                                                bf16* __restrict__ VbT)
{
    __shared__ bf16 Vt[64][40];
    int kt = blockIdx.x, h = blockIdx.y, b = blockIdx.z;
    int bh = b * 8 + h;
    int tid = threadIdx.x;
    int key = tid >> 2, d0 = (tid & 3) * 8;
    uint4 v = *(const uint4*)(Vb + ((size_t)bh * KPAD + kt * 64 + key) * 32 + d0);
    *(uint4*)&Vt[key][d0] = v;
    __syncthreads();
    int d = tid >> 3, kq = (tid & 7) * 8;
    bf16 r[8];
    #pragma unroll
    for (int i = 0; i < 8; i++) r[i] = Vt[kq + i][d];
    *(uint4*)(VbT + ((size_t)bh * 32 + d) * KPAD + kt * 64 + kq) = *(uint4*)r;
}

// ---------------- bf16 mma flash attention, 3-stage pipeline, 2 CTAs/SM ----------------
#define KV_TILES 39

__global__ void __launch_bounds__(256, 2) k_attn(const float* __restrict__ qv,
                                                 const bf16* __restrict__ Kb,
                                                 const bf16* __restrict__ VbT,
                                                 const unsigned* __restrict__ mb,
                                                 bf16* __restrict__ out)
{
    __shared__ __align__(16) unsigned char KsB[3][64 * 80];
    __shared__ __align__(16) unsigned char VsB[3][32 * 144];
    __shared__ unsigned Msm[3][256];

    int tid  = threadIdx.x;
    int warp = tid >> 5, lane = tid & 31;
    int g = lane >> 2, t4 = lane & 3;
    int q0 = blockIdx.x * 128, h = blockIdx.y, b = blockIdx.z;
    int bh = b * 8 + h;

    const bf16* Kg = Kb  + (size_t)bh * KPAD * 32;
    const bf16* Vg = VbT + (size_t)bh * 32 * KPAD;
    const float* qb = qv + ((size_t)b * HW) * 256 + h * 32;

    const float SC = 0.17677669529663687f * 1.4426950408889634f;  // 1/sqrt(32)*log2e
    int r0 = q0 + warp * 16 + g;
    int r1 = r0 + 8;

    unsigned qa[2][4];
    #pragma unroll
    for (int ks = 0; ks < 2; ks++) {
        #pragma unroll
        for (int half = 0; half < 2; half++) {
            int kc = ks * 16 + half * 8 + 2 * t4;
            float2 u0 = *(const float2*)(qb + (size_t)r0 * 256 + kc);
            float2 u1 = *(const float2*)(qb + (size_t)r1 * 256 + kc);
            qa[ks][half * 2 + 0] = pkbf(u0.x * SC, u0.y * SC);
            qa[ks][half * 2 + 1] = pkbf(u1.x * SC, u1.y * SC);
        }
    }

    auto issue = [&](int kt) {
        int k0 = kt * 64;
        int st = kt % 3;
        {
            int row = tid >> 2, c = tid & 3;
            cpa16(&KsB[st][row * 80 + c * 16], Kg + (size_t)(k0 + row) * 32 + c * 8);
        }
        {
            int d = tid >> 3, c = tid & 7;
            cpa16(&VsB[st][d * 144 + c * 16], Vg + (size_t)d * KPAD + k0 + c * 8);
        }
        cpa_commit();
        if (tid < 128) {
            int row = tid, gq = q0 + row;
            Msm[st][row * 2]     = mb[(size_t)gq * NW + kt * 2];
            Msm[st][row * 2 + 1] = mb[(size_t)gq * NW + kt * 2 + 1];
        }
    };

    float l0 = 0.f, l1 = 0.f;
    float o[4][4] = {};

    issue(0);
    issue(1);
    for (int kt = 0; kt < KV_TILES; kt++) {
        // need group kt done: with a later group in flight wait_group 1 suffices;
        // final iteration must fully drain (round-7 lesson).
        if (kt + 1 < KV_TILES) cpa_wait1(); else cpa_wait0();
        __syncthreads();
        if (kt + 2 < KV_TILES) issue(kt + 2);

        int cur = kt % 3;
        const unsigned* Kw = (const unsigned*)KsB[cur];
        const unsigned* Vw = (const unsigned*)VsB[cur];

        unsigned w00 = Msm[cur][(warp * 16 + g) * 2 + 0];
        unsigned w01 = Msm[cur][(warp * 16 + g) * 2 + 1];
        unsigned w10 = Msm[cur][(warp * 16 + 8 + g) * 2 + 0];
        unsigned w11 = Msm[cur][(warp * 16 + 8 + g) * 2 + 1];

        float rs0 = 0.f, rs1 = 0.f;

        #pragma unroll
        for (int j = 0; j < 4; j++) {
            int n8a = 2 * j, n8b = 2 * j + 1;
            float s0[4] = {0.f, 0.f, 0.f, 0.f};
            float s1[4] = {0.f, 0.f, 0.f, 0.f};
            #pragma unroll
            for (int ks = 0; ks < 2; ks++) {
                mma_bf16(s0, qa[ks], Kw[(n8a * 8 + g) * 20 + ks * 8 + t4],
                                     Kw[(n8a * 8 + g) * 20 + ks * 8 + t4 + 4]);
                mma_bf16(s1, qa[ks], Kw[(n8b * 8 + g) * 20 + ks * 8 + t4],
                                     Kw[(n8b * 8 + g) * 20 + ks * 8 + t4 + 4]);
            }
            unsigned mr0 = (j < 2) ? w00 : w01;
            unsigned mr1 = (j < 2) ? w10 : w11;
            int sha = (n8a * 8 + 2 * t4) & 31;
            int shb = (n8b * 8 + 2 * t4) & 31;
            if ((mr0 >> sha) & 1u)        s0[0] = -1.0e9f;
            if ((mr0 >> (sha + 1)) & 1u)  s0[1] = -1.0e9f;
            if ((mr1 >> sha) & 1u)        s0[2] = -1.0e9f;
            if ((mr1 >> (sha + 1)) & 1u)  s0[3] = -1.0e9f;
            if ((mr0 >> shb) & 1u)        s1[0] = -1.0e9f;
            if ((mr0 >> (shb + 1)) & 1u)  s1[1] = -1.0e9f;
            if ((mr1 >> shb) & 1u)        s1[2] = -1.0e9f;
            if ((mr1 >> (shb + 1)) & 1u)  s1[3] = -1.0e9f;
            s0[0] = exp2f(s0[0]); s0[1] = exp2f(s0[1]);
            s0[2] = exp2f(s0[2]); s0[3] = exp2f(s0[3]);
            s1[0] = exp2f(s1[0]); s1[1] = exp2f(s1[1]);
            s1[2] = exp2f(s1[2]); s1[3] = exp2f(s1[3]);
            rs0 += s0[0] + s0[1] + s1[0] + s1[1];
            rs1 += s0[2] + s0[3] + s1[2] + s1[3];
            unsigned paj[4];
            paj[0] = pkbf(s0[0], s0[1]);
            paj[1] = pkbf(s0[2], s0[3]);
            paj[2] = pkbf(s1[0], s1[1]);
            paj[3] = pkbf(s1[2], s1[3]);
            #pragma unroll
            for (int d8 = 0; d8 < 4; d8++) {
                mma_bf16(o[d8], paj, Vw[(d8 * 8 + g) * 36 + j * 8 + t4],
                                     Vw[(d8 * 8 + g) * 36 + j * 8 + t4 + 4]);
            }
        }
        l0 += rs0;
        l1 += rs1;
    }

    l0 += __shfl_xor_sync(0xffffffffu, l0, 1);
    l0 += __shfl_xor_sync(0xffffffffu, l0, 2);
    l1 += __shfl_xor_sync(0xffffffffu, l1, 1);
    l1 += __shfl_xor_sync(0xffffffffu, l1, 2);
    float inv0 = 1.0f / l0, inv1 = 1.0f / l1;
    #pragma unroll
    for (int d8 = 0; d8 < 4; d8++) {
        int dc = h * 32 + d8 * 8 + 2 * t4;
        *(unsigned*)(out + ((size_t)b * HW + r0) * 256 + dc) =
            pkbf(o[d8][0] * inv0, o[d8][1] * inv0);
        *(unsigned*)(out + ((size_t)b * HW + r1) * 256 + dc) =
            pkbf(o[d8][2] * inv1, o[d8][3] * inv1);
    }
}

// ---------------- launch ----------------
extern "C" void kernel_launch(void* const* d_in, const int* in_sizes, int n_in,
                              void* d_out, int out_size)
{
    const float* x          = (const float*)d_in[0];
    const float* conv_w     = (const float*)d_in[1];
    const float* conv_b     = (const float*)d_in[2];
    const float* ln_local_w = (const float*)d_in[3];
    const float* ln_local_b = (const float*)d_in[4];
    const float* ln_reg_w   = (const float*)d_in[5];
    const float* ln_reg_b   = (const float*)d_in[6];
    const float* in_proj_w  = (const float*)d_in[7];
    const float* in_proj_b  = (const float*)d_in[8];
    const float* out_proj_w = (const float*)d_in[9];
    const float* out_proj_b = (const float*)d_in[10];
    const float* ln_out_w   = (const float*)d_in[11];
    const float* ln_out_b   = (const float*)d_in[12];
    const float* mlp_w1     = (const float*)d_in[13];
    const float* mlp_b1     = (const float*)d_in[14];
    const float* mlp_w2     = (const float*)d_in[15];
    const float* mlp_b2     = (const float*)d_in[16];
    const void*  attn_mask  = (const void*)d_in[17];
    float* out = (float*)d_out;

    float *xp, *q, *op;
    bf16 *f, *ob, *hid, *m1, *Kb, *Vb, *VbT, *wqkv, *wout, *wm1, *wm2;
    unsigned* mbp;
    cudaGetSymbolAddress((void**)&xp,  g_xp);
    cudaGetSymbolAddress((void**)&f,   g_f);
    cudaGetSymbolAddress((void**)&q,   g_q);
    cudaGetSymbolAddress((void**)&ob,  g_ob);
    cudaGetSymbolAddress((void**)&op,  g_op);
    cudaGetSymbolAddress((void**)&hid, g_hid);
    cudaGetSymbolAddress((void**)&m1,  g_m1);
    cudaGetSymbolAddress((void**)&mbp, g_mb);
    cudaGetSymbolAddress((void**)&Kb,  g_Kb);
    cudaGetSymbolAddress((void**)&Vb,  g_Vb);
    cudaGetSymbolAddress((void**)&VbT, g_VbT);
    cudaGetSymbolAddress((void**)&wqkv, g_wqkv);
    cudaGetSymbolAddress((void**)&wout, g_wout);
    cudaGetSymbolAddress((void**)&wm1,  g_wm1);
    cudaGetSymbolAddress((void**)&wm2,  g_wm2);

    // preamble (2 launches)
    k_pack_mask<<<(Stok * NW + 255) / 256, 256>>>(attn_mask, mbp);
    k_cvtw_all<<<(WTOT / 4 + 255) / 256, 256>>>(in_proj_w, out_proj_w, mlp_w1, mlp_w2);

    // conv (1x1), reading x[b][c][p] directly (fused transpose, tf32)
    k_conv<<<dim3(Cc / 64, (Bz * HW) / 128), 256>>>(x, conv_w, conv_b, xp, Bz * HW, Cc, Cc);

    // feats: LN local + pooled LN (bf16 out)
    k_ln<<<Bz * HW / 8, 256>>>(xp, HW, ln_local_w, ln_local_b, f, Stok);
    k_pool_ln<<<dim3(144, Bz), 256>>>(xp, ln_reg_w, ln_reg_b, f, 4, HW, 0);
    k_pool_ln<<<dim3(36,  Bz), 256>>>(xp, ln_reg_w, ln_reg_b, f, 8, HW + 144, 1);

    // qkv bf16 GEMM, split epilogue: Q -> g_q f32 (local only), K/V -> g_Kb/g_Vb bf16
    k_bgemm<0, 1><<<dim3(768 / 64, (Bz * Stok + 127) / 128), 256>>>(
        f, wqkv, in_proj_b, nullptr, nullptr, q, Bz * Stok, 3 * Cc, Cc);

    // transpose V (bf16 -> bf16)
    k_pack_v<<<dim3(KV_TILES, 8, Bz), 256>>>(Vb, VbT);

    // attention — only local q tokens; bf16 output
    k_attn<<<dim3(HW / 128, 8, Bz), 256>>>(q, Kb, VbT, mbp, ob);

    // out_proj (bf16 in, f32 out)
    k_bgemm<0, 0><<<dim3(Cc / 64, (Bz * HW) / 128), 256>>>(
        ob, wout, out_proj_b, nullptr, nullptr, op, Bz * HW, Cc, Cc);

    // ln_out on local tokens (bf16 out)
    k_ln<<<Bz * HW / 8, 256>>>(op, HW, ln_out_w, ln_out_b, hid, HW);

    // mlp: mlp1 bf16->bf16 with GELU; mlp2 fused transposed final store (+op residual +x)
    k_bgemm<1, 3><<<dim3(BOT / 64, (Bz * HW) / 128), 256>>>(
        hid, wm1, mlp_b1, nullptr, nullptr, m1, Bz * HW, BOT, Cc);
    k_bgemm<0, 4><<<dim3(Cc / 64, (Bz * HW) / 128), 256>>>(
        m1, wm2, mlp_b2, op, x, out, Bz * HW, Cc, BOT);
}